// round 1
// baseline (speedup 1.0000x reference)
#include <cuda_runtime.h>
#include <cuda_bf16.h>

// Problem constants
#define S_LEN 1025
#define B_SZ  8
#define E_SZ  1024
#define H_CNT 16
#define HD    64
#define NTOK  (S_LEN * B_SZ)          // 8200
#define NTOK_PROJ (1024 * B_SZ)       // 8192 (rows that get projected)
#define ROW_STRIDE (B_SZ * E_SZ)      // 8192 floats per (s) step

// Scratch buffers (device globals: allocation-free)
__device__ float g_q[NTOK * E_SZ];
__device__ float g_k[NTOK * E_SZ];
__device__ float g_v[NTOK * E_SZ];
__device__ float g_ctx[NTOK * E_SZ];

// ---------------------------------------------------------------------------
// Tiled fp32 GEMM: C[M, 1024] = A[M, 1024] @ W[1024, 1024]^T + bias
// W row-major [N, K] (so C[m,n] = sum_k A[m,k] * W[n,k]).
// 128x128 block tile, BK=16, 256 threads, 8x8 per-thread micro-tile.
// ---------------------------------------------------------------------------
__global__ __launch_bounds__(256) void gemm_bias_kernel(
    const float* __restrict__ A, const float* __restrict__ W,
    const float* __restrict__ bias, float* __restrict__ C, int M)
{
    __shared__ float As[16][128];
    __shared__ float Bs[16][128];

    const int tid = threadIdx.x;
    const int n0 = blockIdx.x * 128;
    const int m0 = blockIdx.y * 128;
    const int ty = tid >> 4;          // 0..15
    const int tx = tid & 15;          // 0..15
    const int lr = tid >> 2;          // 0..63 (load row)
    const int lc = (tid & 3) << 2;    // 0,4,8,12 (load col*4)

    float acc[8][8];
#pragma unroll
    for (int i = 0; i < 8; ++i)
#pragma unroll
        for (int j = 0; j < 8; ++j) acc[i][j] = 0.f;

    for (int k0 = 0; k0 < 1024; k0 += 16) {
#pragma unroll
        for (int h = 0; h < 2; ++h) {
            int m = m0 + lr + h * 64;
            float4 av = make_float4(0.f, 0.f, 0.f, 0.f);
            if (m < M) av = *(const float4*)&A[m * 1024 + k0 + lc];
            As[lc + 0][lr + h * 64] = av.x;
            As[lc + 1][lr + h * 64] = av.y;
            As[lc + 2][lr + h * 64] = av.z;
            As[lc + 3][lr + h * 64] = av.w;

            int n = n0 + lr + h * 64;   // always < 1024
            float4 bv = *(const float4*)&W[n * 1024 + k0 + lc];
            Bs[lc + 0][lr + h * 64] = bv.x;
            Bs[lc + 1][lr + h * 64] = bv.y;
            Bs[lc + 2][lr + h * 64] = bv.z;
            Bs[lc + 3][lr + h * 64] = bv.w;
        }
        __syncthreads();

#pragma unroll
        for (int k = 0; k < 16; ++k) {
            float a[8], b[8];
            *(float4*)&a[0] = *(const float4*)&As[k][ty * 8];
            *(float4*)&a[4] = *(const float4*)&As[k][ty * 8 + 4];
            *(float4*)&b[0] = *(const float4*)&Bs[k][tx * 8];
            *(float4*)&b[4] = *(const float4*)&Bs[k][tx * 8 + 4];
#pragma unroll
            for (int i = 0; i < 8; ++i)
#pragma unroll
                for (int j = 0; j < 8; ++j)
                    acc[i][j] += a[i] * b[j];
        }
        __syncthreads();
    }

    float bb[8];
    *(float4*)&bb[0] = *(const float4*)&bias[n0 + tx * 8];
    *(float4*)&bb[4] = *(const float4*)&bias[n0 + tx * 8 + 4];

#pragma unroll
    for (int i = 0; i < 8; ++i) {
        int m = m0 + ty * 8 + i;
        if (m < M) {
            float4 w0, w1;
            w0.x = acc[i][0] + bb[0];
            w0.y = acc[i][1] + bb[1];
            w0.z = acc[i][2] + bb[2];
            w0.w = acc[i][3] + bb[3];
            w1.x = acc[i][4] + bb[4];
            w1.y = acc[i][5] + bb[5];
            w1.z = acc[i][6] + bb[6];
            w1.w = acc[i][7] + bb[7];
            *(float4*)&C[m * 1024 + n0 + tx * 8]     = w0;
            *(float4*)&C[m * 1024 + n0 + tx * 8 + 4] = w1;
        }
    }
}

// ---------------------------------------------------------------------------
// Fill the dummy row s=1024: q/k/v row = raw query[-1] (no projection).
// ---------------------------------------------------------------------------
__global__ void fill_last_row(const float* __restrict__ query,
                              float* __restrict__ q, float* __restrict__ k,
                              float* __restrict__ v)
{
    int idx = blockIdx.x * 256 + threadIdx.x;   // 0..8191 (b*1024 + e)
    if (idx < B_SZ * E_SZ) {
        int off = 1024 * ROW_STRIDE + idx;      // same flat offset in src & dst
        float val = query[off];
        q[off] = val;
        k[off] = val;
        v[off] = val;
    }
}

// ---------------------------------------------------------------------------
// Flash attention: one block = one (q-tile of 64 rows) x one (b,h).
// Online softmax fully in registers (4x4 ownership; shfl over 16-lane groups).
// smem: Qs[64][64], Ps[64][64], Vs[64][64], Kt[64][68] (d-major K, padded).
// ---------------------------------------------------------------------------
#define SMEM_ATTN ((3 * 64 * 64 + 64 * 68) * 4)   // 66,560 bytes

__global__ __launch_bounds__(256) void attn_kernel(
    const float* __restrict__ Qg, const float* __restrict__ Kg,
    const float* __restrict__ Vg, float* __restrict__ Ctx)
{
    extern __shared__ float sm[];
    float* Qs = sm;                // [64][64]
    float* Ps = Qs + 64 * 64;      // [64][64]
    float* Vs = Ps + 64 * 64;      // [64][64]
    float* Kt = Vs + 64 * 64;      // [64][68]  Kt[d][t]

    const int tid = threadIdx.x;
    const int qt = blockIdx.x;                         // 0..16
    const int bh = blockIdx.y;                         // 0..127
    const int hb = (bh >> 4) * E_SZ + (bh & 15) * HD;  // b*1024 + h*64
    const int ty = tid >> 4, tx = tid & 15;
    const int r0 = ty * 4, c0 = tx * 4;

    // Load Q tile, pre-scaled by 1/sqrt(hd) = 0.125
#pragma unroll
    for (int i = 0; i < 16; ++i) {
        int e = i * 256 + tid;
        int r = e >> 6, c = e & 63;
        int qs = qt * 64 + r;
        Qs[r * 64 + c] = (qs < S_LEN) ? Qg[qs * ROW_STRIDE + hb + c] * 0.125f : 0.f;
    }

    float o[4][4];
#pragma unroll
    for (int i = 0; i < 4; ++i)
#pragma unroll
        for (int j = 0; j < 4; ++j) o[i][j] = 0.f;
    float mrow[4] = {-1e30f, -1e30f, -1e30f, -1e30f};
    float lrow[4] = {0.f, 0.f, 0.f, 0.f};

    for (int kb = 0; kb < 17; ++kb) {
        __syncthreads();   // protect smem reuse from previous iteration
        // load K (d-major, padded stride 68) and V (t-major)
#pragma unroll
        for (int i = 0; i < 16; ++i) {
            int e = i * 256 + tid;
            int r = e >> 6, c = e & 63;
            int ks = kb * 64 + r;
            float kvv = 0.f, vvv = 0.f;
            if (ks < S_LEN) {
                kvv = Kg[ks * ROW_STRIDE + hb + c];
                vvv = Vg[ks * ROW_STRIDE + hb + c];
            }
            Kt[c * 68 + r] = kvv;
            Vs[r * 64 + c] = vvv;
        }
        __syncthreads();

        // S = (Q*scale) @ K^T  (4x4 per thread), d unrolled by 4 via float4
        float s[4][4];
#pragma unroll
        for (int i = 0; i < 4; ++i)
#pragma unroll
            for (int j = 0; j < 4; ++j) s[i][j] = 0.f;

#pragma unroll
        for (int d0 = 0; d0 < 64; d0 += 4) {
            float qa[4][4];   // [i][dk]
            float kbm[4][4];  // [dk][j]
#pragma unroll
            for (int i = 0; i < 4; ++i) {
                float4 t4 = *(const float4*)&Qs[(r0 + i) * 64 + d0];
                qa[i][0] = t4.x; qa[i][1] = t4.y; qa[i][2] = t4.z; qa[i][3] = t4.w;
            }
#pragma unroll
            for (int dk = 0; dk < 4; ++dk) {
                float4 t4 = *(const float4*)&Kt[(d0 + dk) * 68 + c0];
                kbm[dk][0] = t4.x; kbm[dk][1] = t4.y; kbm[dk][2] = t4.z; kbm[dk][3] = t4.w;
            }
#pragma unroll
            for (int i = 0; i < 4; ++i)
#pragma unroll
                for (int j = 0; j < 4; ++j)
#pragma unroll
                    for (int dk = 0; dk < 4; ++dk)
                        s[i][j] += qa[i][dk] * kbm[dk][j];
        }

        // mask invalid key columns (t >= 1025)
#pragma unroll
        for (int j = 0; j < 4; ++j) {
            if (kb * 64 + c0 + j >= S_LEN) {
                s[0][j] = -1e30f; s[1][j] = -1e30f;
                s[2][j] = -1e30f; s[3][j] = -1e30f;
            }
        }

        // online softmax per row, stats in registers (redundant across tx group)
#pragma unroll
        for (int i = 0; i < 4; ++i) {
            float tm = fmaxf(fmaxf(s[i][0], s[i][1]), fmaxf(s[i][2], s[i][3]));
#pragma unroll
            for (int msk = 1; msk < 16; msk <<= 1)
                tm = fmaxf(tm, __shfl_xor_sync(0xffffffffu, tm, msk));
            float mnew = fmaxf(mrow[i], tm);
            float corr = __expf(mrow[i] - mnew);
            float4 p;
            p.x = __expf(s[i][0] - mnew);
            p.y = __expf(s[i][1] - mnew);
            p.z = __expf(s[i][2] - mnew);
            p.w = __expf(s[i][3] - mnew);
            float rs = (p.x + p.y) + (p.z + p.w);
#pragma unroll
            for (int msk = 1; msk < 16; msk <<= 1)
                rs += __shfl_xor_sync(0xffffffffu, rs, msk);
            lrow[i] = lrow[i] * corr + rs;
            mrow[i] = mnew;
            o[i][0] *= corr; o[i][1] *= corr; o[i][2] *= corr; o[i][3] *= corr;
            *(float4*)&Ps[(r0 + i) * 64 + c0] = p;
        }
        __syncthreads();

        // O += P @ V, t unrolled by 4
#pragma unroll
        for (int t0 = 0; t0 < 64; t0 += 4) {
            float pa[4][4];   // [i][tk]
            float vb[4][4];   // [tk][j]
#pragma unroll
            for (int i = 0; i < 4; ++i) {
                float4 t4 = *(const float4*)&Ps[(r0 + i) * 64 + t0];
                pa[i][0] = t4.x; pa[i][1] = t4.y; pa[i][2] = t4.z; pa[i][3] = t4.w;
            }
#pragma unroll
            for (int tk = 0; tk < 4; ++tk) {
                float4 t4 = *(const float4*)&Vs[(t0 + tk) * 64 + c0];
                vb[tk][0] = t4.x; vb[tk][1] = t4.y; vb[tk][2] = t4.z; vb[tk][3] = t4.w;
            }
#pragma unroll
            for (int i = 0; i < 4; ++i)
#pragma unroll
                for (int j = 0; j < 4; ++j)
#pragma unroll
                    for (int tk = 0; tk < 4; ++tk)
                        o[i][j] += pa[i][tk] * vb[tk][j];
        }
    }

    // epilogue: normalize and write context
#pragma unroll
    for (int i = 0; i < 4; ++i) {
        int qs = qt * 64 + r0 + i;
        if (qs < S_LEN) {
            float inv = 1.0f / lrow[i];
            float4 w = make_float4(o[i][0] * inv, o[i][1] * inv,
                                   o[i][2] * inv, o[i][3] * inv);
            *(float4*)&Ctx[qs * ROW_STRIDE + hb + c0] = w;
        }
    }
}

// ---------------------------------------------------------------------------
// Launch
// ---------------------------------------------------------------------------
extern "C" void kernel_launch(void* const* d_in, const int* in_sizes, int n_in,
                              void* d_out, int out_size)
{
    const float* query = (const float*)d_in[0];
    const float* key   = (const float*)d_in[1];
    const float* value = (const float*)d_in[2];
    const float* W_in  = (const float*)d_in[3];   // [3072, 1024]
    const float* b_in  = (const float*)d_in[4];   // [3072]
    const float* W_out = (const float*)d_in[5];   // [1024, 1024]
    const float* b_out = (const float*)d_in[6];   // [1024]
    float* out = (float*)d_out;

    float *qb, *kb, *vb, *ctxb;
    cudaGetSymbolAddress((void**)&qb,   g_q);
    cudaGetSymbolAddress((void**)&kb,   g_k);
    cudaGetSymbolAddress((void**)&vb,   g_v);
    cudaGetSymbolAddress((void**)&ctxb, g_ctx);

    cudaFuncSetAttribute(attn_kernel,
                         cudaFuncAttributeMaxDynamicSharedMemorySize, SMEM_ATTN);

    // QKV projections on the first 1024*8 tokens
    dim3 g1(8, 64);
    gemm_bias_kernel<<<g1, 256>>>(query, W_in,                 b_in,        qb, NTOK_PROJ);
    gemm_bias_kernel<<<g1, 256>>>(key,   W_in + 1024 * 1024,   b_in + 1024, kb, NTOK_PROJ);
    gemm_bias_kernel<<<g1, 256>>>(value, W_in + 2 * 1024 * 1024, b_in + 2048, vb, NTOK_PROJ);

    // dummy row s=1024 (raw query last row into q, k, v)
    fill_last_row<<<32, 256>>>(query, qb, kb, vb);

    // attention
    dim3 ga(17, B_SZ * H_CNT);
    attn_kernel<<<ga, 256, SMEM_ATTN>>>(qb, kb, vb, ctxb);

    // output projection over all 8200 tokens
    dim3 g3(8, 65);
    gemm_bias_kernel<<<g3, 256>>>(ctxb, W_out, b_out, out, NTOK);
}

// round 4
// speedup vs baseline: 1.7626x; 1.7626x over previous
#include <cuda_runtime.h>
#include <cuda_bf16.h>
#include <cstdint>

// Problem constants
#define S_LEN 1025
#define B_SZ  8
#define E_SZ  1024
#define H_CNT 16
#define HD    64
#define NTOK  (S_LEN * B_SZ)          // 8200
#define NTOK_PROJ (1024 * B_SZ)       // 8192
#define ROW_STRIDE (B_SZ * E_SZ)      // 8192 floats per s step

// ---------------- scratch (device globals: allocation-free) ----------------
__device__ float g_q[NTOK * E_SZ];
__device__ float g_k[NTOK * E_SZ];
__device__ float g_v[NTOK * E_SZ];
__device__ float g_ctx[NTOK * E_SZ];

__device__ __nv_bfloat16 g_qh[NTOK_PROJ * E_SZ], g_ql[NTOK_PROJ * E_SZ];
__device__ __nv_bfloat16 g_kh[NTOK_PROJ * E_SZ], g_kl[NTOK_PROJ * E_SZ];
__device__ __nv_bfloat16 g_vh[NTOK_PROJ * E_SZ], g_vl[NTOK_PROJ * E_SZ];
__device__ __nv_bfloat16 g_wih[3072 * 1024],     g_wil[3072 * 1024];
__device__ __nv_bfloat16 g_woh[1024 * 1024],     g_wol[1024 * 1024];
__device__ __nv_bfloat16 g_ch[NTOK * E_SZ],      g_cl[NTOK * E_SZ];

// ---------------- helpers (sm_80+ features only, legal on compute_103) -----
__device__ __forceinline__ uint32_t smem_u32(const void* p) {
    uint32_t a;
    asm("{ .reg .u64 t; cvta.to.shared.u64 t, %1; cvt.u32.u64 %0, t; }"
        : "=r"(a) : "l"(p));
    return a;
}

__device__ __forceinline__ void ldsm4(uint32_t* r, uint32_t addr) {
    asm volatile("ldmatrix.sync.aligned.m8n8.x4.shared.b16 {%0,%1,%2,%3}, [%4];"
                 : "=r"(r[0]), "=r"(r[1]), "=r"(r[2]), "=r"(r[3]) : "r"(addr));
}

__device__ __forceinline__ void mma_bf16(float* d, const uint32_t* a, const uint32_t* b) {
    asm volatile(
        "mma.sync.aligned.m16n8k16.row.col.f32.bf16.bf16.f32 "
        "{%0,%1,%2,%3}, {%4,%5,%6,%7}, {%8,%9}, {%0,%1,%2,%3};"
        : "+f"(d[0]), "+f"(d[1]), "+f"(d[2]), "+f"(d[3])
        : "r"(a[0]), "r"(a[1]), "r"(a[2]), "r"(a[3]), "r"(b[0]), "r"(b[1]));
}

#define CP_ASYNC16(dst, src, sz) \
    asm volatile("cp.async.cg.shared.global [%0], [%1], 16, %2;" \
                 :: "r"(dst), "l"(src), "r"(sz))
#define CP_COMMIT() asm volatile("cp.async.commit_group;" ::: "memory")
#define CP_WAIT(n)  asm volatile("cp.async.wait_group %0;" :: "n"(n) : "memory")

// ---------------------------------------------------------------------------
// mma.sync split-bf16 GEMM: C[M,1024] = (Ah+Al) @ (Wh+Wl)^T + bias
// 128x128 CTA tile, BK=64, 8 warps (2x4), 2-stage cp.async pipeline.
// D += Ah*Bh + Ah*Bl + Al*Bh   (Al*Bl ~2^-18, dropped)
// SMEM per operand tile: 128 rows x 128 bytes, SW128 swizzle.
// ---------------------------------------------------------------------------
#define OP_BYTES   (128 * 128)            // 16 KB
#define STAGE_BYTES (4 * OP_BYTES)        // 64 KB
#define GK_SMEM    (2 * STAGE_BYTES)      // 128 KB

__device__ __forceinline__ void load_stage(
    char* stage,
    const __nv_bfloat16* __restrict__ Ah, const __nv_bfloat16* __restrict__ Al,
    const __nv_bfloat16* __restrict__ Bh, const __nv_bfloat16* __restrict__ Bl,
    int m0, int n0, int k0, int M, int tid)
{
#pragma unroll
    for (int o = 0; o < 4; ++o) {
        const __nv_bfloat16* src_base = (o == 0) ? Ah : (o == 1) ? Al : (o == 2) ? Bh : Bl;
        const int row0 = (o < 2) ? m0 : n0;
        char* dstop = stage + o * OP_BYTES;
#pragma unroll
        for (int i = 0; i < 4; ++i) {
            int ch = i * 256 + tid;          // 0..1023 16B chunks
            int r = ch >> 3, c = ch & 7;
            uint32_t dst = smem_u32(dstop + r * 128 + (((c ^ (r & 7))) << 4));
            const char* src = (const char*)(src_base + (size_t)(row0 + r) * 1024 + k0 + c * 8);
            int sz = (o >= 2 || (row0 + r) < M) ? 16 : 0;   // zero-fill OOB rows
            CP_ASYNC16(dst, src, sz);
        }
    }
}

__device__ __forceinline__ void tc_gemm_body(
    const __nv_bfloat16* __restrict__ Ah, const __nv_bfloat16* __restrict__ Al,
    const __nv_bfloat16* __restrict__ Wh, const __nv_bfloat16* __restrict__ Wl,
    const float* __restrict__ bias, float* __restrict__ C, int M,
    char* sm, int n0, int m0)
{
    const int tid = threadIdx.x;
    const int wid = tid >> 5, lane = tid & 31;
    const int wm = wid >> 2, wn = wid & 3;     // 2 x 4 warp grid

    float acc[4][4][4];
#pragma unroll
    for (int a = 0; a < 4; ++a)
#pragma unroll
        for (int b = 0; b < 4; ++b)
#pragma unroll
            for (int c = 0; c < 4; ++c) acc[a][b][c] = 0.f;

    // ldmatrix lane addressing (constant across k-chunks)
    const int a_row_l = lane & 15;             // row within m16 tile
    const int a_chk_l = lane >> 4;             // 0/1 -> k8 half
    const int b_row_l = (lane & 7) + ((lane >> 4) << 3);   // n row within n16 pair
    const int b_chk_l = (lane >> 3) & 1;

    load_stage(sm, Ah, Al, Wh, Wl, m0, n0, 0, M, tid);
    CP_COMMIT();

    for (int t = 0; t < 16; ++t) {
        if (t + 1 < 16) {
            load_stage(sm + ((t + 1) & 1) * STAGE_BYTES, Ah, Al, Wh, Wl,
                       m0, n0, (t + 1) * 64, M, tid);
            CP_COMMIT();
            CP_WAIT(1);
        } else {
            CP_WAIT(0);
        }
        __syncthreads();

        char* st = sm + (t & 1) * STAGE_BYTES;
        const uint32_t sAh = smem_u32(st);
        const uint32_t sAl = sAh + OP_BYTES;
        const uint32_t sBh = sAh + 2 * OP_BYTES;
        const uint32_t sBl = sAh + 3 * OP_BYTES;

#pragma unroll
        for (int ks = 0; ks < 4; ++ks) {
            uint32_t ah[4][4], al[4][4], bh[2][4], bl[2][4];
            const int achk = ks * 2 + a_chk_l;
#pragma unroll
            for (int mt = 0; mt < 4; ++mt) {
                int row = wm * 64 + mt * 16 + a_row_l;
                uint32_t off = row * 128 + ((achk ^ (row & 7)) << 4);
                ldsm4(ah[mt], sAh + off);
                ldsm4(al[mt], sAl + off);
            }
            const int bchk = ks * 2 + b_chk_l;
#pragma unroll
            for (int np = 0; np < 2; ++np) {
                int row = wn * 32 + np * 16 + b_row_l;
                uint32_t off = row * 128 + ((bchk ^ (row & 7)) << 4);
                ldsm4(bh[np], sBh + off);
                ldsm4(bl[np], sBl + off);
            }
#pragma unroll
            for (int mt = 0; mt < 4; ++mt)
#pragma unroll
                for (int np = 0; np < 2; ++np) {
                    mma_bf16(acc[mt][np * 2],     ah[mt], &bh[np][0]);
                    mma_bf16(acc[mt][np * 2 + 1], ah[mt], &bh[np][2]);
                    mma_bf16(acc[mt][np * 2],     ah[mt], &bl[np][0]);
                    mma_bf16(acc[mt][np * 2 + 1], ah[mt], &bl[np][2]);
                    mma_bf16(acc[mt][np * 2],     al[mt], &bh[np][0]);
                    mma_bf16(acc[mt][np * 2 + 1], al[mt], &bh[np][2]);
                }
        }
        __syncthreads();
    }

    // epilogue: bias add + direct global store (fp32)
#pragma unroll
    for (int mt = 0; mt < 4; ++mt) {
        int mA = m0 + wm * 64 + mt * 16 + (lane >> 2);
        int mB = mA + 8;
#pragma unroll
        for (int nt = 0; nt < 4; ++nt) {
            int n = n0 + wn * 32 + nt * 8 + (lane & 3) * 2;
            float2 bv = *(const float2*)&bias[n];
            if (mA < M) {
                float2 w = make_float2(acc[mt][nt][0] + bv.x, acc[mt][nt][1] + bv.y);
                *(float2*)&C[(size_t)mA * 1024 + n] = w;
            }
            if (mB < M) {
                float2 w = make_float2(acc[mt][nt][2] + bv.x, acc[mt][nt][3] + bv.y);
                *(float2*)&C[(size_t)mB * 1024 + n] = w;
            }
        }
    }
}

__global__ __launch_bounds__(256)
void tc_gemm_one(const __nv_bfloat16* __restrict__ Ah, const __nv_bfloat16* __restrict__ Al,
                 const __nv_bfloat16* __restrict__ Wh, const __nv_bfloat16* __restrict__ Wl,
                 const float* __restrict__ bias, float* __restrict__ C, int M)
{
    extern __shared__ char sm[];
    tc_gemm_body(Ah, Al, Wh, Wl, bias, C, M, sm, blockIdx.x * 128, blockIdx.y * 128);
}

__global__ __launch_bounds__(256)
void tc_gemm_qkv(const __nv_bfloat16* __restrict__ qh, const __nv_bfloat16* __restrict__ ql,
                 const __nv_bfloat16* __restrict__ kh, const __nv_bfloat16* __restrict__ kl,
                 const __nv_bfloat16* __restrict__ vh, const __nv_bfloat16* __restrict__ vl,
                 const __nv_bfloat16* __restrict__ Wh, const __nv_bfloat16* __restrict__ Wl,
                 const float* __restrict__ bias,
                 float* __restrict__ Cq, float* __restrict__ Ck, float* __restrict__ Cv)
{
    extern __shared__ char sm[];
    const int z = blockIdx.z;
    const __nv_bfloat16* Ah = (z == 0) ? qh : (z == 1) ? kh : vh;
    const __nv_bfloat16* Al = (z == 0) ? ql : (z == 1) ? kl : vl;
    float* C = (z == 0) ? Cq : (z == 1) ? Ck : Cv;
    tc_gemm_body(Ah, Al, Wh + (size_t)z * 1024 * 1024, Wl + (size_t)z * 1024 * 1024,
                 bias + z * 1024, C, NTOK_PROJ, sm, blockIdx.x * 128, blockIdx.y * 128);
}

// ---------------------------------------------------------------------------
// fp32 -> (bf16 hi, bf16 lo) split, vectorized by 4
// ---------------------------------------------------------------------------
__global__ __launch_bounds__(256) void split_bf16(
    const float4* __restrict__ x, uint2* __restrict__ hi, uint2* __restrict__ lo, int n4)
{
    int i = blockIdx.x * 256 + threadIdx.x;
    if (i < n4) {
        float4 v = x[i];
        __nv_bfloat16 hx = __float2bfloat16_rn(v.x);
        __nv_bfloat16 hy = __float2bfloat16_rn(v.y);
        __nv_bfloat16 hz = __float2bfloat16_rn(v.z);
        __nv_bfloat16 hw = __float2bfloat16_rn(v.w);
        __nv_bfloat16 lx = __float2bfloat16_rn(v.x - __bfloat162float(hx));
        __nv_bfloat16 ly = __float2bfloat16_rn(v.y - __bfloat162float(hy));
        __nv_bfloat16 lz = __float2bfloat16_rn(v.z - __bfloat162float(hz));
        __nv_bfloat16 lw = __float2bfloat16_rn(v.w - __bfloat162float(hw));
        __nv_bfloat162 h01 = __halves2bfloat162(hx, hy), h23 = __halves2bfloat162(hz, hw);
        __nv_bfloat162 l01 = __halves2bfloat162(lx, ly), l23 = __halves2bfloat162(lz, lw);
        uint2 uh, ul;
        uh.x = *(uint32_t*)&h01; uh.y = *(uint32_t*)&h23;
        ul.x = *(uint32_t*)&l01; ul.y = *(uint32_t*)&l23;
        hi[i] = uh; lo[i] = ul;
    }
}

// ---------------------------------------------------------------------------
// Dummy row s=1024: q/k/v row = raw query[-1]
// ---------------------------------------------------------------------------
__global__ void fill_last_row(const float* __restrict__ query,
                              float* __restrict__ q, float* __restrict__ k,
                              float* __restrict__ v)
{
    int idx = blockIdx.x * 256 + threadIdx.x;
    if (idx < B_SZ * E_SZ) {
        int off = 1024 * ROW_STRIDE + idx;
        float val = query[off];
        q[off] = val; k[off] = val; v[off] = val;
    }
}

// ---------------------------------------------------------------------------
// Flash attention (fp32 SIMT, unchanged)
// ---------------------------------------------------------------------------
#define SMEM_ATTN ((3 * 64 * 64 + 64 * 68) * 4)

__global__ __launch_bounds__(256) void attn_kernel(
    const float* __restrict__ Qg, const float* __restrict__ Kg,
    const float* __restrict__ Vg, float* __restrict__ Ctx)
{
    extern __shared__ float smf[];
    float* Qs = smf;
    float* Ps = Qs + 64 * 64;
    float* Vs = Ps + 64 * 64;
    float* Kt = Vs + 64 * 64;

    const int tid = threadIdx.x;
    const int qt = blockIdx.x;
    const int bh = blockIdx.y;
    const int hb = (bh >> 4) * E_SZ + (bh & 15) * HD;
    const int ty = tid >> 4, tx = tid & 15;
    const int r0 = ty * 4, c0 = tx * 4;

#pragma unroll
    for (int i = 0; i < 16; ++i) {
        int e = i * 256 + tid;
        int r = e >> 6, c = e & 63;
        int qs = qt * 64 + r;
        Qs[r * 64 + c] = (qs < S_LEN) ? Qg[qs * ROW_STRIDE + hb + c] * 0.125f : 0.f;
    }

    float o[4][4];
#pragma unroll
    for (int i = 0; i < 4; ++i)
#pragma unroll
        for (int j = 0; j < 4; ++j) o[i][j] = 0.f;
    float mrow[4] = {-1e30f, -1e30f, -1e30f, -1e30f};
    float lrow[4] = {0.f, 0.f, 0.f, 0.f};

    for (int kb = 0; kb < 17; ++kb) {
        __syncthreads();
#pragma unroll
        for (int i = 0; i < 16; ++i) {
            int e = i * 256 + tid;
            int r = e >> 6, c = e & 63;
            int ks = kb * 64 + r;
            float kvv = 0.f, vvv = 0.f;
            if (ks < S_LEN) {
                kvv = Kg[ks * ROW_STRIDE + hb + c];
                vvv = Vg[ks * ROW_STRIDE + hb + c];
            }
            Kt[c * 68 + r] = kvv;
            Vs[r * 64 + c] = vvv;
        }
        __syncthreads();

        float s[4][4];
#pragma unroll
        for (int i = 0; i < 4; ++i)
#pragma unroll
            for (int j = 0; j < 4; ++j) s[i][j] = 0.f;

#pragma unroll
        for (int d0 = 0; d0 < 64; d0 += 4) {
            float qa[4][4], kbm[4][4];
#pragma unroll
            for (int i = 0; i < 4; ++i) {
                float4 t4 = *(const float4*)&Qs[(r0 + i) * 64 + d0];
                qa[i][0] = t4.x; qa[i][1] = t4.y; qa[i][2] = t4.z; qa[i][3] = t4.w;
            }
#pragma unroll
            for (int dk = 0; dk < 4; ++dk) {
                float4 t4 = *(const float4*)&Kt[(d0 + dk) * 68 + c0];
                kbm[dk][0] = t4.x; kbm[dk][1] = t4.y; kbm[dk][2] = t4.z; kbm[dk][3] = t4.w;
            }
#pragma unroll
            for (int i = 0; i < 4; ++i)
#pragma unroll
                for (int j = 0; j < 4; ++j)
#pragma unroll
                    for (int dk = 0; dk < 4; ++dk)
                        s[i][j] += qa[i][dk] * kbm[dk][j];
        }

#pragma unroll
        for (int j = 0; j < 4; ++j) {
            if (kb * 64 + c0 + j >= S_LEN) {
                s[0][j] = -1e30f; s[1][j] = -1e30f;
                s[2][j] = -1e30f; s[3][j] = -1e30f;
            }
        }

#pragma unroll
        for (int i = 0; i < 4; ++i) {
            float tm = fmaxf(fmaxf(s[i][0], s[i][1]), fmaxf(s[i][2], s[i][3]));
#pragma unroll
            for (int msk = 1; msk < 16; msk <<= 1)
                tm = fmaxf(tm, __shfl_xor_sync(0xffffffffu, tm, msk));
            float mnew = fmaxf(mrow[i], tm);
            float corr = __expf(mrow[i] - mnew);
            float4 p;
            p.x = __expf(s[i][0] - mnew);
            p.y = __expf(s[i][1] - mnew);
            p.z = __expf(s[i][2] - mnew);
            p.w = __expf(s[i][3] - mnew);
            float rs = (p.x + p.y) + (p.z + p.w);
#pragma unroll
            for (int msk = 1; msk < 16; msk <<= 1)
                rs += __shfl_xor_sync(0xffffffffu, rs, msk);
            lrow[i] = lrow[i] * corr + rs;
            mrow[i] = mnew;
            o[i][0] *= corr; o[i][1] *= corr; o[i][2] *= corr; o[i][3] *= corr;
            *(float4*)&Ps[(r0 + i) * 64 + c0] = p;
        }
        __syncthreads();

#pragma unroll
        for (int t0 = 0; t0 < 64; t0 += 4) {
            float pa[4][4], vb[4][4];
#pragma unroll
            for (int i = 0; i < 4; ++i) {
                float4 t4 = *(const float4*)&Ps[(r0 + i) * 64 + t0];
                pa[i][0] = t4.x; pa[i][1] = t4.y; pa[i][2] = t4.z; pa[i][3] = t4.w;
            }
#pragma unroll
            for (int tk = 0; tk < 4; ++tk) {
                float4 t4 = *(const float4*)&Vs[(t0 + tk) * 64 + c0];
                vb[tk][0] = t4.x; vb[tk][1] = t4.y; vb[tk][2] = t4.z; vb[tk][3] = t4.w;
            }
#pragma unroll
            for (int i = 0; i < 4; ++i)
#pragma unroll
                for (int j = 0; j < 4; ++j)
#pragma unroll
                    for (int tk = 0; tk < 4; ++tk)
                        o[i][j] += pa[i][tk] * vb[tk][j];
        }
    }

#pragma unroll
    for (int i = 0; i < 4; ++i) {
        int qs = qt * 64 + r0 + i;
        if (qs < S_LEN) {
            float inv = 1.0f / lrow[i];
            float4 w = make_float4(o[i][0] * inv, o[i][1] * inv,
                                   o[i][2] * inv, o[i][3] * inv);
            *(float4*)&Ctx[qs * ROW_STRIDE + hb + c0] = w;
        }
    }
}

// ---------------------------------------------------------------------------
// Launch
// ---------------------------------------------------------------------------
extern "C" void kernel_launch(void* const* d_in, const int* in_sizes, int n_in,
                              void* d_out, int out_size)
{
    const float* query = (const float*)d_in[0];
    const float* key   = (const float*)d_in[1];
    const float* value = (const float*)d_in[2];
    const float* W_in  = (const float*)d_in[3];
    const float* b_in  = (const float*)d_in[4];
    const float* W_out = (const float*)d_in[5];
    const float* b_out = (const float*)d_in[6];
    float* out = (float*)d_out;

    float *qb, *kb, *vb, *ctxb;
    cudaGetSymbolAddress((void**)&qb,   g_q);
    cudaGetSymbolAddress((void**)&kb,   g_k);
    cudaGetSymbolAddress((void**)&vb,   g_v);
    cudaGetSymbolAddress((void**)&ctxb, g_ctx);

    __nv_bfloat16 *qh, *ql, *kh, *kl, *vh, *vl, *wih, *wil, *woh, *wol, *ch, *cl;
    cudaGetSymbolAddress((void**)&qh,  g_qh);  cudaGetSymbolAddress((void**)&ql,  g_ql);
    cudaGetSymbolAddress((void**)&kh,  g_kh);  cudaGetSymbolAddress((void**)&kl,  g_kl);
    cudaGetSymbolAddress((void**)&vh,  g_vh);  cudaGetSymbolAddress((void**)&vl,  g_vl);
    cudaGetSymbolAddress((void**)&wih, g_wih); cudaGetSymbolAddress((void**)&wil, g_wil);
    cudaGetSymbolAddress((void**)&woh, g_woh); cudaGetSymbolAddress((void**)&wol, g_wol);
    cudaGetSymbolAddress((void**)&ch,  g_ch);  cudaGetSymbolAddress((void**)&cl,  g_cl);

    cudaFuncSetAttribute(tc_gemm_qkv, cudaFuncAttributeMaxDynamicSharedMemorySize, GK_SMEM);
    cudaFuncSetAttribute(tc_gemm_one, cudaFuncAttributeMaxDynamicSharedMemorySize, GK_SMEM);
    cudaFuncSetAttribute(attn_kernel, cudaFuncAttributeMaxDynamicSharedMemorySize, SMEM_ATTN);

    // fp32 -> bf16 hi/lo splits
    split_bf16<<<8192, 256>>>((const float4*)query, (uint2*)qh, (uint2*)ql, NTOK_PROJ * E_SZ / 4);
    split_bf16<<<8192, 256>>>((const float4*)key,   (uint2*)kh, (uint2*)kl, NTOK_PROJ * E_SZ / 4);
    split_bf16<<<8192, 256>>>((const float4*)value, (uint2*)vh, (uint2*)vl, NTOK_PROJ * E_SZ / 4);
    split_bf16<<<3072, 256>>>((const float4*)W_in,  (uint2*)wih, (uint2*)wil, 3072 * 1024 / 4);
    split_bf16<<<1024, 256>>>((const float4*)W_out, (uint2*)woh, (uint2*)wol, 1024 * 1024 / 4);

    // QKV projections (mma.sync tensor cores)
    tc_gemm_qkv<<<dim3(8, 64, 3), 256, GK_SMEM>>>(qh, ql, kh, kl, vh, vl,
                                                  wih, wil, b_in, qb, kb, vb);

    fill_last_row<<<32, 256>>>(query, qb, kb, vb);

    // attention (fp32 SIMT)
    dim3 ga(17, B_SZ * H_CNT);
    attn_kernel<<<ga, 256, SMEM_ATTN>>>(qb, kb, vb, ctxb);

    // out projection (mma.sync tensor cores)
    split_bf16<<<8200, 256>>>((const float4*)ctxb, (uint2*)ch, (uint2*)cl, NTOK * E_SZ / 4);
    tc_gemm_one<<<dim3(8, 65, 1), 256, GK_SMEM>>>(ch, cl, woh, wol, b_out, out, NTOK);
}

// round 6
// speedup vs baseline: 3.1497x; 1.7870x over previous
#include <cuda_runtime.h>
#include <cuda_bf16.h>
#include <cstdint>

// Problem constants
#define S_LEN 1025
#define B_SZ  8
#define E_SZ  1024
#define H_CNT 16
#define HD    64
#define NTOK  (S_LEN * B_SZ)          // 8200
#define NTOK_PROJ (1024 * B_SZ)       // 8192

// ---------------- scratch (device globals: allocation-free) ----------------
// raw-input splits (pre-projection)
__device__ __nv_bfloat16 g_qh[NTOK_PROJ * E_SZ], g_ql[NTOK_PROJ * E_SZ];
__device__ __nv_bfloat16 g_kh[NTOK_PROJ * E_SZ], g_kl[NTOK_PROJ * E_SZ];
__device__ __nv_bfloat16 g_vh[NTOK_PROJ * E_SZ], g_vl[NTOK_PROJ * E_SZ];
__device__ __nv_bfloat16 g_wih[3072 * 1024],     g_wil[3072 * 1024];
__device__ __nv_bfloat16 g_woh[1024 * 1024],     g_wol[1024 * 1024];
// projected q/k/v splits (attention inputs, include dummy row s=1024)
__device__ __nv_bfloat16 g_aqh[NTOK * E_SZ], g_aql[NTOK * E_SZ];
__device__ __nv_bfloat16 g_akh[NTOK * E_SZ], g_akl[NTOK * E_SZ];
__device__ __nv_bfloat16 g_avh[NTOK * E_SZ], g_avl[NTOK * E_SZ];
// context splits (out-proj input)
__device__ __nv_bfloat16 g_ch[NTOK * E_SZ], g_cl[NTOK * E_SZ];

// ---------------- helpers (sm_80+ only; legal on bare compute_103) ---------
__device__ __forceinline__ uint32_t smem_u32(const void* p) {
    uint32_t a;
    asm("{ .reg .u64 t; cvta.to.shared.u64 t, %1; cvt.u32.u64 %0, t; }"
        : "=r"(a) : "l"(p));
    return a;
}
__device__ __forceinline__ void ldsm4(uint32_t* r, uint32_t addr) {
    asm volatile("ldmatrix.sync.aligned.m8n8.x4.shared.b16 {%0,%1,%2,%3}, [%4];"
                 : "=r"(r[0]), "=r"(r[1]), "=r"(r[2]), "=r"(r[3]) : "r"(addr));
}
__device__ __forceinline__ void ldsm4_t(uint32_t* r, uint32_t addr) {
    asm volatile("ldmatrix.sync.aligned.m8n8.x4.trans.shared.b16 {%0,%1,%2,%3}, [%4];"
                 : "=r"(r[0]), "=r"(r[1]), "=r"(r[2]), "=r"(r[3]) : "r"(addr));
}
__device__ __forceinline__ void mma_bf16(float* d, const uint32_t* a, const uint32_t* b) {
    asm volatile(
        "mma.sync.aligned.m16n8k16.row.col.f32.bf16.bf16.f32 "
        "{%0,%1,%2,%3}, {%4,%5,%6,%7}, {%8,%9}, {%0,%1,%2,%3};"
        : "+f"(d[0]), "+f"(d[1]), "+f"(d[2]), "+f"(d[3])
        : "r"(a[0]), "r"(a[1]), "r"(a[2]), "r"(a[3]), "r"(b[0]), "r"(b[1]));
}
#define CP_ASYNC16(dst, src, sz) \
    asm volatile("cp.async.cg.shared.global [%0], [%1], 16, %2;" \
                 :: "r"(dst), "l"(src), "r"(sz))
#define CP_COMMIT() asm volatile("cp.async.commit_group;" ::: "memory")
#define CP_WAIT(n)  asm volatile("cp.async.wait_group %0;" :: "n"(n) : "memory")

// split a pair of floats into packed bf16 hi and bf16 residual lo
__device__ __forceinline__ void split2(float a, float b, uint32_t& hi, uint32_t& lo) {
    __nv_bfloat162 h = __floats2bfloat162_rn(a, b);
    float ra = a - __bfloat162float(__low2bfloat16(h));
    float rb = b - __bfloat162float(__high2bfloat16(h));
    __nv_bfloat162 l = __floats2bfloat162_rn(ra, rb);
    hi = *(uint32_t*)&h;
    lo = *(uint32_t*)&l;
}

// ---------------------------------------------------------------------------
// mma.sync split-bf16 GEMM (from round 4), epilogue either fp32 or bf16-split
// ---------------------------------------------------------------------------
#define OP_BYTES    (128 * 128)
#define STAGE_BYTES (4 * OP_BYTES)
#define GK_SMEM     (2 * STAGE_BYTES)    // 128 KB

__device__ __forceinline__ void load_stage(
    char* stage,
    const __nv_bfloat16* __restrict__ Ah, const __nv_bfloat16* __restrict__ Al,
    const __nv_bfloat16* __restrict__ Bh, const __nv_bfloat16* __restrict__ Bl,
    int m0, int n0, int k0, int M, int tid)
{
#pragma unroll
    for (int o = 0; o < 4; ++o) {
        const __nv_bfloat16* src_base = (o == 0) ? Ah : (o == 1) ? Al : (o == 2) ? Bh : Bl;
        const int row0 = (o < 2) ? m0 : n0;
        char* dstop = stage + o * OP_BYTES;
#pragma unroll
        for (int i = 0; i < 4; ++i) {
            int ch = i * 256 + tid;
            int r = ch >> 3, c = ch & 7;
            uint32_t dst = smem_u32(dstop + r * 128 + ((c ^ (r & 7)) << 4));
            const char* src = (const char*)(src_base + (size_t)(row0 + r) * 1024 + k0 + c * 8);
            int sz = (o >= 2 || (row0 + r) < M) ? 16 : 0;
            CP_ASYNC16(dst, src, sz);
        }
    }
}

template<int SPLIT_OUT>
__device__ __forceinline__ void tc_gemm_body(
    const __nv_bfloat16* __restrict__ Ah, const __nv_bfloat16* __restrict__ Al,
    const __nv_bfloat16* __restrict__ Wh, const __nv_bfloat16* __restrict__ Wl,
    const float* __restrict__ bias, float* __restrict__ C,
    __nv_bfloat16* __restrict__ Ch, __nv_bfloat16* __restrict__ Cl, int M,
    char* sm, int n0, int m0)
{
    const int tid = threadIdx.x;
    const int wid = tid >> 5, lane = tid & 31;
    const int wm = wid >> 2, wn = wid & 3;

    float acc[4][4][4];
#pragma unroll
    for (int a = 0; a < 4; ++a)
#pragma unroll
        for (int b = 0; b < 4; ++b)
#pragma unroll
            for (int c = 0; c < 4; ++c) acc[a][b][c] = 0.f;

    const int a_row_l = lane & 15;
    const int a_chk_l = lane >> 4;
    const int b_row_l = (lane & 7) + ((lane >> 4) << 3);
    const int b_chk_l = (lane >> 3) & 1;

    load_stage(sm, Ah, Al, Wh, Wl, m0, n0, 0, M, tid);
    CP_COMMIT();

    for (int t = 0; t < 16; ++t) {
        if (t + 1 < 16) {
            load_stage(sm + ((t + 1) & 1) * STAGE_BYTES, Ah, Al, Wh, Wl,
                       m0, n0, (t + 1) * 64, M, tid);
            CP_COMMIT();
            CP_WAIT(1);
        } else {
            CP_WAIT(0);
        }
        __syncthreads();

        char* st = sm + (t & 1) * STAGE_BYTES;
        const uint32_t sAh = smem_u32(st);
        const uint32_t sAl = sAh + OP_BYTES;
        const uint32_t sBh = sAh + 2 * OP_BYTES;
        const uint32_t sBl = sAh + 3 * OP_BYTES;

#pragma unroll
        for (int ks = 0; ks < 4; ++ks) {
            uint32_t ah[4][4], al[4][4], bh[2][4], bl[2][4];
            const int achk = ks * 2 + a_chk_l;
#pragma unroll
            for (int mt = 0; mt < 4; ++mt) {
                int row = wm * 64 + mt * 16 + a_row_l;
                uint32_t off = row * 128 + ((achk ^ (row & 7)) << 4);
                ldsm4(ah[mt], sAh + off);
                ldsm4(al[mt], sAl + off);
            }
            const int bchk = ks * 2 + b_chk_l;
#pragma unroll
            for (int np = 0; np < 2; ++np) {
                int row = wn * 32 + np * 16 + b_row_l;
                uint32_t off = row * 128 + ((bchk ^ (row & 7)) << 4);
                ldsm4(bh[np], sBh + off);
                ldsm4(bl[np], sBl + off);
            }
#pragma unroll
            for (int mt = 0; mt < 4; ++mt)
#pragma unroll
                for (int np = 0; np < 2; ++np) {
                    mma_bf16(acc[mt][np * 2],     ah[mt], &bh[np][0]);
                    mma_bf16(acc[mt][np * 2 + 1], ah[mt], &bh[np][2]);
                    mma_bf16(acc[mt][np * 2],     ah[mt], &bl[np][0]);
                    mma_bf16(acc[mt][np * 2 + 1], ah[mt], &bl[np][2]);
                    mma_bf16(acc[mt][np * 2],     al[mt], &bh[np][0]);
                    mma_bf16(acc[mt][np * 2 + 1], al[mt], &bh[np][2]);
                }
        }
        __syncthreads();
    }

#pragma unroll
    for (int mt = 0; mt < 4; ++mt) {
        int mA = m0 + wm * 64 + mt * 16 + (lane >> 2);
        int mB = mA + 8;
#pragma unroll
        for (int nt = 0; nt < 4; ++nt) {
            int n = n0 + wn * 32 + nt * 8 + (lane & 3) * 2;
            float2 bv = *(const float2*)&bias[n];
            float v0 = acc[mt][nt][0] + bv.x, v1 = acc[mt][nt][1] + bv.y;
            float v2 = acc[mt][nt][2] + bv.x, v3 = acc[mt][nt][3] + bv.y;
            if (SPLIT_OUT) {
                if (mA < M) {
                    uint32_t hi, lo; split2(v0, v1, hi, lo);
                    *(uint32_t*)(Ch + (size_t)mA * 1024 + n) = hi;
                    *(uint32_t*)(Cl + (size_t)mA * 1024 + n) = lo;
                }
                if (mB < M) {
                    uint32_t hi, lo; split2(v2, v3, hi, lo);
                    *(uint32_t*)(Ch + (size_t)mB * 1024 + n) = hi;
                    *(uint32_t*)(Cl + (size_t)mB * 1024 + n) = lo;
                }
            } else {
                if (mA < M) *(float2*)&C[(size_t)mA * 1024 + n] = make_float2(v0, v1);
                if (mB < M) *(float2*)&C[(size_t)mB * 1024 + n] = make_float2(v2, v3);
            }
        }
    }
}

__global__ __launch_bounds__(256)
void tc_gemm_out(const __nv_bfloat16* __restrict__ Ah, const __nv_bfloat16* __restrict__ Al,
                 const __nv_bfloat16* __restrict__ Wh, const __nv_bfloat16* __restrict__ Wl,
                 const float* __restrict__ bias, float* __restrict__ C, int M)
{
    extern __shared__ char sm[];
    tc_gemm_body<0>(Ah, Al, Wh, Wl, bias, C, nullptr, nullptr, M, sm,
                    blockIdx.x * 128, blockIdx.y * 128);
}

__global__ __launch_bounds__(256)
void tc_gemm_qkv(const __nv_bfloat16* __restrict__ qh, const __nv_bfloat16* __restrict__ ql,
                 const __nv_bfloat16* __restrict__ kh, const __nv_bfloat16* __restrict__ kl,
                 const __nv_bfloat16* __restrict__ vh, const __nv_bfloat16* __restrict__ vl,
                 const __nv_bfloat16* __restrict__ Wh, const __nv_bfloat16* __restrict__ Wl,
                 const float* __restrict__ bias,
                 __nv_bfloat16* __restrict__ oqh, __nv_bfloat16* __restrict__ oql,
                 __nv_bfloat16* __restrict__ okh, __nv_bfloat16* __restrict__ okl,
                 __nv_bfloat16* __restrict__ ovh, __nv_bfloat16* __restrict__ ovl)
{
    extern __shared__ char sm[];
    const int z = blockIdx.z;
    const __nv_bfloat16* Ah = (z == 0) ? qh : (z == 1) ? kh : vh;
    const __nv_bfloat16* Al = (z == 0) ? ql : (z == 1) ? kl : vl;
    __nv_bfloat16* Ch = (z == 0) ? oqh : (z == 1) ? okh : ovh;
    __nv_bfloat16* Cl = (z == 0) ? oql : (z == 1) ? okl : ovl;
    tc_gemm_body<1>(Ah, Al, Wh + (size_t)z * 1024 * 1024, Wl + (size_t)z * 1024 * 1024,
                    bias + z * 1024, nullptr, Ch, Cl, NTOK_PROJ, sm,
                    blockIdx.x * 128, blockIdx.y * 128);
}

// ---------------------------------------------------------------------------
// fp32 -> (bf16 hi, bf16 lo) split of raw inputs
// ---------------------------------------------------------------------------
__global__ __launch_bounds__(256) void split_bf16(
    const float4* __restrict__ x, uint2* __restrict__ hi, uint2* __restrict__ lo, int n4)
{
    int i = blockIdx.x * 256 + threadIdx.x;
    if (i < n4) {
        float4 v = x[i];
        uint32_t h0, l0, h1, l1;
        split2(v.x, v.y, h0, l0);
        split2(v.z, v.w, h1, l1);
        hi[i] = make_uint2(h0, h1);
        lo[i] = make_uint2(l0, l1);
    }
}

// dummy row s=1024: q/k/v row = raw query[-1], split into bf16 hi/lo
__global__ void fill_last_row_split(const float* __restrict__ query,
                                    __nv_bfloat16* __restrict__ qh, __nv_bfloat16* __restrict__ ql,
                                    __nv_bfloat16* __restrict__ kh, __nv_bfloat16* __restrict__ kl,
                                    __nv_bfloat16* __restrict__ vh, __nv_bfloat16* __restrict__ vl)
{
    int idx = blockIdx.x * 256 + threadIdx.x;    // 0..8191 (b*1024+e)
    if (idx < B_SZ * E_SZ) {
        size_t off = (size_t)1024 * 8192 + idx;  // same flat offset in src & dst
        float v = query[off];
        __nv_bfloat16 h = __float2bfloat16_rn(v);
        __nv_bfloat16 l = __float2bfloat16_rn(v - __bfloat162float(h));
        qh[off] = h; ql[off] = l;
        kh[off] = h; kl[off] = l;
        vh[off] = h; vl[off] = l;
    }
}

// ---------------------------------------------------------------------------
// Flash attention, split-bf16 mma.sync.
// CTA = 128 q rows x (b,h); 8 warps, each owns m16. Key blocks of 64,
// double-buffered cp.async. P kept in registers (acc layout == A-frag layout).
// smem: Qh/Ql 2x16KB + 2 stages x (Kh,Kl,Vh,Vl 4x8KB) = 96 KB.
// ---------------------------------------------------------------------------
#define ATTN_SMEM (32768 + 2 * 32768)

__global__ __launch_bounds__(256) void attn_bf16(
    const __nv_bfloat16* __restrict__ Qh, const __nv_bfloat16* __restrict__ Ql,
    const __nv_bfloat16* __restrict__ Kh, const __nv_bfloat16* __restrict__ Kl,
    const __nv_bfloat16* __restrict__ Vh, const __nv_bfloat16* __restrict__ Vl,
    __nv_bfloat16* __restrict__ Ch, __nv_bfloat16* __restrict__ Cl)
{
    extern __shared__ char sm[];
    const int tid = threadIdx.x, wid = tid >> 5, lane = tid & 31;
    const int qt = blockIdx.x;                 // 0..8 (q tile of 128)
    const int b = blockIdx.y >> 4, h = blockIdx.y & 15;
    const size_t colb = (size_t)h * 64;        // column base within e

    // ---- Q tile load (hi/lo), swizzled ----
#pragma unroll
    for (int i = 0; i < 8; ++i) {
        int ch = i * 256 + tid;                // 0..2047
        int arr = ch >> 10, cc = ch & 1023;
        int r = cc >> 3, c = cc & 7;
        uint32_t dst = smem_u32(sm + arr * 16384 + r * 128 + ((c ^ (r & 7)) << 4));
        int tok = qt * 128 + r;
        const __nv_bfloat16* sb = arr ? Ql : Qh;
        const char* src = (const char*)(sb + (size_t)(tok * 8 + b) * 1024 + colb + c * 8);
        CP_ASYNC16(dst, src, tok <= 1024 ? 16 : 0);
    }

    // ---- stage loader ----
    auto load_kv = [&](int kb, int st) {
        char* sbase = sm + 32768 + st * 32768;
#pragma unroll
        for (int i = 0; i < 8; ++i) {
            int ch = i * 256 + tid;            // 0..2047
            int arr = ch >> 9, cc = ch & 511;
            int r = cc >> 3, c = cc & 7;
            uint32_t dst = smem_u32(sbase + arr * 8192 + r * 128 + ((c ^ (r & 7)) << 4));
            int tok = kb * 64 + r;
            const __nv_bfloat16* p = (arr == 0) ? Kh : (arr == 1) ? Kl : (arr == 2) ? Vh : Vl;
            const char* src = (const char*)(p + (size_t)(tok * 8 + b) * 1024 + colb + c * 8);
            CP_ASYNC16(dst, src, tok <= 1024 ? 16 : 0);
        }
    };
    load_kv(0, 0);
    CP_COMMIT();

    float o[8][4];
#pragma unroll
    for (int nt = 0; nt < 8; ++nt)
#pragma unroll
        for (int j = 0; j < 4; ++j) o[nt][j] = 0.f;
    float m0 = -1e30f, m1 = -1e30f, l0 = 0.f, l1 = 0.f;

    const int a_row_l = lane & 15;
    const int a_chk_l = lane >> 4;
    const int b_row_l = (lane & 7) + ((lane >> 4) << 3);
    const int b_chk_l = (lane >> 3) & 1;
    const uint32_t sQhb = smem_u32(sm);
    const uint32_t sQlb = sQhb + 16384;

    for (int kb = 0; kb < 17; ++kb) {
        if (kb + 1 < 17) { load_kv(kb + 1, (kb + 1) & 1); CP_COMMIT(); CP_WAIT(1); }
        else CP_WAIT(0);
        __syncthreads();

        const uint32_t sKhb = smem_u32(sm + 32768 + (kb & 1) * 32768);
        const uint32_t sKlb = sKhb + 8192;
        const uint32_t sVhb = sKhb + 16384;
        const uint32_t sVlb = sKhb + 24576;

        // ---- S = Q K^T (split) ----
        float s[8][4];
#pragma unroll
        for (int nt = 0; nt < 8; ++nt)
#pragma unroll
            for (int j = 0; j < 4; ++j) s[nt][j] = 0.f;

#pragma unroll
        for (int ks = 0; ks < 4; ++ks) {
            uint32_t qhf[4], qlf[4];
            {
                int row = wid * 16 + a_row_l;
                int chk = ks * 2 + a_chk_l;
                uint32_t off = row * 128 + ((chk ^ (row & 7)) << 4);
                ldsm4(qhf, sQhb + off);
                ldsm4(qlf, sQlb + off);
            }
#pragma unroll
            for (int np = 0; np < 4; ++np) {
                uint32_t khf[4], klf[4];
                int row = np * 16 + b_row_l;
                int chk = ks * 2 + b_chk_l;
                uint32_t off = row * 128 + ((chk ^ (row & 7)) << 4);
                ldsm4(khf, sKhb + off);
                ldsm4(klf, sKlb + off);
                mma_bf16(s[np * 2],     qhf, &khf[0]);
                mma_bf16(s[np * 2 + 1], qhf, &khf[2]);
                mma_bf16(s[np * 2],     qhf, &klf[0]);
                mma_bf16(s[np * 2 + 1], qhf, &klf[2]);
                mma_bf16(s[np * 2],     qlf, &khf[0]);
                mma_bf16(s[np * 2 + 1], qlf, &khf[2]);
            }
        }

        // ---- scale + mask ----
#pragma unroll
        for (int nt = 0; nt < 8; ++nt)
#pragma unroll
            for (int j = 0; j < 4; ++j) s[nt][j] *= 0.125f;
        if (kb == 16) {
#pragma unroll
            for (int nt = 0; nt < 8; ++nt)
#pragma unroll
                for (int j = 0; j < 4; ++j) {
                    int tok = kb * 64 + nt * 8 + (lane & 3) * 2 + (j & 1);
                    if (tok > 1024) s[nt][j] = -1e30f;
                }
        }

        // ---- online softmax (rows: lane>>2 and +8) ----
        float tm0 = -1e30f, tm1 = -1e30f;
#pragma unroll
        for (int nt = 0; nt < 8; ++nt) {
            tm0 = fmaxf(tm0, fmaxf(s[nt][0], s[nt][1]));
            tm1 = fmaxf(tm1, fmaxf(s[nt][2], s[nt][3]));
        }
        tm0 = fmaxf(tm0, __shfl_xor_sync(0xffffffffu, tm0, 1));
        tm0 = fmaxf(tm0, __shfl_xor_sync(0xffffffffu, tm0, 2));
        tm1 = fmaxf(tm1, __shfl_xor_sync(0xffffffffu, tm1, 1));
        tm1 = fmaxf(tm1, __shfl_xor_sync(0xffffffffu, tm1, 2));
        float mn0 = fmaxf(m0, tm0), mn1 = fmaxf(m1, tm1);
        float cr0 = __expf(m0 - mn0), cr1 = __expf(m1 - mn1);
        float rs0 = 0.f, rs1 = 0.f;
#pragma unroll
        for (int nt = 0; nt < 8; ++nt) {
            s[nt][0] = __expf(s[nt][0] - mn0);
            s[nt][1] = __expf(s[nt][1] - mn0);
            s[nt][2] = __expf(s[nt][2] - mn1);
            s[nt][3] = __expf(s[nt][3] - mn1);
            rs0 += s[nt][0] + s[nt][1];
            rs1 += s[nt][2] + s[nt][3];
        }
        rs0 += __shfl_xor_sync(0xffffffffu, rs0, 1);
        rs0 += __shfl_xor_sync(0xffffffffu, rs0, 2);
        rs1 += __shfl_xor_sync(0xffffffffu, rs1, 1);
        rs1 += __shfl_xor_sync(0xffffffffu, rs1, 2);
        l0 = l0 * cr0 + rs0; l1 = l1 * cr1 + rs1;
        m0 = mn0; m1 = mn1;
#pragma unroll
        for (int nt = 0; nt < 8; ++nt) {
            o[nt][0] *= cr0; o[nt][1] *= cr0;
            o[nt][2] *= cr1; o[nt][3] *= cr1;
        }

        // ---- pack P fragments (acc layout == A-frag layout) ----
        uint32_t ph[4][4], pl[4][4];
#pragma unroll
        for (int k2 = 0; k2 < 4; ++k2) {
            int t0 = 2 * k2, t1 = t0 + 1;
            split2(s[t0][0], s[t0][1], ph[k2][0], pl[k2][0]);
            split2(s[t0][2], s[t0][3], ph[k2][1], pl[k2][1]);
            split2(s[t1][0], s[t1][1], ph[k2][2], pl[k2][2]);
            split2(s[t1][2], s[t1][3], ph[k2][3], pl[k2][3]);
        }

        // ---- O += P V (split), V via ldmatrix.trans ----
#pragma unroll
        for (int k2 = 0; k2 < 4; ++k2) {
#pragma unroll
            for (int ntp = 0; ntp < 4; ++ntp) {
                uint32_t vhf[4], vlf[4];
                int row = k2 * 16 + (lane & 15);
                int chk = ntp * 2 + (lane >> 4);
                uint32_t off = row * 128 + ((chk ^ (row & 7)) << 4);
                ldsm4_t(vhf, sVhb + off);
                ldsm4_t(vlf, sVlb + off);
                mma_bf16(o[ntp * 2],     ph[k2], &vhf[0]);
                mma_bf16(o[ntp * 2 + 1], ph[k2], &vhf[2]);
                mma_bf16(o[ntp * 2],     ph[k2], &vlf[0]);
                mma_bf16(o[ntp * 2 + 1], ph[k2], &vlf[2]);
                mma_bf16(o[ntp * 2],     pl[k2], &vhf[0]);
                mma_bf16(o[ntp * 2 + 1], pl[k2], &vhf[2]);
            }
        }
        __syncthreads();
    }

    // ---- epilogue: normalize, split to bf16 hi/lo, store ctx ----
    float inv0 = 1.f / l0, inv1 = 1.f / l1;
    int tok0 = qt * 128 + wid * 16 + (lane >> 2);
    int tok1 = tok0 + 8;
    int dbase = (lane & 3) * 2;
#pragma unroll
    for (int nt = 0; nt < 8; ++nt) {
        int d = nt * 8 + dbase;
        if (tok0 <= 1024) {
            size_t idx = (size_t)(tok0 * 8 + b) * 1024 + colb + d;
            uint32_t hi, lo;
            split2(o[nt][0] * inv0, o[nt][1] * inv0, hi, lo);
            *(uint32_t*)(Ch + idx) = hi;
            *(uint32_t*)(Cl + idx) = lo;
        }
        if (tok1 <= 1024) {
            size_t idx = (size_t)(tok1 * 8 + b) * 1024 + colb + d;
            uint32_t hi, lo;
            split2(o[nt][2] * inv1, o[nt][3] * inv1, hi, lo);
            *(uint32_t*)(Ch + idx) = hi;
            *(uint32_t*)(Cl + idx) = lo;
        }
    }
}

// ---------------------------------------------------------------------------
// Launch
// ---------------------------------------------------------------------------
extern "C" void kernel_launch(void* const* d_in, const int* in_sizes, int n_in,
                              void* d_out, int out_size)
{
    const float* query = (const float*)d_in[0];
    const float* key   = (const float*)d_in[1];
    const float* value = (const float*)d_in[2];
    const float* W_in  = (const float*)d_in[3];
    const float* b_in  = (const float*)d_in[4];
    const float* W_out = (const float*)d_in[5];
    const float* b_out = (const float*)d_in[6];
    float* out = (float*)d_out;

    __nv_bfloat16 *qh, *ql, *kh, *kl, *vh, *vl, *wih, *wil, *woh, *wol;
    __nv_bfloat16 *aqh, *aql, *akh, *akl, *avh, *avl, *ch, *cl;
    cudaGetSymbolAddress((void**)&qh,  g_qh);  cudaGetSymbolAddress((void**)&ql,  g_ql);
    cudaGetSymbolAddress((void**)&kh,  g_kh);  cudaGetSymbolAddress((void**)&kl,  g_kl);
    cudaGetSymbolAddress((void**)&vh,  g_vh);  cudaGetSymbolAddress((void**)&vl,  g_vl);
    cudaGetSymbolAddress((void**)&wih, g_wih); cudaGetSymbolAddress((void**)&wil, g_wil);
    cudaGetSymbolAddress((void**)&woh, g_woh); cudaGetSymbolAddress((void**)&wol, g_wol);
    cudaGetSymbolAddress((void**)&aqh, g_aqh); cudaGetSymbolAddress((void**)&aql, g_aql);
    cudaGetSymbolAddress((void**)&akh, g_akh); cudaGetSymbolAddress((void**)&akl, g_akl);
    cudaGetSymbolAddress((void**)&avh, g_avh); cudaGetSymbolAddress((void**)&avl, g_avl);
    cudaGetSymbolAddress((void**)&ch,  g_ch);  cudaGetSymbolAddress((void**)&cl,  g_cl);

    cudaFuncSetAttribute(tc_gemm_qkv, cudaFuncAttributeMaxDynamicSharedMemorySize, GK_SMEM);
    cudaFuncSetAttribute(tc_gemm_out, cudaFuncAttributeMaxDynamicSharedMemorySize, GK_SMEM);
    cudaFuncSetAttribute(attn_bf16,   cudaFuncAttributeMaxDynamicSharedMemorySize, ATTN_SMEM);

    // raw-input splits
    split_bf16<<<8192, 256>>>((const float4*)query, (uint2*)qh, (uint2*)ql, NTOK_PROJ * E_SZ / 4);
    split_bf16<<<8192, 256>>>((const float4*)key,   (uint2*)kh, (uint2*)kl, NTOK_PROJ * E_SZ / 4);
    split_bf16<<<8192, 256>>>((const float4*)value, (uint2*)vh, (uint2*)vl, NTOK_PROJ * E_SZ / 4);
    split_bf16<<<3072, 256>>>((const float4*)W_in,  (uint2*)wih, (uint2*)wil, 3072 * 1024 / 4);
    split_bf16<<<1024, 256>>>((const float4*)W_out, (uint2*)woh, (uint2*)wol, 1024 * 1024 / 4);

    // QKV projections -> split outputs (attention inputs)
    tc_gemm_qkv<<<dim3(8, 64, 3), 256, GK_SMEM>>>(qh, ql, kh, kl, vh, vl, wih, wil, b_in,
                                                  aqh, aql, akh, akl, avh, avl);

    // dummy row s=1024
    fill_last_row_split<<<32, 256>>>(query, aqh, aql, akh, akl, avh, avl);

    // attention (split-bf16 mma.sync)
    attn_bf16<<<dim3(9, B_SZ * H_CNT), 256, ATTN_SMEM>>>(aqh, aql, akh, akl, avh, avl, ch, cl);

    // out projection
    tc_gemm_out<<<dim3(8, 65), 256, GK_SMEM>>>(ch, cl, woh, wol, b_out, out, NTOK);
}

// round 8
// speedup vs baseline: 3.2366x; 1.0276x over previous
#include <cuda_runtime.h>
#include <cuda_bf16.h>
#include <cstdint>

// Problem constants
#define S_LEN 1025
#define B_SZ  8
#define E_SZ  1024
#define H_CNT 16
#define HD    64
#define NTOK  (S_LEN * B_SZ)          // 8200
#define NTOK_PROJ (1024 * B_SZ)       // 8192

// ---------------- scratch (device globals: allocation-free) ----------------
__device__ __nv_bfloat16 g_qh[NTOK_PROJ * E_SZ], g_ql[NTOK_PROJ * E_SZ];
__device__ __nv_bfloat16 g_kh[NTOK_PROJ * E_SZ], g_kl[NTOK_PROJ * E_SZ];
__device__ __nv_bfloat16 g_vh[NTOK_PROJ * E_SZ], g_vl[NTOK_PROJ * E_SZ];
__device__ __nv_bfloat16 g_wih[3072 * 1024],     g_wil[3072 * 1024];
__device__ __nv_bfloat16 g_woh[1024 * 1024],     g_wol[1024 * 1024];
__device__ __nv_bfloat16 g_aqh[NTOK * E_SZ], g_aql[NTOK * E_SZ];
__device__ __nv_bfloat16 g_akh[NTOK * E_SZ], g_akl[NTOK * E_SZ];
__device__ __nv_bfloat16 g_avh[NTOK * E_SZ], g_avl[NTOK * E_SZ];
__device__ __nv_bfloat16 g_ch[NTOK * E_SZ], g_cl[NTOK * E_SZ];

// ---------------- helpers (sm_80+ only; legal on bare compute_103) ---------
__device__ __forceinline__ uint32_t smem_u32(const void* p) {
    uint32_t a;
    asm("{ .reg .u64 t; cvta.to.shared.u64 t, %1; cvt.u32.u64 %0, t; }"
        : "=r"(a) : "l"(p));
    return a;
}
__device__ __forceinline__ void ldsm4(uint32_t* r, uint32_t addr) {
    asm volatile("ldmatrix.sync.aligned.m8n8.x4.shared.b16 {%0,%1,%2,%3}, [%4];"
                 : "=r"(r[0]), "=r"(r[1]), "=r"(r[2]), "=r"(r[3]) : "r"(addr));
}
__device__ __forceinline__ void ldsm4_t(uint32_t* r, uint32_t addr) {
    asm volatile("ldmatrix.sync.aligned.m8n8.x4.trans.shared.b16 {%0,%1,%2,%3}, [%4];"
                 : "=r"(r[0]), "=r"(r[1]), "=r"(r[2]), "=r"(r[3]) : "r"(addr));
}
__device__ __forceinline__ void mma_bf16(float* d, const uint32_t* a, const uint32_t* b) {
    asm volatile(
        "mma.sync.aligned.m16n8k16.row.col.f32.bf16.bf16.f32 "
        "{%0,%1,%2,%3}, {%4,%5,%6,%7}, {%8,%9}, {%0,%1,%2,%3};"
        : "+f"(d[0]), "+f"(d[1]), "+f"(d[2]), "+f"(d[3])
        : "r"(a[0]), "r"(a[1]), "r"(a[2]), "r"(a[3]), "r"(b[0]), "r"(b[1]));
}
#define CP_ASYNC16(dst, src, sz) \
    asm volatile("cp.async.cg.shared.global [%0], [%1], 16, %2;" \
                 :: "r"(dst), "l"(src), "r"(sz))
#define CP_COMMIT() asm volatile("cp.async.commit_group;" ::: "memory")
#define CP_WAIT(n)  asm volatile("cp.async.wait_group %0;" :: "n"(n) : "memory")

__device__ __forceinline__ void split2(float a, float b, uint32_t& hi, uint32_t& lo) {
    __nv_bfloat162 h = __floats2bfloat162_rn(a, b);
    float ra = a - __bfloat162float(__low2bfloat16(h));
    float rb = b - __bfloat162float(__high2bfloat16(h));
    __nv_bfloat162 l = __floats2bfloat162_rn(ra, rb);
    hi = *(uint32_t*)&h;
    lo = *(uint32_t*)&l;
}

// ---------------------------------------------------------------------------
// mma.sync split-bf16 GEMM, 3-stage cp.async pipeline (prefetch distance 2)
// ---------------------------------------------------------------------------
#define OP_BYTES    (128 * 128)
#define STAGE_BYTES (4 * OP_BYTES)        // 64 KB
#define GK_SMEM     (3 * STAGE_BYTES)     // 192 KB

__device__ __forceinline__ void load_stage(
    char* stage,
    const __nv_bfloat16* __restrict__ Ah, const __nv_bfloat16* __restrict__ Al,
    const __nv_bfloat16* __restrict__ Bh, const __nv_bfloat16* __restrict__ Bl,
    int m0, int n0, int k0, int M, int tid)
{
#pragma unroll
    for (int o = 0; o < 4; ++o) {
        const __nv_bfloat16* src_base = (o == 0) ? Ah : (o == 1) ? Al : (o == 2) ? Bh : Bl;
        const int row0 = (o < 2) ? m0 : n0;
        char* dstop = stage + o * OP_BYTES;
#pragma unroll
        for (int i = 0; i < 4; ++i) {
            int ch = i * 256 + tid;
            int r = ch >> 3, c = ch & 7;
            uint32_t dst = smem_u32(dstop + r * 128 + ((c ^ (r & 7)) << 4));
            const char* src = (const char*)(src_base + (size_t)(row0 + r) * 1024 + k0 + c * 8);
            int sz = (o >= 2 || (row0 + r) < M) ? 16 : 0;
            CP_ASYNC16(dst, src, sz);
        }
    }
}

template<int SPLIT_OUT>
__device__ __forceinline__ void tc_gemm_body(
    const __nv_bfloat16* __restrict__ Ah, const __nv_bfloat16* __restrict__ Al,
    const __nv_bfloat16* __restrict__ Wh, const __nv_bfloat16* __restrict__ Wl,
    const float* __restrict__ bias, float* __restrict__ C,
    __nv_bfloat16* __restrict__ Ch, __nv_bfloat16* __restrict__ Cl, int M,
    char* sm, int n0, int m0)
{
    const int tid = threadIdx.x;
    const int wid = tid >> 5, lane = tid & 31;
    const int wm = wid >> 2, wn = wid & 3;

    float acc[4][4][4];
#pragma unroll
    for (int a = 0; a < 4; ++a)
#pragma unroll
        for (int b = 0; b < 4; ++b)
#pragma unroll
            for (int c = 0; c < 4; ++c) acc[a][b][c] = 0.f;

    const int a_row_l = lane & 15;
    const int a_chk_l = lane >> 4;
    const int b_row_l = (lane & 7) + ((lane >> 4) << 3);
    const int b_chk_l = (lane >> 3) & 1;

    // prologue: stages 0, 1
    load_stage(sm,               Ah, Al, Wh, Wl, m0, n0, 0,  M, tid); CP_COMMIT();
    load_stage(sm + STAGE_BYTES, Ah, Al, Wh, Wl, m0, n0, 64, M, tid); CP_COMMIT();

    int cur = 0, pre = 2;
    for (int t = 0; t < 16; ++t) {
        CP_WAIT(1);                // stage t complete; t+1 may be in flight
        __syncthreads();           // all warps done with stage t-1 (slot == pre)
        if (t + 2 < 16)
            load_stage(sm + pre * STAGE_BYTES, Ah, Al, Wh, Wl, m0, n0, (t + 2) * 64, M, tid);
        CP_COMMIT();               // commit every iter (possibly empty) for uniform counting

        char* st = sm + cur * STAGE_BYTES;
        const uint32_t sAh = smem_u32(st);
        const uint32_t sAl = sAh + OP_BYTES;
        const uint32_t sBh = sAh + 2 * OP_BYTES;
        const uint32_t sBl = sAh + 3 * OP_BYTES;

#pragma unroll
        for (int ks = 0; ks < 4; ++ks) {
            uint32_t ah[4][4], al[4][4], bh[2][4], bl[2][4];
            const int achk = ks * 2 + a_chk_l;
#pragma unroll
            for (int mt = 0; mt < 4; ++mt) {
                int row = wm * 64 + mt * 16 + a_row_l;
                uint32_t off = row * 128 + ((achk ^ (row & 7)) << 4);
                ldsm4(ah[mt], sAh + off);
                ldsm4(al[mt], sAl + off);
            }
            const int bchk = ks * 2 + b_chk_l;
#pragma unroll
            for (int np = 0; np < 2; ++np) {
                int row = wn * 32 + np * 16 + b_row_l;
                uint32_t off = row * 128 + ((bchk ^ (row & 7)) << 4);
                ldsm4(bh[np], sBh + off);
                ldsm4(bl[np], sBl + off);
            }
#pragma unroll
            for (int mt = 0; mt < 4; ++mt)
#pragma unroll
                for (int np = 0; np < 2; ++np) {
                    mma_bf16(acc[mt][np * 2],     ah[mt], &bh[np][0]);
                    mma_bf16(acc[mt][np * 2 + 1], ah[mt], &bh[np][2]);
                    mma_bf16(acc[mt][np * 2],     ah[mt], &bl[np][0]);
                    mma_bf16(acc[mt][np * 2 + 1], ah[mt], &bl[np][2]);
                    mma_bf16(acc[mt][np * 2],     al[mt], &bh[np][0]);
                    mma_bf16(acc[mt][np * 2 + 1], al[mt], &bh[np][2]);
                }
        }
        cur = (cur == 2) ? 0 : cur + 1;
        pre = (pre == 2) ? 0 : pre + 1;
    }

#pragma unroll
    for (int mt = 0; mt < 4; ++mt) {
        int mA = m0 + wm * 64 + mt * 16 + (lane >> 2);
        int mB = mA + 8;
#pragma unroll
        for (int nt = 0; nt < 4; ++nt) {
            int n = n0 + wn * 32 + nt * 8 + (lane & 3) * 2;
            float2 bv = *(const float2*)&bias[n];
            float v0 = acc[mt][nt][0] + bv.x, v1 = acc[mt][nt][1] + bv.y;
            float v2 = acc[mt][nt][2] + bv.x, v3 = acc[mt][nt][3] + bv.y;
            if (SPLIT_OUT) {
                if (mA < M) {
                    uint32_t hi, lo; split2(v0, v1, hi, lo);
                    *(uint32_t*)(Ch + (size_t)mA * 1024 + n) = hi;
                    *(uint32_t*)(Cl + (size_t)mA * 1024 + n) = lo;
                }
                if (mB < M) {
                    uint32_t hi, lo; split2(v2, v3, hi, lo);
                    *(uint32_t*)(Ch + (size_t)mB * 1024 + n) = hi;
                    *(uint32_t*)(Cl + (size_t)mB * 1024 + n) = lo;
                }
            } else {
                if (mA < M) *(float2*)&C[(size_t)mA * 1024 + n] = make_float2(v0, v1);
                if (mB < M) *(float2*)&C[(size_t)mB * 1024 + n] = make_float2(v2, v3);
            }
        }
    }
}

__global__ __launch_bounds__(256)
void tc_gemm_out(const __nv_bfloat16* __restrict__ Ah, const __nv_bfloat16* __restrict__ Al,
                 const __nv_bfloat16* __restrict__ Wh, const __nv_bfloat16* __restrict__ Wl,
                 const float* __restrict__ bias, float* __restrict__ C, int M)
{
    extern __shared__ char sm[];
    tc_gemm_body<0>(Ah, Al, Wh, Wl, bias, C, nullptr, nullptr, M, sm,
                    blockIdx.x * 128, blockIdx.y * 128);
}

__global__ __launch_bounds__(256)
void tc_gemm_qkv(const __nv_bfloat16* __restrict__ qh, const __nv_bfloat16* __restrict__ ql,
                 const __nv_bfloat16* __restrict__ kh, const __nv_bfloat16* __restrict__ kl,
                 const __nv_bfloat16* __restrict__ vh, const __nv_bfloat16* __restrict__ vl,
                 const __nv_bfloat16* __restrict__ Wh, const __nv_bfloat16* __restrict__ Wl,
                 const float* __restrict__ bias,
                 __nv_bfloat16* __restrict__ oqh, __nv_bfloat16* __restrict__ oql,
                 __nv_bfloat16* __restrict__ okh, __nv_bfloat16* __restrict__ okl,
                 __nv_bfloat16* __restrict__ ovh, __nv_bfloat16* __restrict__ ovl)
{
    extern __shared__ char sm[];
    const int z = blockIdx.z;
    const __nv_bfloat16* Ah = (z == 0) ? qh : (z == 1) ? kh : vh;
    const __nv_bfloat16* Al = (z == 0) ? ql : (z == 1) ? kl : vl;
    __nv_bfloat16* Ch = (z == 0) ? oqh : (z == 1) ? okh : ovh;
    __nv_bfloat16* Cl = (z == 0) ? oql : (z == 1) ? okl : ovl;
    tc_gemm_body<1>(Ah, Al, Wh + (size_t)z * 1024 * 1024, Wl + (size_t)z * 1024 * 1024,
                    bias + z * 1024, nullptr, Ch, Cl, NTOK_PROJ, sm,
                    blockIdx.x * 128, blockIdx.y * 128);
}

// ---------------------------------------------------------------------------
// Fused fp32 -> (bf16 hi, bf16 lo) split of ALL five input tensors, 1 launch
// f4 layout: [q | k | v | W_in | W_out]
// ---------------------------------------------------------------------------
#define NQ4  (NTOK_PROJ * E_SZ / 4)      // 2,097,152 each for q/k/v
#define NWI4 (3072 * 1024 / 4)           // 786,432
#define NWO4 (1024 * 1024 / 4)           // 262,144
#define NSPLIT_TOT (3 * NQ4 + NWI4 + NWO4)

__global__ __launch_bounds__(256) void split_all(
    const float4* __restrict__ q, const float4* __restrict__ k, const float4* __restrict__ v,
    const float4* __restrict__ wi, const float4* __restrict__ wo,
    uint2* __restrict__ qh, uint2* __restrict__ ql,
    uint2* __restrict__ kh, uint2* __restrict__ kl,
    uint2* __restrict__ vh, uint2* __restrict__ vl,
    uint2* __restrict__ wih, uint2* __restrict__ wil,
    uint2* __restrict__ woh, uint2* __restrict__ wol)
{
    int i = blockIdx.x * 256 + threadIdx.x;
    if (i >= NSPLIT_TOT) return;
    const float4* src; uint2 *dh, *dl; int off;
    if (i < NQ4)            { src = q;  dh = qh;  dl = ql;  off = i; }
    else if (i < 2 * NQ4)   { src = k;  dh = kh;  dl = kl;  off = i - NQ4; }
    else if (i < 3 * NQ4)   { src = v;  dh = vh;  dl = vl;  off = i - 2 * NQ4; }
    else if (i < 3 * NQ4 + NWI4) { src = wi; dh = wih; dl = wil; off = i - 3 * NQ4; }
    else                    { src = wo; dh = woh; dl = wol; off = i - 3 * NQ4 - NWI4; }
    float4 val = src[off];
    uint32_t h0, l0, h1, l1;
    split2(val.x, val.y, h0, l0);
    split2(val.z, val.w, h1, l1);
    dh[off] = make_uint2(h0, h1);
    dl[off] = make_uint2(l0, l1);
}

// dummy row s=1024: q/k/v row = raw query[-1], split into bf16 hi/lo
__global__ void fill_last_row_split(const float* __restrict__ query,
                                    __nv_bfloat16* __restrict__ qh, __nv_bfloat16* __restrict__ ql,
                                    __nv_bfloat16* __restrict__ kh, __nv_bfloat16* __restrict__ kl,
                                    __nv_bfloat16* __restrict__ vh, __nv_bfloat16* __restrict__ vl)
{
    int idx = blockIdx.x * 256 + threadIdx.x;
    if (idx < B_SZ * E_SZ) {
        size_t off = (size_t)1024 * 8192 + idx;
        float v = query[off];
        __nv_bfloat16 h = __float2bfloat16_rn(v);
        __nv_bfloat16 l = __float2bfloat16_rn(v - __bfloat162float(h));
        qh[off] = h; ql[off] = l;
        kh[off] = h; kl[off] = l;
        vh[off] = h; vl[off] = l;
    }
}

// ---------------------------------------------------------------------------
// Flash attention, split-bf16 mma.sync (unchanged from round 6)
// ---------------------------------------------------------------------------
#define ATTN_SMEM (32768 + 2 * 32768)

__global__ __launch_bounds__(256) void attn_bf16(
    const __nv_bfloat16* __restrict__ Qh, const __nv_bfloat16* __restrict__ Ql,
    const __nv_bfloat16* __restrict__ Kh, const __nv_bfloat16* __restrict__ Kl,
    const __nv_bfloat16* __restrict__ Vh, const __nv_bfloat16* __restrict__ Vl,
    __nv_bfloat16* __restrict__ Ch, __nv_bfloat16* __restrict__ Cl)
{
    extern __shared__ char sm[];
    const int tid = threadIdx.x, wid = tid >> 5, lane = tid & 31;
    const int qt = blockIdx.x;
    const int b = blockIdx.y >> 4, h = blockIdx.y & 15;
    const size_t colb = (size_t)h * 64;

#pragma unroll
    for (int i = 0; i < 8; ++i) {
        int ch = i * 256 + tid;
        int arr = ch >> 10, cc = ch & 1023;
        int r = cc >> 3, c = cc & 7;
        uint32_t dst = smem_u32(sm + arr * 16384 + r * 128 + ((c ^ (r & 7)) << 4));
        int tok = qt * 128 + r;
        const __nv_bfloat16* sb = arr ? Ql : Qh;
        const char* src = (const char*)(sb + (size_t)(tok * 8 + b) * 1024 + colb + c * 8);
        CP_ASYNC16(dst, src, tok <= 1024 ? 16 : 0);
    }

    auto load_kv = [&](int kb, int st) {
        char* sbase = sm + 32768 + st * 32768;
#pragma unroll
        for (int i = 0; i < 8; ++i) {
            int ch = i * 256 + tid;
            int arr = ch >> 9, cc = ch & 511;
            int r = cc >> 3, c = cc & 7;
            uint32_t dst = smem_u32(sbase + arr * 8192 + r * 128 + ((c ^ (r & 7)) << 4));
            int tok = kb * 64 + r;
            const __nv_bfloat16* p = (arr == 0) ? Kh : (arr == 1) ? Kl : (arr == 2) ? Vh : Vl;
            const char* src = (const char*)(p + (size_t)(tok * 8 + b) * 1024 + colb + c * 8);
            CP_ASYNC16(dst, src, tok <= 1024 ? 16 : 0);
        }
    };
    load_kv(0, 0);
    CP_COMMIT();

    float o[8][4];
#pragma unroll
    for (int nt = 0; nt < 8; ++nt)
#pragma unroll
        for (int j = 0; j < 4; ++j) o[nt][j] = 0.f;
    float m0 = -1e30f, m1 = -1e30f, l0 = 0.f, l1 = 0.f;

    const int a_row_l = lane & 15;
    const int a_chk_l = lane >> 4;
    const int b_row_l = (lane & 7) + ((lane >> 4) << 3);
    const int b_chk_l = (lane >> 3) & 1;
    const uint32_t sQhb = smem_u32(sm);
    const uint32_t sQlb = sQhb + 16384;

    for (int kb = 0; kb < 17; ++kb) {
        if (kb + 1 < 17) { load_kv(kb + 1, (kb + 1) & 1); CP_COMMIT(); CP_WAIT(1); }
        else CP_WAIT(0);
        __syncthreads();

        const uint32_t sKhb = smem_u32(sm + 32768 + (kb & 1) * 32768);
        const uint32_t sKlb = sKhb + 8192;
        const uint32_t sVhb = sKhb + 16384;
        const uint32_t sVlb = sKhb + 24576;

        float s[8][4];
#pragma unroll
        for (int nt = 0; nt < 8; ++nt)
#pragma unroll
            for (int j = 0; j < 4; ++j) s[nt][j] = 0.f;

#pragma unroll
        for (int ks = 0; ks < 4; ++ks) {
            uint32_t qhf[4], qlf[4];
            {
                int row = wid * 16 + a_row_l;
                int chk = ks * 2 + a_chk_l;
                uint32_t off = row * 128 + ((chk ^ (row & 7)) << 4);
                ldsm4(qhf, sQhb + off);
                ldsm4(qlf, sQlb + off);
            }
#pragma unroll
            for (int np = 0; np < 4; ++np) {
                uint32_t khf[4], klf[4];
                int row = np * 16 + b_row_l;
                int chk = ks * 2 + b_chk_l;
                uint32_t off = row * 128 + ((chk ^ (row & 7)) << 4);
                ldsm4(khf, sKhb + off);
                ldsm4(klf, sKlb + off);
                mma_bf16(s[np * 2],     qhf, &khf[0]);
                mma_bf16(s[np * 2 + 1], qhf, &khf[2]);
                mma_bf16(s[np * 2],     qhf, &klf[0]);
                mma_bf16(s[np * 2 + 1], qhf, &klf[2]);
                mma_bf16(s[np * 2],     qlf, &khf[0]);
                mma_bf16(s[np * 2 + 1], qlf, &khf[2]);
            }
        }

#pragma unroll
        for (int nt = 0; nt < 8; ++nt)
#pragma unroll
            for (int j = 0; j < 4; ++j) s[nt][j] *= 0.125f;
        if (kb == 16) {
#pragma unroll
            for (int nt = 0; nt < 8; ++nt)
#pragma unroll
                for (int j = 0; j < 4; ++j) {
                    int tok = kb * 64 + nt * 8 + (lane & 3) * 2 + (j & 1);
                    if (tok > 1024) s[nt][j] = -1e30f;
                }
        }

        float tm0 = -1e30f, tm1 = -1e30f;
#pragma unroll
        for (int nt = 0; nt < 8; ++nt) {
            tm0 = fmaxf(tm0, fmaxf(s[nt][0], s[nt][1]));
            tm1 = fmaxf(tm1, fmaxf(s[nt][2], s[nt][3]));
        }
        tm0 = fmaxf(tm0, __shfl_xor_sync(0xffffffffu, tm0, 1));
        tm0 = fmaxf(tm0, __shfl_xor_sync(0xffffffffu, tm0, 2));
        tm1 = fmaxf(tm1, __shfl_xor_sync(0xffffffffu, tm1, 1));
        tm1 = fmaxf(tm1, __shfl_xor_sync(0xffffffffu, tm1, 2));
        float mn0 = fmaxf(m0, tm0), mn1 = fmaxf(m1, tm1);
        float cr0 = __expf(m0 - mn0), cr1 = __expf(m1 - mn1);
        float rs0 = 0.f, rs1 = 0.f;
#pragma unroll
        for (int nt = 0; nt < 8; ++nt) {
            s[nt][0] = __expf(s[nt][0] - mn0);
            s[nt][1] = __expf(s[nt][1] - mn0);
            s[nt][2] = __expf(s[nt][2] - mn1);
            s[nt][3] = __expf(s[nt][3] - mn1);
            rs0 += s[nt][0] + s[nt][1];
            rs1 += s[nt][2] + s[nt][3];
        }
        rs0 += __shfl_xor_sync(0xffffffffu, rs0, 1);
        rs0 += __shfl_xor_sync(0xffffffffu, rs0, 2);
        rs1 += __shfl_xor_sync(0xffffffffu, rs1, 1);
        rs1 += __shfl_xor_sync(0xffffffffu, rs1, 2);
        l0 = l0 * cr0 + rs0; l1 = l1 * cr1 + rs1;
        m0 = mn0; m1 = mn1;
#pragma unroll
        for (int nt = 0; nt < 8; ++nt) {
            o[nt][0] *= cr0; o[nt][1] *= cr0;
            o[nt][2] *= cr1; o[nt][3] *= cr1;
        }

        uint32_t ph[4][4], pl[4][4];
#pragma unroll
        for (int k2 = 0; k2 < 4; ++k2) {
            int t0 = 2 * k2, t1 = t0 + 1;
            split2(s[t0][0], s[t0][1], ph[k2][0], pl[k2][0]);
            split2(s[t0][2], s[t0][3], ph[k2][1], pl[k2][1]);
            split2(s[t1][0], s[t1][1], ph[k2][2], pl[k2][2]);
            split2(s[t1][2], s[t1][3], ph[k2][3], pl[k2][3]);
        }

#pragma unroll
        for (int k2 = 0; k2 < 4; ++k2) {
#pragma unroll
            for (int ntp = 0; ntp < 4; ++ntp) {
                uint32_t vhf[4], vlf[4];
                int row = k2 * 16 + (lane & 15);
                int chk = ntp * 2 + (lane >> 4);
                uint32_t off = row * 128 + ((chk ^ (row & 7)) << 4);
                ldsm4_t(vhf, sVhb + off);
                ldsm4_t(vlf, sVlb + off);
                mma_bf16(o[ntp * 2],     ph[k2], &vhf[0]);
                mma_bf16(o[ntp * 2 + 1], ph[k2], &vhf[2]);
                mma_bf16(o[ntp * 2],     ph[k2], &vlf[0]);
                mma_bf16(o[ntp * 2 + 1], ph[k2], &vlf[2]);
                mma_bf16(o[ntp * 2],     pl[k2], &vhf[0]);
                mma_bf16(o[ntp * 2 + 1], pl[k2], &vhf[2]);
            }
        }
        __syncthreads();
    }

    float inv0 = 1.f / l0, inv1 = 1.f / l1;
    int tok0 = qt * 128 + wid * 16 + (lane >> 2);
    int tok1 = tok0 + 8;
    int dbase = (lane & 3) * 2;
#pragma unroll
    for (int nt = 0; nt < 8; ++nt) {
        int d = nt * 8 + dbase;
        if (tok0 <= 1024) {
            size_t idx = (size_t)(tok0 * 8 + b) * 1024 + colb + d;
            uint32_t hi, lo;
            split2(o[nt][0] * inv0, o[nt][1] * inv0, hi, lo);
            *(uint32_t*)(Ch + idx) = hi;
            *(uint32_t*)(Cl + idx) = lo;
        }
        if (tok1 <= 1024) {
            size_t idx = (size_t)(tok1 * 8 + b) * 1024 + colb + d;
            uint32_t hi, lo;
            split2(o[nt][2] * inv1, o[nt][3] * inv1, hi, lo);
            *(uint32_t*)(Ch + idx) = hi;
            *(uint32_t*)(Cl + idx) = lo;
        }
    }
}

// ---------------------------------------------------------------------------
// Launch
// ---------------------------------------------------------------------------
extern "C" void kernel_launch(void* const* d_in, const int* in_sizes, int n_in,
                              void* d_out, int out_size)
{
    const float* query = (const float*)d_in[0];
    const float* key   = (const float*)d_in[1];
    const float* value = (const float*)d_in[2];
    const float* W_in  = (const float*)d_in[3];
    const float* b_in  = (const float*)d_in[4];
    const float* W_out = (const float*)d_in[5];
    const float* b_out = (const float*)d_in[6];
    float* out = (float*)d_out;

    __nv_bfloat16 *qh, *ql, *kh, *kl, *vh, *vl, *wih, *wil, *woh, *wol;
    __nv_bfloat16 *aqh, *aql, *akh, *akl, *avh, *avl, *ch, *cl;
    cudaGetSymbolAddress((void**)&qh,  g_qh);  cudaGetSymbolAddress((void**)&ql,  g_ql);
    cudaGetSymbolAddress((void**)&kh,  g_kh);  cudaGetSymbolAddress((void**)&kl,  g_kl);
    cudaGetSymbolAddress((void**)&vh,  g_vh);  cudaGetSymbolAddress((void**)&vl,  g_vl);
    cudaGetSymbolAddress((void**)&wih, g_wih); cudaGetSymbolAddress((void**)&wil, g_wil);
    cudaGetSymbolAddress((void**)&woh, g_woh); cudaGetSymbolAddress((void**)&wol, g_wol);
    cudaGetSymbolAddress((void**)&aqh, g_aqh); cudaGetSymbolAddress((void**)&aql, g_aql);
    cudaGetSymbolAddress((void**)&akh, g_akh); cudaGetSymbolAddress((void**)&akl, g_akl);
    cudaGetSymbolAddress((void**)&avh, g_avh); cudaGetSymbolAddress((void**)&avl, g_avl);
    cudaGetSymbolAddress((void**)&ch,  g_ch);  cudaGetSymbolAddress((void**)&cl,  g_cl);

    cudaFuncSetAttribute(tc_gemm_qkv, cudaFuncAttributeMaxDynamicSharedMemorySize, GK_SMEM);
    cudaFuncSetAttribute(tc_gemm_out, cudaFuncAttributeMaxDynamicSharedMemorySize, GK_SMEM);
    cudaFuncSetAttribute(attn_bf16,   cudaFuncAttributeMaxDynamicSharedMemorySize, ATTN_SMEM);

    // fused raw-input splits (single launch)
    split_all<<<(NSPLIT_TOT + 255) / 256, 256>>>(
        (const float4*)query, (const float4*)key, (const float4*)value,
        (const float4*)W_in, (const float4*)W_out,
        (uint2*)qh, (uint2*)ql, (uint2*)kh, (uint2*)kl, (uint2*)vh, (uint2*)vl,
        (uint2*)wih, (uint2*)wil, (uint2*)woh, (uint2*)wol);

    // QKV projections -> split outputs
    tc_gemm_qkv<<<dim3(8, 64, 3), 256, GK_SMEM>>>(qh, ql, kh, kl, vh, vl, wih, wil, b_in,
                                                  aqh, aql, akh, akl, avh, avl);

    fill_last_row_split<<<32, 256>>>(query, aqh, aql, akh, akl, avh, avl);

    // attention (split-bf16 mma.sync)
    attn_bf16<<<dim3(9, B_SZ * H_CNT), 256, ATTN_SMEM>>>(aqh, aql, akh, akl, avh, avl, ch, cl);

    // out projection
    tc_gemm_out<<<dim3(8, 65), 256, GK_SMEM>>>(ch, cl, woh, wol, b_out, out, NTOK);
}

// round 10
// speedup vs baseline: 3.9231x; 1.2121x over previous
#include <cuda_runtime.h>
#include <cuda_bf16.h>
#include <cuda_fp16.h>
#include <cstdint>

// Problem constants
#define S_LEN 1025
#define B_SZ  8
#define E_SZ  1024
#define H_CNT 16
#define HD    64
#define NTOK  (S_LEN * B_SZ)          // 8200
#define NTOK_PROJ (1024 * B_SZ)       // 8192

// ---------------- scratch (device globals: allocation-free) ----------------
__device__ __nv_bfloat16 g_qh[NTOK_PROJ * E_SZ], g_ql[NTOK_PROJ * E_SZ];
__device__ __nv_bfloat16 g_kh[NTOK_PROJ * E_SZ], g_kl[NTOK_PROJ * E_SZ];
__device__ __nv_bfloat16 g_vh[NTOK_PROJ * E_SZ], g_vl[NTOK_PROJ * E_SZ];
__device__ __nv_bfloat16 g_wih[3072 * 1024],     g_wil[3072 * 1024];
__device__ __nv_bfloat16 g_woh[1024 * 1024],     g_wol[1024 * 1024];
__device__ __half        g_aq[NTOK * E_SZ];      // projected q (pre-scaled by 0.125), fp16
__device__ __half        g_ak[NTOK * E_SZ];      // projected k, fp16
__device__ __half        g_av[NTOK * E_SZ];      // projected v, fp16
__device__ __nv_bfloat16 g_ch[NTOK * E_SZ], g_cl[NTOK * E_SZ];   // ctx split (bf16)

// ---------------- helpers (sm_80+ only; legal on bare compute_103) ---------
__device__ __forceinline__ uint32_t smem_u32(const void* p) {
    uint32_t a;
    asm("{ .reg .u64 t; cvta.to.shared.u64 t, %1; cvt.u32.u64 %0, t; }"
        : "=r"(a) : "l"(p));
    return a;
}
__device__ __forceinline__ void ldsm4(uint32_t* r, uint32_t addr) {
    asm volatile("ldmatrix.sync.aligned.m8n8.x4.shared.b16 {%0,%1,%2,%3}, [%4];"
                 : "=r"(r[0]), "=r"(r[1]), "=r"(r[2]), "=r"(r[3]) : "r"(addr));
}
__device__ __forceinline__ void ldsm4_t(uint32_t* r, uint32_t addr) {
    asm volatile("ldmatrix.sync.aligned.m8n8.x4.trans.shared.b16 {%0,%1,%2,%3}, [%4];"
                 : "=r"(r[0]), "=r"(r[1]), "=r"(r[2]), "=r"(r[3]) : "r"(addr));
}
__device__ __forceinline__ void mma_bf16(float* d, const uint32_t* a, const uint32_t* b) {
    asm volatile(
        "mma.sync.aligned.m16n8k16.row.col.f32.bf16.bf16.f32 "
        "{%0,%1,%2,%3}, {%4,%5,%6,%7}, {%8,%9}, {%0,%1,%2,%3};"
        : "+f"(d[0]), "+f"(d[1]), "+f"(d[2]), "+f"(d[3])
        : "r"(a[0]), "r"(a[1]), "r"(a[2]), "r"(a[3]), "r"(b[0]), "r"(b[1]));
}
__device__ __forceinline__ void mma_f16(float* d, const uint32_t* a, const uint32_t* b) {
    asm volatile(
        "mma.sync.aligned.m16n8k16.row.col.f32.f16.f16.f32 "
        "{%0,%1,%2,%3}, {%4,%5,%6,%7}, {%8,%9}, {%0,%1,%2,%3};"
        : "+f"(d[0]), "+f"(d[1]), "+f"(d[2]), "+f"(d[3])
        : "r"(a[0]), "r"(a[1]), "r"(a[2]), "r"(a[3]), "r"(b[0]), "r"(b[1]));
}
#define CP_ASYNC16(dst, src, sz) \
    asm volatile("cp.async.cg.shared.global [%0], [%1], 16, %2;" \
                 :: "r"(dst), "l"(src), "r"(sz))
#define CP_COMMIT() asm volatile("cp.async.commit_group;" ::: "memory")
#define CP_WAIT(n)  asm volatile("cp.async.wait_group %0;" :: "n"(n) : "memory")

__device__ __forceinline__ void split2(float a, float b, uint32_t& hi, uint32_t& lo) {
    __nv_bfloat162 h = __floats2bfloat162_rn(a, b);
    float ra = a - __bfloat162float(__low2bfloat16(h));
    float rb = b - __bfloat162float(__high2bfloat16(h));
    __nv_bfloat162 l = __floats2bfloat162_rn(ra, rb);
    hi = *(uint32_t*)&h;
    lo = *(uint32_t*)&l;
}
__device__ __forceinline__ void split2h(float a, float b, uint32_t& hi, uint32_t& lo) {
    __half2 h = __floats2half2_rn(a, b);
    float ra = a - __half2float(__low2half(h));
    float rb = b - __half2float(__high2half(h));
    __half2 l = __floats2half2_rn(ra, rb);
    hi = *(uint32_t*)&h;
    lo = *(uint32_t*)&l;
}

// ---------------------------------------------------------------------------
// mma.sync split-bf16 GEMM, 3-stage cp.async pipeline.
// OUT_MODE 0: fp32 C.  OUT_MODE 2: fp16 H (scaled by oscale after bias).
// ---------------------------------------------------------------------------
#define OP_BYTES    (128 * 128)
#define STAGE_BYTES (4 * OP_BYTES)
#define GK_SMEM     (3 * STAGE_BYTES)     // 192 KB

__device__ __forceinline__ void load_stage(
    char* stage,
    const __nv_bfloat16* __restrict__ Ah, const __nv_bfloat16* __restrict__ Al,
    const __nv_bfloat16* __restrict__ Bh, const __nv_bfloat16* __restrict__ Bl,
    int m0, int n0, int k0, int M, int tid)
{
#pragma unroll
    for (int o = 0; o < 4; ++o) {
        const __nv_bfloat16* src_base = (o == 0) ? Ah : (o == 1) ? Al : (o == 2) ? Bh : Bl;
        const int row0 = (o < 2) ? m0 : n0;
        char* dstop = stage + o * OP_BYTES;
#pragma unroll
        for (int i = 0; i < 4; ++i) {
            int ch = i * 256 + tid;
            int r = ch >> 3, c = ch & 7;
            uint32_t dst = smem_u32(dstop + r * 128 + ((c ^ (r & 7)) << 4));
            const char* src = (const char*)(src_base + (size_t)(row0 + r) * 1024 + k0 + c * 8);
            int sz = (o >= 2 || (row0 + r) < M) ? 16 : 0;
            CP_ASYNC16(dst, src, sz);
        }
    }
}

template<int OUT_MODE>
__device__ __forceinline__ void tc_gemm_body(
    const __nv_bfloat16* __restrict__ Ah, const __nv_bfloat16* __restrict__ Al,
    const __nv_bfloat16* __restrict__ Wh, const __nv_bfloat16* __restrict__ Wl,
    const float* __restrict__ bias, float* __restrict__ C,
    __half* __restrict__ H, float oscale, int M,
    char* sm, int n0, int m0)
{
    const int tid = threadIdx.x;
    const int wid = tid >> 5, lane = tid & 31;
    const int wm = wid >> 2, wn = wid & 3;

    float acc[4][4][4];
#pragma unroll
    for (int a = 0; a < 4; ++a)
#pragma unroll
        for (int b = 0; b < 4; ++b)
#pragma unroll
            for (int c = 0; c < 4; ++c) acc[a][b][c] = 0.f;

    const int a_row_l = lane & 15;
    const int a_chk_l = lane >> 4;
    const int b_row_l = (lane & 7) + ((lane >> 4) << 3);
    const int b_chk_l = (lane >> 3) & 1;

    load_stage(sm,               Ah, Al, Wh, Wl, m0, n0, 0,  M, tid); CP_COMMIT();
    load_stage(sm + STAGE_BYTES, Ah, Al, Wh, Wl, m0, n0, 64, M, tid); CP_COMMIT();

    int cur = 0, pre = 2;
    for (int t = 0; t < 16; ++t) {
        CP_WAIT(1);
        __syncthreads();
        if (t + 2 < 16)
            load_stage(sm + pre * STAGE_BYTES, Ah, Al, Wh, Wl, m0, n0, (t + 2) * 64, M, tid);
        CP_COMMIT();

        char* st = sm + cur * STAGE_BYTES;
        const uint32_t sAh = smem_u32(st);
        const uint32_t sAl = sAh + OP_BYTES;
        const uint32_t sBh = sAh + 2 * OP_BYTES;
        const uint32_t sBl = sAh + 3 * OP_BYTES;

#pragma unroll
        for (int ks = 0; ks < 4; ++ks) {
            uint32_t ah[4][4], al[4][4], bh[2][4], bl[2][4];
            const int achk = ks * 2 + a_chk_l;
#pragma unroll
            for (int mt = 0; mt < 4; ++mt) {
                int row = wm * 64 + mt * 16 + a_row_l;
                uint32_t off = row * 128 + ((achk ^ (row & 7)) << 4);
                ldsm4(ah[mt], sAh + off);
                ldsm4(al[mt], sAl + off);
            }
            const int bchk = ks * 2 + b_chk_l;
#pragma unroll
            for (int np = 0; np < 2; ++np) {
                int row = wn * 32 + np * 16 + b_row_l;
                uint32_t off = row * 128 + ((bchk ^ (row & 7)) << 4);
                ldsm4(bh[np], sBh + off);
                ldsm4(bl[np], sBl + off);
            }
#pragma unroll
            for (int mt = 0; mt < 4; ++mt)
#pragma unroll
                for (int np = 0; np < 2; ++np) {
                    mma_bf16(acc[mt][np * 2],     ah[mt], &bh[np][0]);
                    mma_bf16(acc[mt][np * 2 + 1], ah[mt], &bh[np][2]);
                    mma_bf16(acc[mt][np * 2],     ah[mt], &bl[np][0]);
                    mma_bf16(acc[mt][np * 2 + 1], ah[mt], &bl[np][2]);
                    mma_bf16(acc[mt][np * 2],     al[mt], &bh[np][0]);
                    mma_bf16(acc[mt][np * 2 + 1], al[mt], &bh[np][2]);
                }
        }
        cur = (cur == 2) ? 0 : cur + 1;
        pre = (pre == 2) ? 0 : pre + 1;
    }

#pragma unroll
    for (int mt = 0; mt < 4; ++mt) {
        int mA = m0 + wm * 64 + mt * 16 + (lane >> 2);
        int mB = mA + 8;
#pragma unroll
        for (int nt = 0; nt < 4; ++nt) {
            int n = n0 + wn * 32 + nt * 8 + (lane & 3) * 2;
            float2 bv = *(const float2*)&bias[n];
            float v0 = acc[mt][nt][0] + bv.x, v1 = acc[mt][nt][1] + bv.y;
            float v2 = acc[mt][nt][2] + bv.x, v3 = acc[mt][nt][3] + bv.y;
            if (OUT_MODE == 2) {
                if (mA < M) {
                    __half2 hv = __floats2half2_rn(v0 * oscale, v1 * oscale);
                    *(uint32_t*)(H + (size_t)mA * 1024 + n) = *(uint32_t*)&hv;
                }
                if (mB < M) {
                    __half2 hv = __floats2half2_rn(v2 * oscale, v3 * oscale);
                    *(uint32_t*)(H + (size_t)mB * 1024 + n) = *(uint32_t*)&hv;
                }
            } else {
                if (mA < M) *(float2*)&C[(size_t)mA * 1024 + n] = make_float2(v0, v1);
                if (mB < M) *(float2*)&C[(size_t)mB * 1024 + n] = make_float2(v2, v3);
            }
        }
    }
}

__global__ __launch_bounds__(256)
void tc_gemm_out(const __nv_bfloat16* __restrict__ Ah, const __nv_bfloat16* __restrict__ Al,
                 const __nv_bfloat16* __restrict__ Wh, const __nv_bfloat16* __restrict__ Wl,
                 const float* __restrict__ bias, float* __restrict__ C, int M)
{
    extern __shared__ char sm[];
    tc_gemm_body<0>(Ah, Al, Wh, Wl, bias, C, nullptr, 1.f, M, sm,
                    blockIdx.x * 128, blockIdx.y * 128);
}

__global__ __launch_bounds__(256)
void tc_gemm_qkv(const __nv_bfloat16* __restrict__ qh, const __nv_bfloat16* __restrict__ ql,
                 const __nv_bfloat16* __restrict__ kh, const __nv_bfloat16* __restrict__ kl,
                 const __nv_bfloat16* __restrict__ vh, const __nv_bfloat16* __restrict__ vl,
                 const __nv_bfloat16* __restrict__ Wh, const __nv_bfloat16* __restrict__ Wl,
                 const float* __restrict__ bias,
                 __half* __restrict__ oq, __half* __restrict__ ok, __half* __restrict__ ov)
{
    extern __shared__ char sm[];
    const int z = blockIdx.z;
    const __nv_bfloat16* Ah = (z == 0) ? qh : (z == 1) ? kh : vh;
    const __nv_bfloat16* Al = (z == 0) ? ql : (z == 1) ? kl : vl;
    __half* H = (z == 0) ? oq : (z == 1) ? ok : ov;
    float oscale = (z == 0) ? 0.125f : 1.f;    // fold softmax scale into q
    tc_gemm_body<2>(Ah, Al, Wh + (size_t)z * 1024 * 1024, Wl + (size_t)z * 1024 * 1024,
                    bias + z * 1024, nullptr, H, oscale, NTOK_PROJ, sm,
                    blockIdx.x * 128, blockIdx.y * 128);
}

// ---------------------------------------------------------------------------
// Fused fp32 -> (bf16 hi, bf16 lo) split of ALL five input tensors, 1 launch
// ---------------------------------------------------------------------------
#define NQ4  (NTOK_PROJ * E_SZ / 4)
#define NWI4 (3072 * 1024 / 4)
#define NWO4 (1024 * 1024 / 4)
#define NSPLIT_TOT (3 * NQ4 + NWI4 + NWO4)

__global__ __launch_bounds__(256) void split_all(
    const float4* __restrict__ q, const float4* __restrict__ k, const float4* __restrict__ v,
    const float4* __restrict__ wi, const float4* __restrict__ wo,
    uint2* __restrict__ qh, uint2* __restrict__ ql,
    uint2* __restrict__ kh, uint2* __restrict__ kl,
    uint2* __restrict__ vh, uint2* __restrict__ vl,
    uint2* __restrict__ wih, uint2* __restrict__ wil,
    uint2* __restrict__ woh, uint2* __restrict__ wol)
{
    int i = blockIdx.x * 256 + threadIdx.x;
    if (i >= NSPLIT_TOT) return;
    const float4* src; uint2 *dh, *dl; int off;
    if (i < NQ4)            { src = q;  dh = qh;  dl = ql;  off = i; }
    else if (i < 2 * NQ4)   { src = k;  dh = kh;  dl = kl;  off = i - NQ4; }
    else if (i < 3 * NQ4)   { src = v;  dh = vh;  dl = vl;  off = i - 2 * NQ4; }
    else if (i < 3 * NQ4 + NWI4) { src = wi; dh = wih; dl = wil; off = i - 3 * NQ4; }
    else                    { src = wo; dh = woh; dl = wol; off = i - 3 * NQ4 - NWI4; }
    float4 val = src[off];
    uint32_t h0, l0, h1, l1;
    split2(val.x, val.y, h0, l0);
    split2(val.z, val.w, h1, l1);
    dh[off] = make_uint2(h0, h1);
    dl[off] = make_uint2(l0, l1);
}

// dummy row s=1024: q (scaled by 0.125) / k / v = raw query[-1], as fp16
__global__ void fill_last_row_f16(const float* __restrict__ query,
                                  __half* __restrict__ aq, __half* __restrict__ ak,
                                  __half* __restrict__ av)
{
    int idx = blockIdx.x * 256 + threadIdx.x;
    if (idx < B_SZ * E_SZ) {
        size_t off = (size_t)1024 * 8192 + idx;
        float v = query[off];
        aq[off] = __float2half_rn(v * 0.125f);
        ak[off] = __float2half_rn(v);
        av[off] = __float2half_rn(v);
    }
}

// ---------------------------------------------------------------------------
// Flash attention, fp16 mma.sync: QK 1-term (q pre-scaled), PV 2-term (split P).
// CTA = 128 q rows x (b,h); 8 warps each own m16. Key blocks of 64, dbl-buffered.
// smem: Q 16KB + 2 stages x (K 8KB + V 8KB) = 48 KB.
// ---------------------------------------------------------------------------
#define ATTN_SMEM (16384 + 2 * 16384)

__global__ __launch_bounds__(256) void attn_f16(
    const __half* __restrict__ Qf, const __half* __restrict__ Kf,
    const __half* __restrict__ Vf,
    __nv_bfloat16* __restrict__ Ch, __nv_bfloat16* __restrict__ Cl)
{
    extern __shared__ char sm[];
    const int tid = threadIdx.x, wid = tid >> 5, lane = tid & 31;
    const int qt = blockIdx.x;
    const int b = blockIdx.y >> 4, h = blockIdx.y & 15;
    const size_t colb = (size_t)h * 64;

    // ---- Q tile (128 x 64 fp16 = 16KB), swizzled ----
#pragma unroll
    for (int i = 0; i < 4; ++i) {
        int ch = i * 256 + tid;              // 0..1023 16B chunks
        int r = ch >> 3, c = ch & 7;
        uint32_t dst = smem_u32(sm + r * 128 + ((c ^ (r & 7)) << 4));
        int tok = qt * 128 + r;
        const char* src = (const char*)(Qf + (size_t)(tok * 8 + b) * 1024 + colb + c * 8);
        CP_ASYNC16(dst, src, tok <= 1024 ? 16 : 0);
    }

    auto load_kv = [&](int kb, int st) {
        char* sbase = sm + 16384 + st * 16384;
#pragma unroll
        for (int i = 0; i < 4; ++i) {
            int ch = i * 256 + tid;          // 0..1023
            int arr = ch >> 9, cc = ch & 511;
            int r = cc >> 3, c = cc & 7;
            uint32_t dst = smem_u32(sbase + arr * 8192 + r * 128 + ((c ^ (r & 7)) << 4));
            int tok = kb * 64 + r;
            const __half* p = arr ? Vf : Kf;
            const char* src = (const char*)(p + (size_t)(tok * 8 + b) * 1024 + colb + c * 8);
            CP_ASYNC16(dst, src, tok <= 1024 ? 16 : 0);
        }
    };
    load_kv(0, 0);
    CP_COMMIT();

    float o[8][4];
#pragma unroll
    for (int nt = 0; nt < 8; ++nt)
#pragma unroll
        for (int j = 0; j < 4; ++j) o[nt][j] = 0.f;
    float m0 = -1e30f, m1 = -1e30f, l0 = 0.f, l1 = 0.f;

    const int a_row_l = lane & 15;
    const int a_chk_l = lane >> 4;
    const int b_row_l = (lane & 7) + ((lane >> 4) << 3);
    const int b_chk_l = (lane >> 3) & 1;
    const uint32_t sQb = smem_u32(sm);

    for (int kb = 0; kb < 17; ++kb) {
        if (kb + 1 < 17) { load_kv(kb + 1, (kb + 1) & 1); CP_COMMIT(); CP_WAIT(1); }
        else CP_WAIT(0);
        __syncthreads();

        const uint32_t sKb = smem_u32(sm + 16384 + (kb & 1) * 16384);
        const uint32_t sVb = sKb + 8192;

        // ---- S = Q K^T (1-term fp16; q pre-scaled by 0.125) ----
        float s[8][4];
#pragma unroll
        for (int nt = 0; nt < 8; ++nt)
#pragma unroll
            for (int j = 0; j < 4; ++j) s[nt][j] = 0.f;

#pragma unroll
        for (int ks = 0; ks < 4; ++ks) {
            uint32_t qf[4];
            {
                int row = wid * 16 + a_row_l;
                int chk = ks * 2 + a_chk_l;
                ldsm4(qf, sQb + row * 128 + ((chk ^ (row & 7)) << 4));
            }
#pragma unroll
            for (int np = 0; np < 4; ++np) {
                uint32_t kf[4];
                int row = np * 16 + b_row_l;
                int chk = ks * 2 + b_chk_l;
                ldsm4(kf, sKb + row * 128 + ((chk ^ (row & 7)) << 4));
                mma_f16(s[np * 2],     qf, &kf[0]);
                mma_f16(s[np * 2 + 1], qf, &kf[2]);
            }
        }

        // ---- mask tail block ----
        if (kb == 16) {
#pragma unroll
            for (int nt = 0; nt < 8; ++nt)
#pragma unroll
                for (int j = 0; j < 4; ++j) {
                    int tok = kb * 64 + nt * 8 + (lane & 3) * 2 + (j & 1);
                    if (tok > 1024) s[nt][j] = -1e30f;
                }
        }

        // ---- online softmax ----
        float tm0 = -1e30f, tm1 = -1e30f;
#pragma unroll
        for (int nt = 0; nt < 8; ++nt) {
            tm0 = fmaxf(tm0, fmaxf(s[nt][0], s[nt][1]));
            tm1 = fmaxf(tm1, fmaxf(s[nt][2], s[nt][3]));
        }
        tm0 = fmaxf(tm0, __shfl_xor_sync(0xffffffffu, tm0, 1));
        tm0 = fmaxf(tm0, __shfl_xor_sync(0xffffffffu, tm0, 2));
        tm1 = fmaxf(tm1, __shfl_xor_sync(0xffffffffu, tm1, 1));
        tm1 = fmaxf(tm1, __shfl_xor_sync(0xffffffffu, tm1, 2));
        float mn0 = fmaxf(m0, tm0), mn1 = fmaxf(m1, tm1);
        float cr0 = __expf(m0 - mn0), cr1 = __expf(m1 - mn1);
        float rs0 = 0.f, rs1 = 0.f;
#pragma unroll
        for (int nt = 0; nt < 8; ++nt) {
            s[nt][0] = __expf(s[nt][0] - mn0);
            s[nt][1] = __expf(s[nt][1] - mn0);
            s[nt][2] = __expf(s[nt][2] - mn1);
            s[nt][3] = __expf(s[nt][3] - mn1);
            rs0 += s[nt][0] + s[nt][1];
            rs1 += s[nt][2] + s[nt][3];
        }
        rs0 += __shfl_xor_sync(0xffffffffu, rs0, 1);
        rs0 += __shfl_xor_sync(0xffffffffu, rs0, 2);
        rs1 += __shfl_xor_sync(0xffffffffu, rs1, 1);
        rs1 += __shfl_xor_sync(0xffffffffu, rs1, 2);
        l0 = l0 * cr0 + rs0; l1 = l1 * cr1 + rs1;
        m0 = mn0; m1 = mn1;
#pragma unroll
        for (int nt = 0; nt < 8; ++nt) {
            o[nt][0] *= cr0; o[nt][1] *= cr0;
            o[nt][2] *= cr1; o[nt][3] *= cr1;
        }

        // ---- pack P fragments as fp16 hi/lo (acc layout == A-frag layout) ----
        uint32_t ph[4][4], pl[4][4];
#pragma unroll
        for (int k2 = 0; k2 < 4; ++k2) {
            int t0 = 2 * k2, t1 = t0 + 1;
            split2h(s[t0][0], s[t0][1], ph[k2][0], pl[k2][0]);
            split2h(s[t0][2], s[t0][3], ph[k2][1], pl[k2][1]);
            split2h(s[t1][0], s[t1][1], ph[k2][2], pl[k2][2]);
            split2h(s[t1][2], s[t1][3], ph[k2][3], pl[k2][3]);
        }

        // ---- O += P V (2-term: Ph + Pl; V single fp16), V via ldmatrix.trans ----
#pragma unroll
        for (int k2 = 0; k2 < 4; ++k2) {
#pragma unroll
            for (int ntp = 0; ntp < 4; ++ntp) {
                uint32_t vf[4];
                int row = k2 * 16 + (lane & 15);
                int chk = ntp * 2 + (lane >> 4);
                ldsm4_t(vf, sVb + row * 128 + ((chk ^ (row & 7)) << 4));
                mma_f16(o[ntp * 2],     ph[k2], &vf[0]);
                mma_f16(o[ntp * 2 + 1], ph[k2], &vf[2]);
                mma_f16(o[ntp * 2],     pl[k2], &vf[0]);
                mma_f16(o[ntp * 2 + 1], pl[k2], &vf[2]);
            }
        }
        __syncthreads();
    }

    // ---- epilogue: normalize, split to bf16 hi/lo ctx ----
    float inv0 = 1.f / l0, inv1 = 1.f / l1;
    int tok0 = qt * 128 + wid * 16 + (lane >> 2);
    int tok1 = tok0 + 8;
    int dbase = (lane & 3) * 2;
#pragma unroll
    for (int nt = 0; nt < 8; ++nt) {
        int d = nt * 8 + dbase;
        if (tok0 <= 1024) {
            size_t idx = (size_t)(tok0 * 8 + b) * 1024 + colb + d;
            uint32_t hi, lo;
            split2(o[nt][0] * inv0, o[nt][1] * inv0, hi, lo);
            *(uint32_t*)(Ch + idx) = hi;
            *(uint32_t*)(Cl + idx) = lo;
        }
        if (tok1 <= 1024) {
            size_t idx = (size_t)(tok1 * 8 + b) * 1024 + colb + d;
            uint32_t hi, lo;
            split2(o[nt][2] * inv1, o[nt][3] * inv1, hi, lo);
            *(uint32_t*)(Ch + idx) = hi;
            *(uint32_t*)(Cl + idx) = lo;
        }
    }
}

// ---------------------------------------------------------------------------
// Launch
// ---------------------------------------------------------------------------
extern "C" void kernel_launch(void* const* d_in, const int* in_sizes, int n_in,
                              void* d_out, int out_size)
{
    const float* query = (const float*)d_in[0];
    const float* key   = (const float*)d_in[1];
    const float* value = (const float*)d_in[2];
    const float* W_in  = (const float*)d_in[3];
    const float* b_in  = (const float*)d_in[4];
    const float* W_out = (const float*)d_in[5];
    const float* b_out = (const float*)d_in[6];
    float* out = (float*)d_out;

    __nv_bfloat16 *qh, *ql, *kh, *kl, *vh, *vl, *wih, *wil, *woh, *wol, *ch, *cl;
    __half *aq, *ak, *av;
    cudaGetSymbolAddress((void**)&qh,  g_qh);  cudaGetSymbolAddress((void**)&ql,  g_ql);
    cudaGetSymbolAddress((void**)&kh,  g_kh);  cudaGetSymbolAddress((void**)&kl,  g_kl);
    cudaGetSymbolAddress((void**)&vh,  g_vh);  cudaGetSymbolAddress((void**)&vl,  g_vl);
    cudaGetSymbolAddress((void**)&wih, g_wih); cudaGetSymbolAddress((void**)&wil, g_wil);
    cudaGetSymbolAddress((void**)&woh, g_woh); cudaGetSymbolAddress((void**)&wol, g_wol);
    cudaGetSymbolAddress((void**)&aq,  g_aq);  cudaGetSymbolAddress((void**)&ak,  g_ak);
    cudaGetSymbolAddress((void**)&av,  g_av);
    cudaGetSymbolAddress((void**)&ch,  g_ch);  cudaGetSymbolAddress((void**)&cl,  g_cl);

    cudaFuncSetAttribute(tc_gemm_qkv, cudaFuncAttributeMaxDynamicSharedMemorySize, GK_SMEM);
    cudaFuncSetAttribute(tc_gemm_out, cudaFuncAttributeMaxDynamicSharedMemorySize, GK_SMEM);
    cudaFuncSetAttribute(attn_f16,    cudaFuncAttributeMaxDynamicSharedMemorySize, ATTN_SMEM);

    // fused raw-input splits
    split_all<<<(NSPLIT_TOT + 255) / 256, 256>>>(
        (const float4*)query, (const float4*)key, (const float4*)value,
        (const float4*)W_in, (const float4*)W_out,
        (uint2*)qh, (uint2*)ql, (uint2*)kh, (uint2*)kl, (uint2*)vh, (uint2*)vl,
        (uint2*)wih, (uint2*)wil, (uint2*)woh, (uint2*)wol);

    // QKV projections -> fp16 outputs (q pre-scaled by 0.125)
    tc_gemm_qkv<<<dim3(8, 64, 3), 256, GK_SMEM>>>(qh, ql, kh, kl, vh, vl, wih, wil, b_in,
                                                  aq, ak, av);

    fill_last_row_f16<<<32, 256>>>(query, aq, ak, av);

    // attention (fp16 mma.sync, QK 1-term / PV 2-term)
    attn_f16<<<dim3(9, B_SZ * H_CNT), 256, ATTN_SMEM>>>(aq, ak, av, ch, cl);

    // out projection (3-term split-bf16)
    tc_gemm_out<<<dim3(8, 65), 256, GK_SMEM>>>(ch, cl, woh, wol, b_out, out, NTOK);
}

// round 12
// speedup vs baseline: 4.8776x; 1.2433x over previous
#include <cuda_runtime.h>
#include <cuda_bf16.h>
#include <cuda_fp16.h>
#include <cstdint>

// Problem constants
#define S_LEN 1025
#define B_SZ  8
#define E_SZ  1024
#define H_CNT 16
#define HD    64
#define NTOK  (S_LEN * B_SZ)          // 8200
#define NTOK_PROJ (1024 * B_SZ)       // 8192
#define QSCALE 0.180336880f           // 0.125 * log2(e)

// ---------------- scratch (device globals: allocation-free) ----------------
__device__ __half g_qh[NTOK_PROJ * E_SZ], g_ql[NTOK_PROJ * E_SZ];
__device__ __half g_kh[NTOK_PROJ * E_SZ], g_kl[NTOK_PROJ * E_SZ];
__device__ __half g_vh[NTOK_PROJ * E_SZ], g_vl[NTOK_PROJ * E_SZ];
__device__ __half g_wi[3072 * 1024];
__device__ __half g_wo[1024 * 1024];
__device__ __half g_aq[NTOK * E_SZ];      // projected q (pre-scaled by 0.125*log2e)
__device__ __half g_ak[NTOK * E_SZ];
__device__ __half g_av[NTOK * E_SZ];
__device__ __half g_ch[NTOK * E_SZ], g_cl[NTOK * E_SZ];   // ctx split (fp16)

// ---------------- helpers (sm_80+ only; legal on bare compute_103) ---------
__device__ __forceinline__ uint32_t smem_u32(const void* p) {
    uint32_t a;
    asm("{ .reg .u64 t; cvta.to.shared.u64 t, %1; cvt.u32.u64 %0, t; }"
        : "=r"(a) : "l"(p));
    return a;
}
__device__ __forceinline__ void ldsm4(uint32_t* r, uint32_t addr) {
    asm volatile("ldmatrix.sync.aligned.m8n8.x4.shared.b16 {%0,%1,%2,%3}, [%4];"
                 : "=r"(r[0]), "=r"(r[1]), "=r"(r[2]), "=r"(r[3]) : "r"(addr));
}
__device__ __forceinline__ void ldsm4_t(uint32_t* r, uint32_t addr) {
    asm volatile("ldmatrix.sync.aligned.m8n8.x4.trans.shared.b16 {%0,%1,%2,%3}, [%4];"
                 : "=r"(r[0]), "=r"(r[1]), "=r"(r[2]), "=r"(r[3]) : "r"(addr));
}
__device__ __forceinline__ void mma_f16(float* d, const uint32_t* a, const uint32_t* b) {
    asm volatile(
        "mma.sync.aligned.m16n8k16.row.col.f32.f16.f16.f32 "
        "{%0,%1,%2,%3}, {%4,%5,%6,%7}, {%8,%9}, {%0,%1,%2,%3};"
        : "+f"(d[0]), "+f"(d[1]), "+f"(d[2]), "+f"(d[3])
        : "r"(a[0]), "r"(a[1]), "r"(a[2]), "r"(a[3]), "r"(b[0]), "r"(b[1]));
}
#define CP_ASYNC16(dst, src, sz) \
    asm volatile("cp.async.cg.shared.global [%0], [%1], 16, %2;" \
                 :: "r"(dst), "l"(src), "r"(sz))
#define CP_COMMIT() asm volatile("cp.async.commit_group;" ::: "memory")
#define CP_WAIT(n)  asm volatile("cp.async.wait_group %0;" :: "n"(n) : "memory")

__device__ __forceinline__ void split2h(float a, float b, uint32_t& hi, uint32_t& lo) {
    __half2 h = __floats2half2_rn(a, b);
    float ra = a - __half2float(__low2half(h));
    float rb = b - __half2float(__high2half(h));
    __half2 l = __floats2half2_rn(ra, rb);
    hi = *(uint32_t*)&h;
    lo = *(uint32_t*)&l;
}

// ---------------------------------------------------------------------------
// 2-MMA fp16 GEMM: C[M,1024] = (Ah+Al)[M,1024] @ W[N,1024]^T + bias
// A split into fp16 hi/lo; W single fp16. D += Ah*W + Al*W.
// 128x128 CTA tile, BK=64, 8 warps (2x4), 3-stage cp.async pipeline.
// ---------------------------------------------------------------------------
#define OP_BYTES    (128 * 128)           // 16 KB per operand tile
#define STAGE_BYTES (3 * OP_BYTES)        // 48 KB (Ah | Al | W)
#define GK_SMEM     (3 * STAGE_BYTES)     // 144 KB

__device__ __forceinline__ void load_stage(
    char* stage,
    const __half* __restrict__ Ah, const __half* __restrict__ Al,
    const __half* __restrict__ W,
    int m0, int n0, int k0, int M, int tid)
{
#pragma unroll
    for (int o = 0; o < 3; ++o) {
        const __half* src_base = (o == 0) ? Ah : (o == 1) ? Al : W;
        const int row0 = (o < 2) ? m0 : n0;
        char* dstop = stage + o * OP_BYTES;
#pragma unroll
        for (int i = 0; i < 4; ++i) {
            int ch = i * 256 + tid;          // 0..1023 16B chunks
            int r = ch >> 3, c = ch & 7;
            uint32_t dst = smem_u32(dstop + r * 128 + ((c ^ (r & 7)) << 4));
            const char* src = (const char*)(src_base + (size_t)(row0 + r) * 1024 + k0 + c * 8);
            int sz = (o >= 2 || (row0 + r) < M) ? 16 : 0;
            CP_ASYNC16(dst, src, sz);
        }
    }
}

template<int OUT_MODE>   // 0: fp32 C; 2: fp16 H scaled by oscale
__device__ __forceinline__ void tc_gemm_body(
    const __half* __restrict__ Ah, const __half* __restrict__ Al,
    const __half* __restrict__ W,
    const float* __restrict__ bias, float* __restrict__ C,
    __half* __restrict__ H, float oscale, int M,
    char* sm, int n0, int m0)
{
    const int tid = threadIdx.x;
    const int wid = tid >> 5, lane = tid & 31;
    const int wm = wid >> 2, wn = wid & 3;

    float acc[4][4][4];
#pragma unroll
    for (int a = 0; a < 4; ++a)
#pragma unroll
        for (int b = 0; b < 4; ++b)
#pragma unroll
            for (int c = 0; c < 4; ++c) acc[a][b][c] = 0.f;

    const int a_row_l = lane & 15;
    const int a_chk_l = lane >> 4;
    const int b_row_l = (lane & 7) + ((lane >> 4) << 3);
    const int b_chk_l = (lane >> 3) & 1;

    load_stage(sm,               Ah, Al, W, m0, n0, 0,  M, tid); CP_COMMIT();
    load_stage(sm + STAGE_BYTES, Ah, Al, W, m0, n0, 64, M, tid); CP_COMMIT();

    int cur = 0, pre = 2;
    for (int t = 0; t < 16; ++t) {
        CP_WAIT(1);
        __syncthreads();
        if (t + 2 < 16)
            load_stage(sm + pre * STAGE_BYTES, Ah, Al, W, m0, n0, (t + 2) * 64, M, tid);
        CP_COMMIT();

        char* st = sm + cur * STAGE_BYTES;
        const uint32_t sAh = smem_u32(st);
        const uint32_t sAl = sAh + OP_BYTES;
        const uint32_t sW  = sAh + 2 * OP_BYTES;

#pragma unroll
        for (int ks = 0; ks < 4; ++ks) {
            uint32_t ah[4][4], al[4][4], w[2][4];
            const int achk = ks * 2 + a_chk_l;
#pragma unroll
            for (int mt = 0; mt < 4; ++mt) {
                int row = wm * 64 + mt * 16 + a_row_l;
                uint32_t off = row * 128 + ((achk ^ (row & 7)) << 4);
                ldsm4(ah[mt], sAh + off);
                ldsm4(al[mt], sAl + off);
            }
            const int bchk = ks * 2 + b_chk_l;
#pragma unroll
            for (int np = 0; np < 2; ++np) {
                int row = wn * 32 + np * 16 + b_row_l;
                uint32_t off = row * 128 + ((bchk ^ (row & 7)) << 4);
                ldsm4(w[np], sW + off);
            }
#pragma unroll
            for (int mt = 0; mt < 4; ++mt)
#pragma unroll
                for (int np = 0; np < 2; ++np) {
                    mma_f16(acc[mt][np * 2],     ah[mt], &w[np][0]);
                    mma_f16(acc[mt][np * 2 + 1], ah[mt], &w[np][2]);
                    mma_f16(acc[mt][np * 2],     al[mt], &w[np][0]);
                    mma_f16(acc[mt][np * 2 + 1], al[mt], &w[np][2]);
                }
        }
        cur = (cur == 2) ? 0 : cur + 1;
        pre = (pre == 2) ? 0 : pre + 1;
    }

#pragma unroll
    for (int mt = 0; mt < 4; ++mt) {
        int mA = m0 + wm * 64 + mt * 16 + (lane >> 2);
        int mB = mA + 8;
#pragma unroll
        for (int nt = 0; nt < 4; ++nt) {
            int n = n0 + wn * 32 + nt * 8 + (lane & 3) * 2;
            float2 bv = *(const float2*)&bias[n];
            float v0 = acc[mt][nt][0] + bv.x, v1 = acc[mt][nt][1] + bv.y;
            float v2 = acc[mt][nt][2] + bv.x, v3 = acc[mt][nt][3] + bv.y;
            if (OUT_MODE == 2) {
                if (mA < M) {
                    __half2 hv = __floats2half2_rn(v0 * oscale, v1 * oscale);
                    *(uint32_t*)(H + (size_t)mA * 1024 + n) = *(uint32_t*)&hv;
                }
                if (mB < M) {
                    __half2 hv = __floats2half2_rn(v2 * oscale, v3 * oscale);
                    *(uint32_t*)(H + (size_t)mB * 1024 + n) = *(uint32_t*)&hv;
                }
            } else {
                if (mA < M) *(float2*)&C[(size_t)mA * 1024 + n] = make_float2(v0, v1);
                if (mB < M) *(float2*)&C[(size_t)mB * 1024 + n] = make_float2(v2, v3);
            }
        }
    }
}

__global__ __launch_bounds__(256)
void tc_gemm_out(const __half* __restrict__ Ah, const __half* __restrict__ Al,
                 const __half* __restrict__ W,
                 const float* __restrict__ bias, float* __restrict__ C, int M)
{
    extern __shared__ char sm[];
    tc_gemm_body<0>(Ah, Al, W, bias, C, nullptr, 1.f, M, sm,
                    blockIdx.x * 128, blockIdx.y * 128);
}

__global__ __launch_bounds__(256)
void tc_gemm_qkv(const __half* __restrict__ qh, const __half* __restrict__ ql,
                 const __half* __restrict__ kh, const __half* __restrict__ kl,
                 const __half* __restrict__ vh, const __half* __restrict__ vl,
                 const __half* __restrict__ W, const float* __restrict__ bias,
                 __half* __restrict__ oq, __half* __restrict__ ok, __half* __restrict__ ov)
{
    extern __shared__ char sm[];
    const int z = blockIdx.z;
    const __half* Ah = (z == 0) ? qh : (z == 1) ? kh : vh;
    const __half* Al = (z == 0) ? ql : (z == 1) ? kl : vl;
    __half* H = (z == 0) ? oq : (z == 1) ? ok : ov;
    float oscale = (z == 0) ? QSCALE : 1.f;   // fold 0.125*log2e into q
    tc_gemm_body<2>(Ah, Al, W + (size_t)z * 1024 * 1024,
                    bias + z * 1024, nullptr, H, oscale, NTOK_PROJ, sm,
                    blockIdx.x * 128, blockIdx.y * 128);
}

// ---------------------------------------------------------------------------
// Fused input conversion: q/k/v -> fp16 hi/lo split; W_in, W_out -> fp16
// ---------------------------------------------------------------------------
#define NQ4  (NTOK_PROJ * E_SZ / 4)
#define NWI4 (3072 * 1024 / 4)
#define NWO4 (1024 * 1024 / 4)
#define NSPLIT_TOT (3 * NQ4 + NWI4 + NWO4)

__global__ __launch_bounds__(256) void split_all(
    const float4* __restrict__ q, const float4* __restrict__ k, const float4* __restrict__ v,
    const float4* __restrict__ wi, const float4* __restrict__ wo,
    uint2* __restrict__ qh, uint2* __restrict__ ql,
    uint2* __restrict__ kh, uint2* __restrict__ kl,
    uint2* __restrict__ vh, uint2* __restrict__ vl,
    uint2* __restrict__ wih, uint2* __restrict__ woh)
{
    int i = blockIdx.x * 256 + threadIdx.x;
    if (i >= NSPLIT_TOT) return;
    if (i >= 3 * NQ4) {               // weights: single fp16
        const float4* src; uint2* dst; int off;
        if (i < 3 * NQ4 + NWI4) { src = wi; dst = wih; off = i - 3 * NQ4; }
        else                    { src = wo; dst = woh; off = i - 3 * NQ4 - NWI4; }
        float4 val = src[off];
        __half2 h01 = __floats2half2_rn(val.x, val.y);
        __half2 h23 = __floats2half2_rn(val.z, val.w);
        dst[off] = make_uint2(*(uint32_t*)&h01, *(uint32_t*)&h23);
        return;
    }
    const float4* src; uint2 *dh, *dl; int off;
    if (i < NQ4)          { src = q; dh = qh; dl = ql; off = i; }
    else if (i < 2 * NQ4) { src = k; dh = kh; dl = kl; off = i - NQ4; }
    else                  { src = v; dh = vh; dl = vl; off = i - 2 * NQ4; }
    float4 val = src[off];
    uint32_t h0, l0, h1, l1;
    split2h(val.x, val.y, h0, l0);
    split2h(val.z, val.w, h1, l1);
    dh[off] = make_uint2(h0, h1);
    dl[off] = make_uint2(l0, l1);
}

// dummy row s=1024: q (scaled) / k / v = raw query[-1], fp16
__global__ void fill_last_row_f16(const float* __restrict__ query,
                                  __half* __restrict__ aq, __half* __restrict__ ak,
                                  __half* __restrict__ av)
{
    int idx = blockIdx.x * 256 + threadIdx.x;
    if (idx < B_SZ * E_SZ) {
        size_t off = (size_t)1024 * 8192 + idx;
        float v = query[off];
        aq[off] = __float2half_rn(v * QSCALE);
        ak[off] = __float2half_rn(v);
        av[off] = __float2half_rn(v);
    }
}

// ---------------------------------------------------------------------------
// Flash attention, fp16 mma.sync: QK 1-term (q pre-scaled incl log2e),
// PV 2-term (split P). Softmax in exp2 domain. ctx emitted as fp16 hi/lo.
// ---------------------------------------------------------------------------
#define ATTN_SMEM (16384 + 2 * 16384)

__global__ __launch_bounds__(256) void attn_f16(
    const __half* __restrict__ Qf, const __half* __restrict__ Kf,
    const __half* __restrict__ Vf,
    __half* __restrict__ Ch, __half* __restrict__ Cl)
{
    extern __shared__ char sm[];
    const int tid = threadIdx.x, wid = tid >> 5, lane = tid & 31;
    const int qt = blockIdx.x;
    const int b = blockIdx.y >> 4, h = blockIdx.y & 15;
    const size_t colb = (size_t)h * 64;

#pragma unroll
    for (int i = 0; i < 4; ++i) {
        int ch = i * 256 + tid;
        int r = ch >> 3, c = ch & 7;
        uint32_t dst = smem_u32(sm + r * 128 + ((c ^ (r & 7)) << 4));
        int tok = qt * 128 + r;
        const char* src = (const char*)(Qf + (size_t)(tok * 8 + b) * 1024 + colb + c * 8);
        CP_ASYNC16(dst, src, tok <= 1024 ? 16 : 0);
    }

    auto load_kv = [&](int kb, int st) {
        char* sbase = sm + 16384 + st * 16384;
#pragma unroll
        for (int i = 0; i < 4; ++i) {
            int ch = i * 256 + tid;
            int arr = ch >> 9, cc = ch & 511;
            int r = cc >> 3, c = cc & 7;
            uint32_t dst = smem_u32(sbase + arr * 8192 + r * 128 + ((c ^ (r & 7)) << 4));
            int tok = kb * 64 + r;
            const __half* p = arr ? Vf : Kf;
            const char* src = (const char*)(p + (size_t)(tok * 8 + b) * 1024 + colb + c * 8);
            CP_ASYNC16(dst, src, tok <= 1024 ? 16 : 0);
        }
    };
    load_kv(0, 0);
    CP_COMMIT();

    float o[8][4];
#pragma unroll
    for (int nt = 0; nt < 8; ++nt)
#pragma unroll
        for (int j = 0; j < 4; ++j) o[nt][j] = 0.f;
    float m0 = -1e30f, m1 = -1e30f, l0 = 0.f, l1 = 0.f;

    const int a_row_l = lane & 15;
    const int a_chk_l = lane >> 4;
    const int b_row_l = (lane & 7) + ((lane >> 4) << 3);
    const int b_chk_l = (lane >> 3) & 1;
    const uint32_t sQb = smem_u32(sm);

    for (int kb = 0; kb < 17; ++kb) {
        if (kb + 1 < 17) { load_kv(kb + 1, (kb + 1) & 1); CP_COMMIT(); CP_WAIT(1); }
        else CP_WAIT(0);
        __syncthreads();

        const uint32_t sKb = smem_u32(sm + 16384 + (kb & 1) * 16384);
        const uint32_t sVb = sKb + 8192;

        float s[8][4];
#pragma unroll
        for (int nt = 0; nt < 8; ++nt)
#pragma unroll
            for (int j = 0; j < 4; ++j) s[nt][j] = 0.f;

#pragma unroll
        for (int ks = 0; ks < 4; ++ks) {
            uint32_t qf[4];
            {
                int row = wid * 16 + a_row_l;
                int chk = ks * 2 + a_chk_l;
                ldsm4(qf, sQb + row * 128 + ((chk ^ (row & 7)) << 4));
            }
#pragma unroll
            for (int np = 0; np < 4; ++np) {
                uint32_t kf[4];
                int row = np * 16 + b_row_l;
                int chk = ks * 2 + b_chk_l;
                ldsm4(kf, sKb + row * 128 + ((chk ^ (row & 7)) << 4));
                mma_f16(s[np * 2],     qf, &kf[0]);
                mma_f16(s[np * 2 + 1], qf, &kf[2]);
            }
        }

        if (kb == 16) {
#pragma unroll
            for (int nt = 0; nt < 8; ++nt)
#pragma unroll
                for (int j = 0; j < 4; ++j) {
                    int tok = kb * 64 + nt * 8 + (lane & 3) * 2 + (j & 1);
                    if (tok > 1024) s[nt][j] = -1e30f;
                }
        }

        // ---- online softmax (exp2 domain; logits already include log2e) ----
        float tm0 = -1e30f, tm1 = -1e30f;
#pragma unroll
        for (int nt = 0; nt < 8; ++nt) {
            tm0 = fmaxf(tm0, fmaxf(s[nt][0], s[nt][1]));
            tm1 = fmaxf(tm1, fmaxf(s[nt][2], s[nt][3]));
        }
        tm0 = fmaxf(tm0, __shfl_xor_sync(0xffffffffu, tm0, 1));
        tm0 = fmaxf(tm0, __shfl_xor_sync(0xffffffffu, tm0, 2));
        tm1 = fmaxf(tm1, __shfl_xor_sync(0xffffffffu, tm1, 1));
        tm1 = fmaxf(tm1, __shfl_xor_sync(0xffffffffu, tm1, 2));
        float mn0 = fmaxf(m0, tm0), mn1 = fmaxf(m1, tm1);
        float cr0 = exp2f(m0 - mn0), cr1 = exp2f(m1 - mn1);
        float rs0 = 0.f, rs1 = 0.f;
#pragma unroll
        for (int nt = 0; nt < 8; ++nt) {
            s[nt][0] = exp2f(s[nt][0] - mn0);
            s[nt][1] = exp2f(s[nt][1] - mn0);
            s[nt][2] = exp2f(s[nt][2] - mn1);
            s[nt][3] = exp2f(s[nt][3] - mn1);
            rs0 += s[nt][0] + s[nt][1];
            rs1 += s[nt][2] + s[nt][3];
        }
        rs0 += __shfl_xor_sync(0xffffffffu, rs0, 1);
        rs0 += __shfl_xor_sync(0xffffffffu, rs0, 2);
        rs1 += __shfl_xor_sync(0xffffffffu, rs1, 1);
        rs1 += __shfl_xor_sync(0xffffffffu, rs1, 2);
        l0 = l0 * cr0 + rs0; l1 = l1 * cr1 + rs1;
        m0 = mn0; m1 = mn1;
#pragma unroll
        for (int nt = 0; nt < 8; ++nt) {
            o[nt][0] *= cr0; o[nt][1] *= cr0;
            o[nt][2] *= cr1; o[nt][3] *= cr1;
        }

        uint32_t ph[4][4], pl[4][4];
#pragma unroll
        for (int k2 = 0; k2 < 4; ++k2) {
            int t0 = 2 * k2, t1 = t0 + 1;
            split2h(s[t0][0], s[t0][1], ph[k2][0], pl[k2][0]);
            split2h(s[t0][2], s[t0][3], ph[k2][1], pl[k2][1]);
            split2h(s[t1][0], s[t1][1], ph[k2][2], pl[k2][2]);
            split2h(s[t1][2], s[t1][3], ph[k2][3], pl[k2][3]);
        }

#pragma unroll
        for (int k2 = 0; k2 < 4; ++k2) {
#pragma unroll
            for (int ntp = 0; ntp < 4; ++ntp) {
                uint32_t vf[4];
                int row = k2 * 16 + (lane & 15);
                int chk = ntp * 2 + (lane >> 4);
                ldsm4_t(vf, sVb + row * 128 + ((chk ^ (row & 7)) << 4));
                mma_f16(o[ntp * 2],     ph[k2], &vf[0]);
                mma_f16(o[ntp * 2 + 1], ph[k2], &vf[2]);
                mma_f16(o[ntp * 2],     pl[k2], &vf[0]);
                mma_f16(o[ntp * 2 + 1], pl[k2], &vf[2]);
            }
        }
        __syncthreads();
    }

    // ---- epilogue: normalize, split to fp16 hi/lo ctx ----
    float inv0 = 1.f / l0, inv1 = 1.f / l1;
    int tok0 = qt * 128 + wid * 16 + (lane >> 2);
    int tok1 = tok0 + 8;
    int dbase = (lane & 3) * 2;
#pragma unroll
    for (int nt = 0; nt < 8; ++nt) {
        int d = nt * 8 + dbase;
        if (tok0 <= 1024) {
            size_t idx = (size_t)(tok0 * 8 + b) * 1024 + colb + d;
            uint32_t hi, lo;
            split2h(o[nt][0] * inv0, o[nt][1] * inv0, hi, lo);
            *(uint32_t*)(Ch + idx) = hi;
            *(uint32_t*)(Cl + idx) = lo;
        }
        if (tok1 <= 1024) {
            size_t idx = (size_t)(tok1 * 8 + b) * 1024 + colb + d;
            uint32_t hi, lo;
            split2h(o[nt][2] * inv1, o[nt][3] * inv1, hi, lo);
            *(uint32_t*)(Ch + idx) = hi;
            *(uint32_t*)(Cl + idx) = lo;
        }
    }
}

// ---------------------------------------------------------------------------
// Launch
// ---------------------------------------------------------------------------
extern "C" void kernel_launch(void* const* d_in, const int* in_sizes, int n_in,
                              void* d_out, int out_size)
{
    const float* query = (const float*)d_in[0];
    const float* key   = (const float*)d_in[1];
    const float* value = (const float*)d_in[2];
    const float* W_in  = (const float*)d_in[3];
    const float* b_in  = (const float*)d_in[4];
    const float* W_out = (const float*)d_in[5];
    const float* b_out = (const float*)d_in[6];
    float* out = (float*)d_out;

    __half *qh, *ql, *kh, *kl, *vh, *vl, *wi, *wo, *aq, *ak, *av, *ch, *cl;
    cudaGetSymbolAddress((void**)&qh, g_qh); cudaGetSymbolAddress((void**)&ql, g_ql);
    cudaGetSymbolAddress((void**)&kh, g_kh); cudaGetSymbolAddress((void**)&kl, g_kl);
    cudaGetSymbolAddress((void**)&vh, g_vh); cudaGetSymbolAddress((void**)&vl, g_vl);
    cudaGetSymbolAddress((void**)&wi, g_wi); cudaGetSymbolAddress((void**)&wo, g_wo);
    cudaGetSymbolAddress((void**)&aq, g_aq); cudaGetSymbolAddress((void**)&ak, g_ak);
    cudaGetSymbolAddress((void**)&av, g_av);
    cudaGetSymbolAddress((void**)&ch, g_ch); cudaGetSymbolAddress((void**)&cl, g_cl);

    cudaFuncSetAttribute(tc_gemm_qkv, cudaFuncAttributeMaxDynamicSharedMemorySize, GK_SMEM);
    cudaFuncSetAttribute(tc_gemm_out, cudaFuncAttributeMaxDynamicSharedMemorySize, GK_SMEM);
    cudaFuncSetAttribute(attn_f16,    cudaFuncAttributeMaxDynamicSharedMemorySize, ATTN_SMEM);

    // fused input conversion
    split_all<<<(NSPLIT_TOT + 255) / 256, 256>>>(
        (const float4*)query, (const float4*)key, (const float4*)value,
        (const float4*)W_in, (const float4*)W_out,
        (uint2*)qh, (uint2*)ql, (uint2*)kh, (uint2*)kl, (uint2*)vh, (uint2*)vl,
        (uint2*)wi, (uint2*)wo);

    // QKV projections (2-MMA fp16) -> fp16 outputs (q pre-scaled)
    tc_gemm_qkv<<<dim3(8, 64, 3), 256, GK_SMEM>>>(qh, ql, kh, kl, vh, vl, wi, b_in,
                                                  aq, ak, av);

    fill_last_row_f16<<<32, 256>>>(query, aq, ak, av);

    // attention (fp16 mma.sync, exp2 softmax)
    attn_f16<<<dim3(9, B_SZ * H_CNT), 256, ATTN_SMEM>>>(aq, ak, av, ch, cl);

    // out projection (2-MMA fp16)
    tc_gemm_out<<<dim3(8, 65), 256, GK_SMEM>>>(ch, cl, wo, b_out, out, NTOK);
}

// round 13
// speedup vs baseline: 5.9494x; 1.2198x over previous
#include <cuda_runtime.h>
#include <cuda_bf16.h>
#include <cuda_fp16.h>
#include <cstdint>

// Problem constants
#define S_LEN 1025
#define B_SZ  8
#define E_SZ  1024
#define H_CNT 16
#define HD    64
#define NTOK  (S_LEN * B_SZ)          // 8200
#define NTOK_PROJ (1024 * B_SZ)       // 8192
#define QSCALE 0.180336880f           // 0.125 * log2(e)

// ---------------- scratch (device globals: allocation-free) ----------------
__device__ __half g_qraw[NTOK_PROJ * E_SZ];                    // raw q, fp16
__device__ __half g_kraw[NTOK_PROJ * E_SZ];                    // raw k, fp16
__device__ __half g_vh[NTOK_PROJ * E_SZ], g_vl[NTOK_PROJ * E_SZ];  // raw v hi/lo
__device__ __half g_wi[3072 * 1024];
__device__ __half g_wo[1024 * 1024];
__device__ __half g_aq[NTOK * E_SZ];      // projected q (pre-scaled by 0.125*log2e)
__device__ __half g_ak[NTOK * E_SZ];
__device__ __half g_av[NTOK * E_SZ];
__device__ __half g_ch[NTOK * E_SZ], g_cl[NTOK * E_SZ];   // ctx split (fp16)

// ---------------- helpers (sm_80+ only; legal on bare compute_103) ---------
__device__ __forceinline__ uint32_t smem_u32(const void* p) {
    uint32_t a;
    asm("{ .reg .u64 t; cvta.to.shared.u64 t, %1; cvt.u32.u64 %0, t; }"
        : "=r"(a) : "l"(p));
    return a;
}
__device__ __forceinline__ void ldsm4(uint32_t* r, uint32_t addr) {
    asm volatile("ldmatrix.sync.aligned.m8n8.x4.shared.b16 {%0,%1,%2,%3}, [%4];"
                 : "=r"(r[0]), "=r"(r[1]), "=r"(r[2]), "=r"(r[3]) : "r"(addr));
}
__device__ __forceinline__ void ldsm4_t(uint32_t* r, uint32_t addr) {
    asm volatile("ldmatrix.sync.aligned.m8n8.x4.trans.shared.b16 {%0,%1,%2,%3}, [%4];"
                 : "=r"(r[0]), "=r"(r[1]), "=r"(r[2]), "=r"(r[3]) : "r"(addr));
}
__device__ __forceinline__ void mma_f16(float* d, const uint32_t* a, const uint32_t* b) {
    asm volatile(
        "mma.sync.aligned.m16n8k16.row.col.f32.f16.f16.f32 "
        "{%0,%1,%2,%3}, {%4,%5,%6,%7}, {%8,%9}, {%0,%1,%2,%3};"
        : "+f"(d[0]), "+f"(d[1]), "+f"(d[2]), "+f"(d[3])
        : "r"(a[0]), "r"(a[1]), "r"(a[2]), "r"(a[3]), "r"(b[0]), "r"(b[1]));
}
#define CP_ASYNC16(dst, src, sz) \
    asm volatile("cp.async.cg.shared.global [%0], [%1], 16, %2;" \
                 :: "r"(dst), "l"(src), "r"(sz))
#define CP_COMMIT() asm volatile("cp.async.commit_group;" ::: "memory")
#define CP_WAIT(n)  asm volatile("cp.async.wait_group %0;" :: "n"(n) : "memory")

__device__ __forceinline__ void split2h(float a, float b, uint32_t& hi, uint32_t& lo) {
    __half2 h = __floats2half2_rn(a, b);
    float ra = a - __half2float(__low2half(h));
    float rb = b - __half2float(__high2half(h));
    __half2 l = __floats2half2_rn(ra, rb);
    hi = *(uint32_t*)&h;
    lo = *(uint32_t*)&l;
}
__device__ __forceinline__ uint32_t pack2h(float a, float b) {
    __half2 h = __floats2half2_rn(a, b);
    return *(uint32_t*)&h;
}

// ---------------------------------------------------------------------------
// fp16 GEMM, NTERMS = 1 (A single) or 2 (A hi+lo). W single fp16.
// 128x128 CTA tile, BK=64, 8 warps (2x4), 3-stage cp.async pipeline.
// Stage layout (fixed): [Ah | Al | W], 16KB each (Al slot unused if NTERMS=1).
// ---------------------------------------------------------------------------
#define OP_BYTES    (128 * 128)
#define STAGE_BYTES (3 * OP_BYTES)        // 48 KB
#define GK_SMEM     (3 * STAGE_BYTES)     // 144 KB

template<int NTERMS>
__device__ __forceinline__ void load_stage(
    char* stage,
    const __half* __restrict__ Ah, const __half* __restrict__ Al,
    const __half* __restrict__ W,
    int m0, int n0, int k0, int M, int tid)
{
#pragma unroll
    for (int o = 0; o < 3; ++o) {
        if (NTERMS == 1 && o == 1) continue;
        const __half* src_base = (o == 0) ? Ah : (o == 1) ? Al : W;
        const int row0 = (o < 2) ? m0 : n0;
        char* dstop = stage + o * OP_BYTES;
#pragma unroll
        for (int i = 0; i < 4; ++i) {
            int ch = i * 256 + tid;
            int r = ch >> 3, c = ch & 7;
            uint32_t dst = smem_u32(dstop + r * 128 + ((c ^ (r & 7)) << 4));
            const char* src = (const char*)(src_base + (size_t)(row0 + r) * 1024 + k0 + c * 8);
            int sz = (o >= 2 || (row0 + r) < M) ? 16 : 0;
            CP_ASYNC16(dst, src, sz);
        }
    }
}

template<int NTERMS, int OUT_MODE>   // OUT_MODE 0: fp32 C; 2: fp16 H * oscale
__device__ __forceinline__ void tc_gemm_body(
    const __half* __restrict__ Ah, const __half* __restrict__ Al,
    const __half* __restrict__ W,
    const float* __restrict__ bias, float* __restrict__ C,
    __half* __restrict__ H, float oscale, int M,
    char* sm, int n0, int m0)
{
    const int tid = threadIdx.x;
    const int wid = tid >> 5, lane = tid & 31;
    const int wm = wid >> 2, wn = wid & 3;

    float acc[4][4][4];
#pragma unroll
    for (int a = 0; a < 4; ++a)
#pragma unroll
        for (int b = 0; b < 4; ++b)
#pragma unroll
            for (int c = 0; c < 4; ++c) acc[a][b][c] = 0.f;

    const int a_row_l = lane & 15;
    const int a_chk_l = lane >> 4;
    const int b_row_l = (lane & 7) + ((lane >> 4) << 3);
    const int b_chk_l = (lane >> 3) & 1;

    load_stage<NTERMS>(sm,               Ah, Al, W, m0, n0, 0,  M, tid); CP_COMMIT();
    load_stage<NTERMS>(sm + STAGE_BYTES, Ah, Al, W, m0, n0, 64, M, tid); CP_COMMIT();

    int cur = 0, pre = 2;
    for (int t = 0; t < 16; ++t) {
        CP_WAIT(1);
        __syncthreads();
        if (t + 2 < 16)
            load_stage<NTERMS>(sm + pre * STAGE_BYTES, Ah, Al, W, m0, n0, (t + 2) * 64, M, tid);
        CP_COMMIT();

        char* st = sm + cur * STAGE_BYTES;
        const uint32_t sAh = smem_u32(st);
        const uint32_t sAl = sAh + OP_BYTES;
        const uint32_t sW  = sAh + 2 * OP_BYTES;

#pragma unroll
        for (int ks = 0; ks < 4; ++ks) {
            uint32_t ah[4][4], al[4][4], w[2][4];
            const int achk = ks * 2 + a_chk_l;
#pragma unroll
            for (int mt = 0; mt < 4; ++mt) {
                int row = wm * 64 + mt * 16 + a_row_l;
                uint32_t off = row * 128 + ((achk ^ (row & 7)) << 4);
                ldsm4(ah[mt], sAh + off);
                if (NTERMS == 2) ldsm4(al[mt], sAl + off);
            }
            const int bchk = ks * 2 + b_chk_l;
#pragma unroll
            for (int np = 0; np < 2; ++np) {
                int row = wn * 32 + np * 16 + b_row_l;
                uint32_t off = row * 128 + ((bchk ^ (row & 7)) << 4);
                ldsm4(w[np], sW + off);
            }
#pragma unroll
            for (int mt = 0; mt < 4; ++mt)
#pragma unroll
                for (int np = 0; np < 2; ++np) {
                    mma_f16(acc[mt][np * 2],     ah[mt], &w[np][0]);
                    mma_f16(acc[mt][np * 2 + 1], ah[mt], &w[np][2]);
                    if (NTERMS == 2) {
                        mma_f16(acc[mt][np * 2],     al[mt], &w[np][0]);
                        mma_f16(acc[mt][np * 2 + 1], al[mt], &w[np][2]);
                    }
                }
        }
        cur = (cur == 2) ? 0 : cur + 1;
        pre = (pre == 2) ? 0 : pre + 1;
    }

#pragma unroll
    for (int mt = 0; mt < 4; ++mt) {
        int mA = m0 + wm * 64 + mt * 16 + (lane >> 2);
        int mB = mA + 8;
#pragma unroll
        for (int nt = 0; nt < 4; ++nt) {
            int n = n0 + wn * 32 + nt * 8 + (lane & 3) * 2;
            float2 bv = *(const float2*)&bias[n];
            float v0 = acc[mt][nt][0] + bv.x, v1 = acc[mt][nt][1] + bv.y;
            float v2 = acc[mt][nt][2] + bv.x, v3 = acc[mt][nt][3] + bv.y;
            if (OUT_MODE == 2) {
                if (mA < M) {
                    __half2 hv = __floats2half2_rn(v0 * oscale, v1 * oscale);
                    *(uint32_t*)(H + (size_t)mA * 1024 + n) = *(uint32_t*)&hv;
                }
                if (mB < M) {
                    __half2 hv = __floats2half2_rn(v2 * oscale, v3 * oscale);
                    *(uint32_t*)(H + (size_t)mB * 1024 + n) = *(uint32_t*)&hv;
                }
            } else {
                if (mA < M) *(float2*)&C[(size_t)mA * 1024 + n] = make_float2(v0, v1);
                if (mB < M) *(float2*)&C[(size_t)mB * 1024 + n] = make_float2(v2, v3);
            }
        }
    }
}

// q,k projections: 1-term fp16 A
__global__ __launch_bounds__(256)
void tc_gemm_qk(const __half* __restrict__ qraw, const __half* __restrict__ kraw,
                const __half* __restrict__ W, const float* __restrict__ bias,
                __half* __restrict__ oq, __half* __restrict__ ok)
{
    extern __shared__ char sm[];
    const int z = blockIdx.z;       // 0=q, 1=k
    tc_gemm_body<1, 2>((z == 0) ? qraw : kraw, nullptr,
                       W + (size_t)z * 1024 * 1024, bias + z * 1024,
                       nullptr, (z == 0) ? oq : ok, (z == 0) ? QSCALE : 1.f,
                       NTOK_PROJ, sm, blockIdx.x * 128, blockIdx.y * 128);
}

// v projection: 2-term (error propagates directly)
__global__ __launch_bounds__(256)
void tc_gemm_v(const __half* __restrict__ vh, const __half* __restrict__ vl,
               const __half* __restrict__ W, const float* __restrict__ bias,
               __half* __restrict__ ov)
{
    extern __shared__ char sm[];
    tc_gemm_body<2, 2>(vh, vl, W + (size_t)2 * 1024 * 1024, bias + 2048,
                       nullptr, ov, 1.f, NTOK_PROJ, sm,
                       blockIdx.x * 128, blockIdx.y * 128);
}

// out projection: 2-term
__global__ __launch_bounds__(256)
void tc_gemm_out(const __half* __restrict__ Ah, const __half* __restrict__ Al,
                 const __half* __restrict__ W,
                 const float* __restrict__ bias, float* __restrict__ C, int M)
{
    extern __shared__ char sm[];
    tc_gemm_body<2, 0>(Ah, Al, W, bias, C, nullptr, 1.f, M, sm,
                       blockIdx.x * 128, blockIdx.y * 128);
}

// ---------------------------------------------------------------------------
// Fused input conversion: q,k,W_in,W_out -> single fp16; v -> fp16 hi/lo
// ---------------------------------------------------------------------------
#define NQ4  (NTOK_PROJ * E_SZ / 4)
#define NWI4 (3072 * 1024 / 4)
#define NWO4 (1024 * 1024 / 4)
#define NSPLIT_TOT (3 * NQ4 + NWI4 + NWO4)

__global__ __launch_bounds__(256) void split_all(
    const float4* __restrict__ q, const float4* __restrict__ k, const float4* __restrict__ v,
    const float4* __restrict__ wi, const float4* __restrict__ wo,
    uint2* __restrict__ qo, uint2* __restrict__ ko,
    uint2* __restrict__ vh, uint2* __restrict__ vl,
    uint2* __restrict__ wih, uint2* __restrict__ woh)
{
    int i = blockIdx.x * 256 + threadIdx.x;
    if (i >= NSPLIT_TOT) return;
    if (i >= 2 * NQ4 && i < 3 * NQ4) {     // v: hi/lo split
        int off = i - 2 * NQ4;
        float4 val = v[off];
        uint32_t h0, l0, h1, l1;
        split2h(val.x, val.y, h0, l0);
        split2h(val.z, val.w, h1, l1);
        vh[off] = make_uint2(h0, h1);
        vl[off] = make_uint2(l0, l1);
        return;
    }
    const float4* src; uint2* dst; int off;
    if (i < NQ4)               { src = q;  dst = qo;  off = i; }
    else if (i < 2 * NQ4)      { src = k;  dst = ko;  off = i - NQ4; }
    else if (i < 3 * NQ4 + NWI4) { src = wi; dst = wih; off = i - 3 * NQ4; }
    else                       { src = wo; dst = woh; off = i - 3 * NQ4 - NWI4; }
    float4 val = src[off];
    __half2 h01 = __floats2half2_rn(val.x, val.y);
    __half2 h23 = __floats2half2_rn(val.z, val.w);
    dst[off] = make_uint2(*(uint32_t*)&h01, *(uint32_t*)&h23);
}

// dummy row s=1024: q (scaled) / k / v = raw query[-1], fp16
__global__ void fill_last_row_f16(const float* __restrict__ query,
                                  __half* __restrict__ aq, __half* __restrict__ ak,
                                  __half* __restrict__ av)
{
    int idx = blockIdx.x * 256 + threadIdx.x;
    if (idx < B_SZ * E_SZ) {
        size_t off = (size_t)1024 * 8192 + idx;
        float v = query[off];
        aq[off] = __float2half_rn(v * QSCALE);
        ak[off] = __float2half_rn(v);
        av[off] = __float2half_rn(v);
    }
}

// ---------------------------------------------------------------------------
// Flash attention, fp16 mma.sync: QK 1-term, PV 1-term (P single fp16).
// Softmax in exp2 domain. ctx emitted as fp16 hi/lo.
// ---------------------------------------------------------------------------
#define ATTN_SMEM (16384 + 2 * 16384)

__global__ __launch_bounds__(256) void attn_f16(
    const __half* __restrict__ Qf, const __half* __restrict__ Kf,
    const __half* __restrict__ Vf,
    __half* __restrict__ Ch, __half* __restrict__ Cl)
{
    extern __shared__ char sm[];
    const int tid = threadIdx.x, wid = tid >> 5, lane = tid & 31;
    const int qt = blockIdx.x;
    const int b = blockIdx.y >> 4, h = blockIdx.y & 15;
    const size_t colb = (size_t)h * 64;

#pragma unroll
    for (int i = 0; i < 4; ++i) {
        int ch = i * 256 + tid;
        int r = ch >> 3, c = ch & 7;
        uint32_t dst = smem_u32(sm + r * 128 + ((c ^ (r & 7)) << 4));
        int tok = qt * 128 + r;
        const char* src = (const char*)(Qf + (size_t)(tok * 8 + b) * 1024 + colb + c * 8);
        CP_ASYNC16(dst, src, tok <= 1024 ? 16 : 0);
    }

    auto load_kv = [&](int kb, int st) {
        char* sbase = sm + 16384 + st * 16384;
#pragma unroll
        for (int i = 0; i < 4; ++i) {
            int ch = i * 256 + tid;
            int arr = ch >> 9, cc = ch & 511;
            int r = cc >> 3, c = cc & 7;
            uint32_t dst = smem_u32(sbase + arr * 8192 + r * 128 + ((c ^ (r & 7)) << 4));
            int tok = kb * 64 + r;
            const __half* p = arr ? Vf : Kf;
            const char* src = (const char*)(p + (size_t)(tok * 8 + b) * 1024 + colb + c * 8);
            CP_ASYNC16(dst, src, tok <= 1024 ? 16 : 0);
        }
    };
    load_kv(0, 0);
    CP_COMMIT();

    float o[8][4];
#pragma unroll
    for (int nt = 0; nt < 8; ++nt)
#pragma unroll
        for (int j = 0; j < 4; ++j) o[nt][j] = 0.f;
    float m0 = -1e30f, m1 = -1e30f, l0 = 0.f, l1 = 0.f;

    const int a_row_l = lane & 15;
    const int a_chk_l = lane >> 4;
    const int b_row_l = (lane & 7) + ((lane >> 4) << 3);
    const int b_chk_l = (lane >> 3) & 1;
    const uint32_t sQb = smem_u32(sm);

    for (int kb = 0; kb < 17; ++kb) {
        if (kb + 1 < 17) { load_kv(kb + 1, (kb + 1) & 1); CP_COMMIT(); CP_WAIT(1); }
        else CP_WAIT(0);
        __syncthreads();

        const uint32_t sKb = smem_u32(sm + 16384 + (kb & 1) * 16384);
        const uint32_t sVb = sKb + 8192;

        float s[8][4];
#pragma unroll
        for (int nt = 0; nt < 8; ++nt)
#pragma unroll
            for (int j = 0; j < 4; ++j) s[nt][j] = 0.f;

#pragma unroll
        for (int ks = 0; ks < 4; ++ks) {
            uint32_t qf[4];
            {
                int row = wid * 16 + a_row_l;
                int chk = ks * 2 + a_chk_l;
                ldsm4(qf, sQb + row * 128 + ((chk ^ (row & 7)) << 4));
            }
#pragma unroll
            for (int np = 0; np < 4; ++np) {
                uint32_t kf[4];
                int row = np * 16 + b_row_l;
                int chk = ks * 2 + b_chk_l;
                ldsm4(kf, sKb + row * 128 + ((chk ^ (row & 7)) << 4));
                mma_f16(s[np * 2],     qf, &kf[0]);
                mma_f16(s[np * 2 + 1], qf, &kf[2]);
            }
        }

        if (kb == 16) {
#pragma unroll
            for (int nt = 0; nt < 8; ++nt)
#pragma unroll
                for (int j = 0; j < 4; ++j) {
                    int tok = kb * 64 + nt * 8 + (lane & 3) * 2 + (j & 1);
                    if (tok > 1024) s[nt][j] = -1e30f;
                }
        }

        // ---- online softmax (exp2 domain) ----
        float tm0 = -1e30f, tm1 = -1e30f;
#pragma unroll
        for (int nt = 0; nt < 8; ++nt) {
            tm0 = fmaxf(tm0, fmaxf(s[nt][0], s[nt][1]));
            tm1 = fmaxf(tm1, fmaxf(s[nt][2], s[nt][3]));
        }
        tm0 = fmaxf(tm0, __shfl_xor_sync(0xffffffffu, tm0, 1));
        tm0 = fmaxf(tm0, __shfl_xor_sync(0xffffffffu, tm0, 2));
        tm1 = fmaxf(tm1, __shfl_xor_sync(0xffffffffu, tm1, 1));
        tm1 = fmaxf(tm1, __shfl_xor_sync(0xffffffffu, tm1, 2));
        float mn0 = fmaxf(m0, tm0), mn1 = fmaxf(m1, tm1);
        float cr0 = exp2f(m0 - mn0), cr1 = exp2f(m1 - mn1);
        float rs0 = 0.f, rs1 = 0.f;
#pragma unroll
        for (int nt = 0; nt < 8; ++nt) {
            s[nt][0] = exp2f(s[nt][0] - mn0);
            s[nt][1] = exp2f(s[nt][1] - mn0);
            s[nt][2] = exp2f(s[nt][2] - mn1);
            s[nt][3] = exp2f(s[nt][3] - mn1);
            rs0 += s[nt][0] + s[nt][1];
            rs1 += s[nt][2] + s[nt][3];
        }
        rs0 += __shfl_xor_sync(0xffffffffu, rs0, 1);
        rs0 += __shfl_xor_sync(0xffffffffu, rs0, 2);
        rs1 += __shfl_xor_sync(0xffffffffu, rs1, 1);
        rs1 += __shfl_xor_sync(0xffffffffu, rs1, 2);
        l0 = l0 * cr0 + rs0; l1 = l1 * cr1 + rs1;
        m0 = mn0; m1 = mn1;
#pragma unroll
        for (int nt = 0; nt < 8; ++nt) {
            o[nt][0] *= cr0; o[nt][1] *= cr0;
            o[nt][2] *= cr1; o[nt][3] *= cr1;
        }

        // ---- pack P as single fp16 (acc layout == A-frag layout) ----
        uint32_t ph[4][4];
#pragma unroll
        for (int k2 = 0; k2 < 4; ++k2) {
            int t0 = 2 * k2, t1 = t0 + 1;
            ph[k2][0] = pack2h(s[t0][0], s[t0][1]);
            ph[k2][1] = pack2h(s[t0][2], s[t0][3]);
            ph[k2][2] = pack2h(s[t1][0], s[t1][1]);
            ph[k2][3] = pack2h(s[t1][2], s[t1][3]);
        }

        // ---- O += P V (1-term), V via ldmatrix.trans ----
#pragma unroll
        for (int k2 = 0; k2 < 4; ++k2) {
#pragma unroll
            for (int ntp = 0; ntp < 4; ++ntp) {
                uint32_t vf[4];
                int row = k2 * 16 + (lane & 15);
                int chk = ntp * 2 + (lane >> 4);
                ldsm4_t(vf, sVb + row * 128 + ((chk ^ (row & 7)) << 4));
                mma_f16(o[ntp * 2],     ph[k2], &vf[0]);
                mma_f16(o[ntp * 2 + 1], ph[k2], &vf[2]);
            }
        }
        __syncthreads();
    }

    // ---- epilogue: normalize, split to fp16 hi/lo ctx ----
    float inv0 = 1.f / l0, inv1 = 1.f / l1;
    int tok0 = qt * 128 + wid * 16 + (lane >> 2);
    int tok1 = tok0 + 8;
    int dbase = (lane & 3) * 2;
#pragma unroll
    for (int nt = 0; nt < 8; ++nt) {
        int d = nt * 8 + dbase;
        if (tok0 <= 1024) {
            size_t idx = (size_t)(tok0 * 8 + b) * 1024 + colb + d;
            uint32_t hi, lo;
            split2h(o[nt][0] * inv0, o[nt][1] * inv0, hi, lo);
            *(uint32_t*)(Ch + idx) = hi;
            *(uint32_t*)(Cl + idx) = lo;
        }
        if (tok1 <= 1024) {
            size_t idx = (size_t)(tok1 * 8 + b) * 1024 + colb + d;
            uint32_t hi, lo;
            split2h(o[nt][2] * inv1, o[nt][3] * inv1, hi, lo);
            *(uint32_t*)(Ch + idx) = hi;
            *(uint32_t*)(Cl + idx) = lo;
        }
    }
}

// ---------------------------------------------------------------------------
// Launch
// ---------------------------------------------------------------------------
extern "C" void kernel_launch(void* const* d_in, const int* in_sizes, int n_in,
                              void* d_out, int out_size)
{
    const float* query = (const float*)d_in[0];
    const float* key   = (const float*)d_in[1];
    const float* value = (const float*)d_in[2];
    const float* W_in  = (const float*)d_in[3];
    const float* b_in  = (const float*)d_in[4];
    const float* W_out = (const float*)d_in[5];
    const float* b_out = (const float*)d_in[6];
    float* out = (float*)d_out;

    __half *qraw, *kraw, *vh, *vl, *wi, *wo, *aq, *ak, *av, *ch, *cl;
    cudaGetSymbolAddress((void**)&qraw, g_qraw); cudaGetSymbolAddress((void**)&kraw, g_kraw);
    cudaGetSymbolAddress((void**)&vh, g_vh);     cudaGetSymbolAddress((void**)&vl, g_vl);
    cudaGetSymbolAddress((void**)&wi, g_wi);     cudaGetSymbolAddress((void**)&wo, g_wo);
    cudaGetSymbolAddress((void**)&aq, g_aq);     cudaGetSymbolAddress((void**)&ak, g_ak);
    cudaGetSymbolAddress((void**)&av, g_av);
    cudaGetSymbolAddress((void**)&ch, g_ch);     cudaGetSymbolAddress((void**)&cl, g_cl);

    cudaFuncSetAttribute(tc_gemm_qk,  cudaFuncAttributeMaxDynamicSharedMemorySize, GK_SMEM);
    cudaFuncSetAttribute(tc_gemm_v,   cudaFuncAttributeMaxDynamicSharedMemorySize, GK_SMEM);
    cudaFuncSetAttribute(tc_gemm_out, cudaFuncAttributeMaxDynamicSharedMemorySize, GK_SMEM);
    cudaFuncSetAttribute(attn_f16,    cudaFuncAttributeMaxDynamicSharedMemorySize, ATTN_SMEM);

    // fused input conversion
    split_all<<<(NSPLIT_TOT + 255) / 256, 256>>>(
        (const float4*)query, (const float4*)key, (const float4*)value,
        (const float4*)W_in, (const float4*)W_out,
        (uint2*)qraw, (uint2*)kraw, (uint2*)vh, (uint2*)vl,
        (uint2*)wi, (uint2*)wo);

    // projections
    tc_gemm_qk<<<dim3(8, 64, 2), 256, GK_SMEM>>>(qraw, kraw, wi, b_in, aq, ak);
    tc_gemm_v<<<dim3(8, 64, 1), 256, GK_SMEM>>>(vh, vl, wi, b_in, av);

    fill_last_row_f16<<<32, 256>>>(query, aq, ak, av);

    // attention (fp16 mma.sync, QK 1-term / PV 1-term, exp2 softmax)
    attn_f16<<<dim3(9, B_SZ * H_CNT), 256, ATTN_SMEM>>>(aq, ak, av, ch, cl);

    // out projection (2-term)
    tc_gemm_out<<<dim3(8, 65), 256, GK_SMEM>>>(ch, cl, wo, b_out, out, NTOK);
}

// round 14
// speedup vs baseline: 8.1445x; 1.3690x over previous
#include <cuda_runtime.h>
#include <cuda_bf16.h>
#include <cuda_fp16.h>
#include <cstdint>

// Problem constants
#define S_LEN 1025
#define B_SZ  8
#define E_SZ  1024
#define H_CNT 16
#define HD    64
#define NTOK  (S_LEN * B_SZ)          // 8200
#define NTOK_PROJ (1024 * B_SZ)       // 8192
#define QSCALE 0.180336880f           // 0.125 * log2(e)

// ---------------- scratch (device globals: allocation-free) ----------------
__device__ __half g_qraw[NTOK_PROJ * E_SZ];
__device__ __half g_kraw[NTOK_PROJ * E_SZ];
__device__ __half g_vraw[NTOK_PROJ * E_SZ];
__device__ __half g_wi[3072 * 1024];
__device__ __half g_wo[1024 * 1024];
__device__ __half g_aq[NTOK * E_SZ];      // projected q (pre-scaled by 0.125*log2e)
__device__ __half g_ak[NTOK * E_SZ];
__device__ __half g_av[NTOK * E_SZ];
__device__ __half g_c[NTOK * E_SZ];       // ctx, single fp16

// ---------------- helpers (sm_80+ only; legal on bare compute_103) ---------
__device__ __forceinline__ uint32_t smem_u32(const void* p) {
    uint32_t a;
    asm("{ .reg .u64 t; cvta.to.shared.u64 t, %1; cvt.u32.u64 %0, t; }"
        : "=r"(a) : "l"(p));
    return a;
}
__device__ __forceinline__ void ldsm4(uint32_t* r, uint32_t addr) {
    asm volatile("ldmatrix.sync.aligned.m8n8.x4.shared.b16 {%0,%1,%2,%3}, [%4];"
                 : "=r"(r[0]), "=r"(r[1]), "=r"(r[2]), "=r"(r[3]) : "r"(addr));
}
__device__ __forceinline__ void ldsm4_t(uint32_t* r, uint32_t addr) {
    asm volatile("ldmatrix.sync.aligned.m8n8.x4.trans.shared.b16 {%0,%1,%2,%3}, [%4];"
                 : "=r"(r[0]), "=r"(r[1]), "=r"(r[2]), "=r"(r[3]) : "r"(addr));
}
__device__ __forceinline__ void mma_f16(float* d, const uint32_t* a, const uint32_t* b) {
    asm volatile(
        "mma.sync.aligned.m16n8k16.row.col.f32.f16.f16.f32 "
        "{%0,%1,%2,%3}, {%4,%5,%6,%7}, {%8,%9}, {%0,%1,%2,%3};"
        : "+f"(d[0]), "+f"(d[1]), "+f"(d[2]), "+f"(d[3])
        : "r"(a[0]), "r"(a[1]), "r"(a[2]), "r"(a[3]), "r"(b[0]), "r"(b[1]));
}
__device__ __forceinline__ float ex2f(float x) {     // MUFU.EX2 fast path
    float r;
    asm("ex2.approx.ftz.f32 %0, %1;" : "=f"(r) : "f"(x));
    return r;
}
#define CP_ASYNC16(dst, src, sz) \
    asm volatile("cp.async.cg.shared.global [%0], [%1], 16, %2;" \
                 :: "r"(dst), "l"(src), "r"(sz))
#define CP_COMMIT() asm volatile("cp.async.commit_group;" ::: "memory")
#define CP_WAIT(n)  asm volatile("cp.async.wait_group %0;" :: "n"(n) : "memory")

__device__ __forceinline__ uint32_t pack2h(float a, float b) {
    __half2 h = __floats2half2_rn(a, b);
    return *(uint32_t*)&h;
}

// ---------------------------------------------------------------------------
// 1-term fp16 GEMM: C[M,1024] = A[M,1024] @ W[N,1024]^T + bias
// 128x128 CTA tile, BK=64, 8 warps (2x4), 3-stage cp.async pipeline.
// Stage: [A | W], 16KB each = 32KB; 3 stages = 96KB -> 2 CTAs/SM.
// ---------------------------------------------------------------------------
#define OP_BYTES    (128 * 128)
#define STAGE_BYTES (2 * OP_BYTES)        // 32 KB
#define GK_SMEM     (3 * STAGE_BYTES)     // 96 KB

__device__ __forceinline__ void load_stage(
    char* stage, const __half* __restrict__ A, const __half* __restrict__ W,
    int m0, int n0, int k0, int M, int tid)
{
#pragma unroll
    for (int o = 0; o < 2; ++o) {
        const __half* src_base = (o == 0) ? A : W;
        const int row0 = (o == 0) ? m0 : n0;
        char* dstop = stage + o * OP_BYTES;
#pragma unroll
        for (int i = 0; i < 4; ++i) {
            int ch = i * 256 + tid;
            int r = ch >> 3, c = ch & 7;
            uint32_t dst = smem_u32(dstop + r * 128 + ((c ^ (r & 7)) << 4));
            const char* src = (const char*)(src_base + (size_t)(row0 + r) * 1024 + k0 + c * 8);
            int sz = (o == 1 || (row0 + r) < M) ? 16 : 0;
            CP_ASYNC16(dst, src, sz);
        }
    }
}

template<int OUT_MODE>   // 0: fp32 C; 2: fp16 H * oscale
__device__ __forceinline__ void tc_gemm_body(
    const __half* __restrict__ A, const __half* __restrict__ W,
    const float* __restrict__ bias, float* __restrict__ C,
    __half* __restrict__ H, float oscale, int M,
    char* sm, int n0, int m0)
{
    const int tid = threadIdx.x;
    const int wid = tid >> 5, lane = tid & 31;
    const int wm = wid >> 2, wn = wid & 3;

    float acc[4][4][4];
#pragma unroll
    for (int a = 0; a < 4; ++a)
#pragma unroll
        for (int b = 0; b < 4; ++b)
#pragma unroll
            for (int c = 0; c < 4; ++c) acc[a][b][c] = 0.f;

    const int a_row_l = lane & 15;
    const int a_chk_l = lane >> 4;
    const int b_row_l = (lane & 7) + ((lane >> 4) << 3);
    const int b_chk_l = (lane >> 3) & 1;

    load_stage(sm,               A, W, m0, n0, 0,  M, tid); CP_COMMIT();
    load_stage(sm + STAGE_BYTES, A, W, m0, n0, 64, M, tid); CP_COMMIT();

    int cur = 0, pre = 2;
    for (int t = 0; t < 16; ++t) {
        CP_WAIT(1);
        __syncthreads();
        if (t + 2 < 16)
            load_stage(sm + pre * STAGE_BYTES, A, W, m0, n0, (t + 2) * 64, M, tid);
        CP_COMMIT();

        char* st = sm + cur * STAGE_BYTES;
        const uint32_t sA = smem_u32(st);
        const uint32_t sW = sA + OP_BYTES;

#pragma unroll
        for (int ks = 0; ks < 4; ++ks) {
            uint32_t a4[4][4], w[2][4];
            const int achk = ks * 2 + a_chk_l;
#pragma unroll
            for (int mt = 0; mt < 4; ++mt) {
                int row = wm * 64 + mt * 16 + a_row_l;
                ldsm4(a4[mt], sA + row * 128 + ((achk ^ (row & 7)) << 4));
            }
            const int bchk = ks * 2 + b_chk_l;
#pragma unroll
            for (int np = 0; np < 2; ++np) {
                int row = wn * 32 + np * 16 + b_row_l;
                ldsm4(w[np], sW + row * 128 + ((bchk ^ (row & 7)) << 4));
            }
#pragma unroll
            for (int mt = 0; mt < 4; ++mt)
#pragma unroll
                for (int np = 0; np < 2; ++np) {
                    mma_f16(acc[mt][np * 2],     a4[mt], &w[np][0]);
                    mma_f16(acc[mt][np * 2 + 1], a4[mt], &w[np][2]);
                }
        }
        cur = (cur == 2) ? 0 : cur + 1;
        pre = (pre == 2) ? 0 : pre + 1;
    }

#pragma unroll
    for (int mt = 0; mt < 4; ++mt) {
        int mA = m0 + wm * 64 + mt * 16 + (lane >> 2);
        int mB = mA + 8;
#pragma unroll
        for (int nt = 0; nt < 4; ++nt) {
            int n = n0 + wn * 32 + nt * 8 + (lane & 3) * 2;
            float2 bv = *(const float2*)&bias[n];
            float v0 = acc[mt][nt][0] + bv.x, v1 = acc[mt][nt][1] + bv.y;
            float v2 = acc[mt][nt][2] + bv.x, v3 = acc[mt][nt][3] + bv.y;
            if (OUT_MODE == 2) {
                if (mA < M) {
                    __half2 hv = __floats2half2_rn(v0 * oscale, v1 * oscale);
                    *(uint32_t*)(H + (size_t)mA * 1024 + n) = *(uint32_t*)&hv;
                }
                if (mB < M) {
                    __half2 hv = __floats2half2_rn(v2 * oscale, v3 * oscale);
                    *(uint32_t*)(H + (size_t)mB * 1024 + n) = *(uint32_t*)&hv;
                }
            } else {
                if (mA < M) *(float2*)&C[(size_t)mA * 1024 + n] = make_float2(v0, v1);
                if (mB < M) *(float2*)&C[(size_t)mB * 1024 + n] = make_float2(v2, v3);
            }
        }
    }
}

// all three projections: 1-term fp16, one launch
__global__ __launch_bounds__(256)
void tc_gemm_qkv(const __half* __restrict__ qraw, const __half* __restrict__ kraw,
                 const __half* __restrict__ vraw,
                 const __half* __restrict__ W, const float* __restrict__ bias,
                 __half* __restrict__ oq, __half* __restrict__ ok, __half* __restrict__ ov)
{
    extern __shared__ char sm[];
    const int z = blockIdx.z;
    const __half* A = (z == 0) ? qraw : (z == 1) ? kraw : vraw;
    __half* H = (z == 0) ? oq : (z == 1) ? ok : ov;
    tc_gemm_body<2>(A, W + (size_t)z * 1024 * 1024, bias + z * 1024,
                    nullptr, H, (z == 0) ? QSCALE : 1.f, NTOK_PROJ, sm,
                    blockIdx.x * 128, blockIdx.y * 128);
}

// out projection: 1-term fp16, fp32 out
__global__ __launch_bounds__(256)
void tc_gemm_out(const __half* __restrict__ A, const __half* __restrict__ W,
                 const float* __restrict__ bias, float* __restrict__ C, int M)
{
    extern __shared__ char sm[];
    tc_gemm_body<0>(A, W, bias, C, nullptr, 1.f, M, sm,
                    blockIdx.x * 128, blockIdx.y * 128);
}

// ---------------------------------------------------------------------------
// Fused input conversion: all 5 tensors -> single fp16
// ---------------------------------------------------------------------------
#define NQ4  (NTOK_PROJ * E_SZ / 4)
#define NWI4 (3072 * 1024 / 4)
#define NWO4 (1024 * 1024 / 4)
#define NSPLIT_TOT (3 * NQ4 + NWI4 + NWO4)

__global__ __launch_bounds__(256) void split_all(
    const float4* __restrict__ q, const float4* __restrict__ k, const float4* __restrict__ v,
    const float4* __restrict__ wi, const float4* __restrict__ wo,
    uint2* __restrict__ qo, uint2* __restrict__ ko, uint2* __restrict__ vo,
    uint2* __restrict__ wih, uint2* __restrict__ woh)
{
    int i = blockIdx.x * 256 + threadIdx.x;
    if (i >= NSPLIT_TOT) return;
    const float4* src; uint2* dst; int off;
    if (i < NQ4)                 { src = q;  dst = qo;  off = i; }
    else if (i < 2 * NQ4)        { src = k;  dst = ko;  off = i - NQ4; }
    else if (i < 3 * NQ4)        { src = v;  dst = vo;  off = i - 2 * NQ4; }
    else if (i < 3 * NQ4 + NWI4) { src = wi; dst = wih; off = i - 3 * NQ4; }
    else                         { src = wo; dst = woh; off = i - 3 * NQ4 - NWI4; }
    float4 val = src[off];
    __half2 h01 = __floats2half2_rn(val.x, val.y);
    __half2 h23 = __floats2half2_rn(val.z, val.w);
    dst[off] = make_uint2(*(uint32_t*)&h01, *(uint32_t*)&h23);
}

// dummy row s=1024: q (scaled) / k / v = raw query[-1], fp16
__global__ void fill_last_row_f16(const float* __restrict__ query,
                                  __half* __restrict__ aq, __half* __restrict__ ak,
                                  __half* __restrict__ av)
{
    int idx = blockIdx.x * 256 + threadIdx.x;
    if (idx < B_SZ * E_SZ) {
        size_t off = (size_t)1024 * 8192 + idx;
        float v = query[off];
        aq[off] = __float2half_rn(v * QSCALE);
        ak[off] = __float2half_rn(v);
        av[off] = __float2half_rn(v);
    }
}

// ---------------------------------------------------------------------------
// Flash attention, fp16 mma.sync: QK 1-term, PV 1-term, MUFU ex2 softmax.
// ctx emitted as single fp16.
// ---------------------------------------------------------------------------
#define ATTN_SMEM (16384 + 2 * 16384)

__global__ __launch_bounds__(256) void attn_f16(
    const __half* __restrict__ Qf, const __half* __restrict__ Kf,
    const __half* __restrict__ Vf, __half* __restrict__ Ctx)
{
    extern __shared__ char sm[];
    const int tid = threadIdx.x, wid = tid >> 5, lane = tid & 31;
    const int qt = blockIdx.x;
    const int b = blockIdx.y >> 4, h = blockIdx.y & 15;
    const size_t colb = (size_t)h * 64;

#pragma unroll
    for (int i = 0; i < 4; ++i) {
        int ch = i * 256 + tid;
        int r = ch >> 3, c = ch & 7;
        uint32_t dst = smem_u32(sm + r * 128 + ((c ^ (r & 7)) << 4));
        int tok = qt * 128 + r;
        const char* src = (const char*)(Qf + (size_t)(tok * 8 + b) * 1024 + colb + c * 8);
        CP_ASYNC16(dst, src, tok <= 1024 ? 16 : 0);
    }

    auto load_kv = [&](int kb, int st) {
        char* sbase = sm + 16384 + st * 16384;
#pragma unroll
        for (int i = 0; i < 4; ++i) {
            int ch = i * 256 + tid;
            int arr = ch >> 9, cc = ch & 511;
            int r = cc >> 3, c = cc & 7;
            uint32_t dst = smem_u32(sbase + arr * 8192 + r * 128 + ((c ^ (r & 7)) << 4));
            int tok = kb * 64 + r;
            const __half* p = arr ? Vf : Kf;
            const char* src = (const char*)(p + (size_t)(tok * 8 + b) * 1024 + colb + c * 8);
            CP_ASYNC16(dst, src, tok <= 1024 ? 16 : 0);
        }
    };
    load_kv(0, 0);
    CP_COMMIT();

    float o[8][4];
#pragma unroll
    for (int nt = 0; nt < 8; ++nt)
#pragma unroll
        for (int j = 0; j < 4; ++j) o[nt][j] = 0.f;
    float m0 = -1e30f, m1 = -1e30f, l0 = 0.f, l1 = 0.f;

    const int a_row_l = lane & 15;
    const int a_chk_l = lane >> 4;
    const int b_row_l = (lane & 7) + ((lane >> 4) << 3);
    const int b_chk_l = (lane >> 3) & 1;
    const uint32_t sQb = smem_u32(sm);

    for (int kb = 0; kb < 17; ++kb) {
        if (kb + 1 < 17) { load_kv(kb + 1, (kb + 1) & 1); CP_COMMIT(); CP_WAIT(1); }
        else CP_WAIT(0);
        __syncthreads();

        const uint32_t sKb = smem_u32(sm + 16384 + (kb & 1) * 16384);
        const uint32_t sVb = sKb + 8192;

        float s[8][4];
#pragma unroll
        for (int nt = 0; nt < 8; ++nt)
#pragma unroll
            for (int j = 0; j < 4; ++j) s[nt][j] = 0.f;

#pragma unroll
        for (int ks = 0; ks < 4; ++ks) {
            uint32_t qf[4];
            {
                int row = wid * 16 + a_row_l;
                int chk = ks * 2 + a_chk_l;
                ldsm4(qf, sQb + row * 128 + ((chk ^ (row & 7)) << 4));
            }
#pragma unroll
            for (int np = 0; np < 4; ++np) {
                uint32_t kf[4];
                int row = np * 16 + b_row_l;
                int chk = ks * 2 + b_chk_l;
                ldsm4(kf, sKb + row * 128 + ((chk ^ (row & 7)) << 4));
                mma_f16(s[np * 2],     qf, &kf[0]);
                mma_f16(s[np * 2 + 1], qf, &kf[2]);
            }
        }

        if (kb == 16) {
#pragma unroll
            for (int nt = 0; nt < 8; ++nt)
#pragma unroll
                for (int j = 0; j < 4; ++j) {
                    int tok = kb * 64 + nt * 8 + (lane & 3) * 2 + (j & 1);
                    if (tok > 1024) s[nt][j] = -1e30f;
                }
        }

        // ---- online softmax (exp2 domain, MUFU ex2) ----
        float tm0 = -1e30f, tm1 = -1e30f;
#pragma unroll
        for (int nt = 0; nt < 8; ++nt) {
            tm0 = fmaxf(tm0, fmaxf(s[nt][0], s[nt][1]));
            tm1 = fmaxf(tm1, fmaxf(s[nt][2], s[nt][3]));
        }
        tm0 = fmaxf(tm0, __shfl_xor_sync(0xffffffffu, tm0, 1));
        tm0 = fmaxf(tm0, __shfl_xor_sync(0xffffffffu, tm0, 2));
        tm1 = fmaxf(tm1, __shfl_xor_sync(0xffffffffu, tm1, 1));
        tm1 = fmaxf(tm1, __shfl_xor_sync(0xffffffffu, tm1, 2));
        float mn0 = fmaxf(m0, tm0), mn1 = fmaxf(m1, tm1);
        float cr0 = ex2f(m0 - mn0), cr1 = ex2f(m1 - mn1);
        float rs0 = 0.f, rs1 = 0.f;
#pragma unroll
        for (int nt = 0; nt < 8; ++nt) {
            s[nt][0] = ex2f(s[nt][0] - mn0);
            s[nt][1] = ex2f(s[nt][1] - mn0);
            s[nt][2] = ex2f(s[nt][2] - mn1);
            s[nt][3] = ex2f(s[nt][3] - mn1);
            rs0 += s[nt][0] + s[nt][1];
            rs1 += s[nt][2] + s[nt][3];
        }
        rs0 += __shfl_xor_sync(0xffffffffu, rs0, 1);
        rs0 += __shfl_xor_sync(0xffffffffu, rs0, 2);
        rs1 += __shfl_xor_sync(0xffffffffu, rs1, 1);
        rs1 += __shfl_xor_sync(0xffffffffu, rs1, 2);
        l0 = l0 * cr0 + rs0; l1 = l1 * cr1 + rs1;
        m0 = mn0; m1 = mn1;
#pragma unroll
        for (int nt = 0; nt < 8; ++nt) {
            o[nt][0] *= cr0; o[nt][1] *= cr0;
            o[nt][2] *= cr1; o[nt][3] *= cr1;
        }

        // ---- pack P as single fp16 (acc layout == A-frag layout) ----
        uint32_t ph[4][4];
#pragma unroll
        for (int k2 = 0; k2 < 4; ++k2) {
            int t0 = 2 * k2, t1 = t0 + 1;
            ph[k2][0] = pack2h(s[t0][0], s[t0][1]);
            ph[k2][1] = pack2h(s[t0][2], s[t0][3]);
            ph[k2][2] = pack2h(s[t1][0], s[t1][1]);
            ph[k2][3] = pack2h(s[t1][2], s[t1][3]);
        }

        // ---- O += P V (1-term), V via ldmatrix.trans ----
#pragma unroll
        for (int k2 = 0; k2 < 4; ++k2) {
#pragma unroll
            for (int ntp = 0; ntp < 4; ++ntp) {
                uint32_t vf[4];
                int row = k2 * 16 + (lane & 15);
                int chk = ntp * 2 + (lane >> 4);
                ldsm4_t(vf, sVb + row * 128 + ((chk ^ (row & 7)) << 4));
                mma_f16(o[ntp * 2],     ph[k2], &vf[0]);
                mma_f16(o[ntp * 2 + 1], ph[k2], &vf[2]);
            }
        }
        __syncthreads();
    }

    // ---- epilogue: normalize, single fp16 ctx ----
    float inv0 = 1.f / l0, inv1 = 1.f / l1;
    int tok0 = qt * 128 + wid * 16 + (lane >> 2);
    int tok1 = tok0 + 8;
    int dbase = (lane & 3) * 2;
#pragma unroll
    for (int nt = 0; nt < 8; ++nt) {
        int d = nt * 8 + dbase;
        if (tok0 <= 1024) {
            size_t idx = (size_t)(tok0 * 8 + b) * 1024 + colb + d;
            *(uint32_t*)(Ctx + idx) = pack2h(o[nt][0] * inv0, o[nt][1] * inv0);
        }
        if (tok1 <= 1024) {
            size_t idx = (size_t)(tok1 * 8 + b) * 1024 + colb + d;
            *(uint32_t*)(Ctx + idx) = pack2h(o[nt][2] * inv1, o[nt][3] * inv1);
        }
    }
}

// ---------------------------------------------------------------------------
// Launch
// ---------------------------------------------------------------------------
extern "C" void kernel_launch(void* const* d_in, const int* in_sizes, int n_in,
                              void* d_out, int out_size)
{
    const float* query = (const float*)d_in[0];
    const float* key   = (const float*)d_in[1];
    const float* value = (const float*)d_in[2];
    const float* W_in  = (const float*)d_in[3];
    const float* b_in  = (const float*)d_in[4];
    const float* W_out = (const float*)d_in[5];
    const float* b_out = (const float*)d_in[6];
    float* out = (float*)d_out;

    __half *qraw, *kraw, *vraw, *wi, *wo, *aq, *ak, *av, *ctx;
    cudaGetSymbolAddress((void**)&qraw, g_qraw);
    cudaGetSymbolAddress((void**)&kraw, g_kraw);
    cudaGetSymbolAddress((void**)&vraw, g_vraw);
    cudaGetSymbolAddress((void**)&wi, g_wi);
    cudaGetSymbolAddress((void**)&wo, g_wo);
    cudaGetSymbolAddress((void**)&aq, g_aq);
    cudaGetSymbolAddress((void**)&ak, g_ak);
    cudaGetSymbolAddress((void**)&av, g_av);
    cudaGetSymbolAddress((void**)&ctx, g_c);

    cudaFuncSetAttribute(tc_gemm_qkv, cudaFuncAttributeMaxDynamicSharedMemorySize, GK_SMEM);
    cudaFuncSetAttribute(tc_gemm_out, cudaFuncAttributeMaxDynamicSharedMemorySize, GK_SMEM);
    cudaFuncSetAttribute(attn_f16,    cudaFuncAttributeMaxDynamicSharedMemorySize, ATTN_SMEM);

    // fused input conversion (all single fp16)
    split_all<<<(NSPLIT_TOT + 255) / 256, 256>>>(
        (const float4*)query, (const float4*)key, (const float4*)value,
        (const float4*)W_in, (const float4*)W_out,
        (uint2*)qraw, (uint2*)kraw, (uint2*)vraw, (uint2*)wi, (uint2*)wo);

    // QKV projections (1-term fp16, single launch)
    tc_gemm_qkv<<<dim3(8, 64, 3), 256, GK_SMEM>>>(qraw, kraw, vraw, wi, b_in, aq, ak, av);

    fill_last_row_f16<<<32, 256>>>(query, aq, ak, av);

    // attention (fp16 mma.sync, MUFU ex2 softmax)
    attn_f16<<<dim3(9, B_SZ * H_CNT), 256, ATTN_SMEM>>>(aq, ak, av, ctx);

    // out projection (1-term fp16)
    tc_gemm_out<<<dim3(8, 65), 256, GK_SMEM>>>(ctx, wo, b_out, out, NTOK);
}

// round 16
// speedup vs baseline: 8.5028x; 1.0440x over previous
#include <cuda_runtime.h>
#include <cuda_bf16.h>
#include <cuda_fp16.h>
#include <cstdint>

// Problem constants
#define S_LEN 1025
#define B_SZ  8
#define E_SZ  1024
#define H_CNT 16
#define HD    64
#define NTOK  (S_LEN * B_SZ)          // 8200
#define NTOK_PROJ (1024 * B_SZ)       // 8192
#define QSCALE 0.180336880f           // 0.125 * log2(e)

// ---------------- scratch (device globals: allocation-free) ----------------
__device__ __half g_qraw[NTOK_PROJ * E_SZ];
__device__ __half g_kraw[NTOK_PROJ * E_SZ];
__device__ __half g_vraw[NTOK_PROJ * E_SZ];
__device__ __half g_wi[3072 * 1024];
__device__ __half g_wo[1024 * 1024];
__device__ __half g_aq[NTOK * E_SZ];      // projected q (pre-scaled by 0.125*log2e)
__device__ __half g_ak[NTOK * E_SZ];
__device__ __half g_av[NTOK * E_SZ];
__device__ __half g_c[NTOK * E_SZ];       // ctx, single fp16

// ---------------- helpers ----------------
__device__ __forceinline__ uint32_t smem_u32(const void* p) {
    uint32_t a;
    asm("{ .reg .u64 t; cvta.to.shared.u64 t, %1; cvt.u32.u64 %0, t; }"
        : "=r"(a) : "l"(p));
    return a;
}
__device__ __forceinline__ void ldsm4(uint32_t* r, uint32_t addr) {
    asm volatile("ldmatrix.sync.aligned.m8n8.x4.shared.b16 {%0,%1,%2,%3}, [%4];"
                 : "=r"(r[0]), "=r"(r[1]), "=r"(r[2]), "=r"(r[3]) : "r"(addr));
}
__device__ __forceinline__ void ldsm4_t(uint32_t* r, uint32_t addr) {
    asm volatile("ldmatrix.sync.aligned.m8n8.x4.trans.shared.b16 {%0,%1,%2,%3}, [%4];"
                 : "=r"(r[0]), "=r"(r[1]), "=r"(r[2]), "=r"(r[3]) : "r"(addr));
}
__device__ __forceinline__ void mma_f16(float* d, const uint32_t* a, const uint32_t* b) {
    asm volatile(
        "mma.sync.aligned.m16n8k16.row.col.f32.f16.f16.f32 "
        "{%0,%1,%2,%3}, {%4,%5,%6,%7}, {%8,%9}, {%0,%1,%2,%3};"
        : "+f"(d[0]), "+f"(d[1]), "+f"(d[2]), "+f"(d[3])
        : "r"(a[0]), "r"(a[1]), "r"(a[2]), "r"(a[3]), "r"(b[0]), "r"(b[1]));
}
__device__ __forceinline__ float ex2f(float x) {
    float r;
    asm("ex2.approx.ftz.f32 %0, %1;" : "=f"(r) : "f"(x));
    return r;
}
#define CP_ASYNC16(dst, src, sz) \
    asm volatile("cp.async.cg.shared.global [%0], [%1], 16, %2;" \
                 :: "r"(dst), "l"(src), "r"(sz))
#define CP_COMMIT() asm volatile("cp.async.commit_group;" ::: "memory")
#define CP_WAIT(n)  asm volatile("cp.async.wait_group %0;" :: "n"(n) : "memory")

__device__ __forceinline__ uint32_t pack2h(float a, float b) {
    __half2 h = __floats2half2_rn(a, b);
    return *(uint32_t*)&h;
}

// ---------------------------------------------------------------------------
// 1-term fp16 GEMM (unchanged from R14): 128x128 tile, BK=64, 8 warps, 3-stage
// ---------------------------------------------------------------------------
#define OP_BYTES    (128 * 128)
#define STAGE_BYTES (2 * OP_BYTES)        // 32 KB
#define GK_SMEM     (3 * STAGE_BYTES)     // 96 KB

__device__ __forceinline__ void load_stage(
    char* stage, const __half* __restrict__ A, const __half* __restrict__ W,
    int m0, int n0, int k0, int M, int tid)
{
#pragma unroll
    for (int o = 0; o < 2; ++o) {
        const __half* src_base = (o == 0) ? A : W;
        const int row0 = (o == 0) ? m0 : n0;
        char* dstop = stage + o * OP_BYTES;
#pragma unroll
        for (int i = 0; i < 4; ++i) {
            int ch = i * 256 + tid;
            int r = ch >> 3, c = ch & 7;
            uint32_t dst = smem_u32(dstop + r * 128 + ((c ^ (r & 7)) << 4));
            const char* src = (const char*)(src_base + (size_t)(row0 + r) * 1024 + k0 + c * 8);
            int sz = (o == 1 || (row0 + r) < M) ? 16 : 0;
            CP_ASYNC16(dst, src, sz);
        }
    }
}

template<int OUT_MODE>   // 0: fp32 C; 2: fp16 H * oscale
__device__ __forceinline__ void tc_gemm_body(
    const __half* __restrict__ A, const __half* __restrict__ W,
    const float* __restrict__ bias, float* __restrict__ C,
    __half* __restrict__ H, float oscale, int M,
    char* sm, int n0, int m0)
{
    const int tid = threadIdx.x;
    const int wid = tid >> 5, lane = tid & 31;
    const int wm = wid >> 2, wn = wid & 3;

    float acc[4][4][4];
#pragma unroll
    for (int a = 0; a < 4; ++a)
#pragma unroll
        for (int b = 0; b < 4; ++b)
#pragma unroll
            for (int c = 0; c < 4; ++c) acc[a][b][c] = 0.f;

    const int a_row_l = lane & 15;
    const int a_chk_l = lane >> 4;
    const int b_row_l = (lane & 7) + ((lane >> 4) << 3);
    const int b_chk_l = (lane >> 3) & 1;

    load_stage(sm,               A, W, m0, n0, 0,  M, tid); CP_COMMIT();
    load_stage(sm + STAGE_BYTES, A, W, m0, n0, 64, M, tid); CP_COMMIT();

    int cur = 0, pre = 2;
    for (int t = 0; t < 16; ++t) {
        CP_WAIT(1);
        __syncthreads();
        if (t + 2 < 16)
            load_stage(sm + pre * STAGE_BYTES, A, W, m0, n0, (t + 2) * 64, M, tid);
        CP_COMMIT();

        char* st = sm + cur * STAGE_BYTES;
        const uint32_t sA = smem_u32(st);
        const uint32_t sW = sA + OP_BYTES;

#pragma unroll
        for (int ks = 0; ks < 4; ++ks) {
            uint32_t a4[4][4], w[2][4];
            const int achk = ks * 2 + a_chk_l;
#pragma unroll
            for (int mt = 0; mt < 4; ++mt) {
                int row = wm * 64 + mt * 16 + a_row_l;
                ldsm4(a4[mt], sA + row * 128 + ((achk ^ (row & 7)) << 4));
            }
            const int bchk = ks * 2 + b_chk_l;
#pragma unroll
            for (int np = 0; np < 2; ++np) {
                int row = wn * 32 + np * 16 + b_row_l;
                ldsm4(w[np], sW + row * 128 + ((bchk ^ (row & 7)) << 4));
            }
#pragma unroll
            for (int mt = 0; mt < 4; ++mt)
#pragma unroll
                for (int np = 0; np < 2; ++np) {
                    mma_f16(acc[mt][np * 2],     a4[mt], &w[np][0]);
                    mma_f16(acc[mt][np * 2 + 1], a4[mt], &w[np][2]);
                }
        }
        cur = (cur == 2) ? 0 : cur + 1;
        pre = (pre == 2) ? 0 : pre + 1;
    }

#pragma unroll
    for (int mt = 0; mt < 4; ++mt) {
        int mA = m0 + wm * 64 + mt * 16 + (lane >> 2);
        int mB = mA + 8;
#pragma unroll
        for (int nt = 0; nt < 4; ++nt) {
            int n = n0 + wn * 32 + nt * 8 + (lane & 3) * 2;
            float2 bv = *(const float2*)&bias[n];
            float v0 = acc[mt][nt][0] + bv.x, v1 = acc[mt][nt][1] + bv.y;
            float v2 = acc[mt][nt][2] + bv.x, v3 = acc[mt][nt][3] + bv.y;
            if (OUT_MODE == 2) {
                if (mA < M) {
                    __half2 hv = __floats2half2_rn(v0 * oscale, v1 * oscale);
                    *(uint32_t*)(H + (size_t)mA * 1024 + n) = *(uint32_t*)&hv;
                }
                if (mB < M) {
                    __half2 hv = __floats2half2_rn(v2 * oscale, v3 * oscale);
                    *(uint32_t*)(H + (size_t)mB * 1024 + n) = *(uint32_t*)&hv;
                }
            } else {
                if (mA < M) *(float2*)&C[(size_t)mA * 1024 + n] = make_float2(v0, v1);
                if (mB < M) *(float2*)&C[(size_t)mB * 1024 + n] = make_float2(v2, v3);
            }
        }
    }
}

__global__ __launch_bounds__(256)
void tc_gemm_qkv(const __half* __restrict__ qraw, const __half* __restrict__ kraw,
                 const __half* __restrict__ vraw,
                 const __half* __restrict__ W, const float* __restrict__ bias,
                 __half* __restrict__ oq, __half* __restrict__ ok, __half* __restrict__ ov)
{
    extern __shared__ char sm[];
    const int z = blockIdx.z;
    const __half* A = (z == 0) ? qraw : (z == 1) ? kraw : vraw;
    __half* H = (z == 0) ? oq : (z == 1) ? ok : ov;
    tc_gemm_body<2>(A, W + (size_t)z * 1024 * 1024, bias + z * 1024,
                    nullptr, H, (z == 0) ? QSCALE : 1.f, NTOK_PROJ, sm,
                    blockIdx.x * 128, blockIdx.y * 128);
}

__global__ __launch_bounds__(256)
void tc_gemm_out(const __half* __restrict__ A, const __half* __restrict__ W,
                 const float* __restrict__ bias, float* __restrict__ C, int M)
{
    extern __shared__ char sm[];
    tc_gemm_body<0>(A, W, bias, C, nullptr, 1.f, M, sm,
                    blockIdx.x * 128, blockIdx.y * 128);
}

// ---------------------------------------------------------------------------
// Fused input conversion (4 elems/thread for MLP) + dummy-row fill at tail
// ---------------------------------------------------------------------------
#define NQ4  (NTOK_PROJ * E_SZ / 4)          // 2,097,152
#define NWI4 (3072 * 1024 / 4)
#define NWO4 (1024 * 1024 / 4)
#define NSPLIT_TOT (3 * NQ4 + NWI4 + NWO4)   // 7,340,032
#define FILL4 2048                            // 8192 floats of dummy row
#define SPLIT_EXT (NSPLIT_TOT + FILL4)

__global__ __launch_bounds__(256) void split_all(
    const float4* __restrict__ q, const float4* __restrict__ k, const float4* __restrict__ v,
    const float4* __restrict__ wi, const float4* __restrict__ wo,
    uint2* __restrict__ qo, uint2* __restrict__ ko, uint2* __restrict__ vo,
    uint2* __restrict__ wih, uint2* __restrict__ woh,
    uint2* __restrict__ aq2, uint2* __restrict__ ak2, uint2* __restrict__ av2)
{
    int base = blockIdx.x * 1024 + threadIdx.x;
#pragma unroll
    for (int u = 0; u < 4; ++u) {
        int i = base + u * 256;
        if (i >= SPLIT_EXT) break;
        if (i >= NSPLIT_TOT) {
            // dummy row s=1024: q scaled, k, v from raw query[-1]
            int off = i - NSPLIT_TOT;
            float4 val = q[NQ4 + off];       // query row 1024 (float4 idx 2,097,152+)
            uint2 hk;
            __half2 k01 = __floats2half2_rn(val.x, val.y);
            __half2 k23 = __floats2half2_rn(val.z, val.w);
            hk.x = *(uint32_t*)&k01; hk.y = *(uint32_t*)&k23;
            uint2 hq;
            __half2 q01 = __floats2half2_rn(val.x * QSCALE, val.y * QSCALE);
            __half2 q23 = __floats2half2_rn(val.z * QSCALE, val.w * QSCALE);
            hq.x = *(uint32_t*)&q01; hq.y = *(uint32_t*)&q23;
            aq2[NQ4 + off] = hq;
            ak2[NQ4 + off] = hk;
            av2[NQ4 + off] = hk;
            continue;
        }
        const float4* src; uint2* dst; int off;
        if (i < NQ4)                 { src = q;  dst = qo;  off = i; }
        else if (i < 2 * NQ4)        { src = k;  dst = ko;  off = i - NQ4; }
        else if (i < 3 * NQ4)        { src = v;  dst = vo;  off = i - 2 * NQ4; }
        else if (i < 3 * NQ4 + NWI4) { src = wi; dst = wih; off = i - 3 * NQ4; }
        else                         { src = wo; dst = woh; off = i - 3 * NQ4 - NWI4; }
        float4 val = src[off];
        __half2 h01 = __floats2half2_rn(val.x, val.y);
        __half2 h23 = __floats2half2_rn(val.z, val.w);
        dst[off] = make_uint2(*(uint32_t*)&h01, *(uint32_t*)&h23);
    }
}

// ---------------------------------------------------------------------------
// Flash attention, fp16 mma.sync, 4 warps x m32 warp tiles (K/V reuse 2x).
// CTA = 128 threads, 128 q rows; key blocks of 64, double-buffered cp.async.
// smem: Q 16KB + 2 stages x (K 8KB + V 8KB) = 48 KB.
// ---------------------------------------------------------------------------
#define ATTN_SMEM (16384 + 2 * 16384)

__global__ __launch_bounds__(128) void attn_f16(
    const __half* __restrict__ Qf, const __half* __restrict__ Kf,
    const __half* __restrict__ Vf, __half* __restrict__ Ctx)
{
    extern __shared__ char sm[];
    const int tid = threadIdx.x, wid = tid >> 5, lane = tid & 31;
    const int qt = blockIdx.x;
    const int b = blockIdx.y >> 4, h = blockIdx.y & 15;
    const size_t colb = (size_t)h * 64;

    // ---- Q tile (128 x 64 fp16 = 16KB), 1024 chunks over 128 threads ----
#pragma unroll
    for (int i = 0; i < 8; ++i) {
        int ch = i * 128 + tid;
        int r = ch >> 3, c = ch & 7;
        uint32_t dst = smem_u32(sm + r * 128 + ((c ^ (r & 7)) << 4));
        int tok = qt * 128 + r;
        const char* src = (const char*)(Qf + (size_t)(tok * 8 + b) * 1024 + colb + c * 8);
        CP_ASYNC16(dst, src, tok <= 1024 ? 16 : 0);
    }

    auto load_kv = [&](int kb, int st) {
        char* sbase = sm + 16384 + st * 16384;
#pragma unroll
        for (int i = 0; i < 8; ++i) {
            int ch = i * 128 + tid;
            int arr = ch >> 9, cc = ch & 511;
            int r = cc >> 3, c = cc & 7;
            uint32_t dst = smem_u32(sbase + arr * 8192 + r * 128 + ((c ^ (r & 7)) << 4));
            int tok = kb * 64 + r;
            const __half* p = arr ? Vf : Kf;
            const char* src = (const char*)(p + (size_t)(tok * 8 + b) * 1024 + colb + c * 8);
            CP_ASYNC16(dst, src, tok <= 1024 ? 16 : 0);
        }
    };
    load_kv(0, 0);
    CP_COMMIT();

    float o[2][8][4];
#pragma unroll
    for (int mt = 0; mt < 2; ++mt)
#pragma unroll
        for (int nt = 0; nt < 8; ++nt)
#pragma unroll
            for (int j = 0; j < 4; ++j) o[mt][nt][j] = 0.f;
    float mr[2][2], lr[2][2];
#pragma unroll
    for (int mt = 0; mt < 2; ++mt) {
        mr[mt][0] = -1e30f; mr[mt][1] = -1e30f;
        lr[mt][0] = 0.f;    lr[mt][1] = 0.f;
    }

    const int a_row_l = lane & 15;
    const int a_chk_l = lane >> 4;
    const int b_row_l = (lane & 7) + ((lane >> 4) << 3);
    const int b_chk_l = (lane >> 3) & 1;
    const uint32_t sQb = smem_u32(sm);

    for (int kb = 0; kb < 17; ++kb) {
        if (kb + 1 < 17) { load_kv(kb + 1, (kb + 1) & 1); CP_COMMIT(); CP_WAIT(1); }
        else CP_WAIT(0);
        __syncthreads();

        const uint32_t sKb = smem_u32(sm + 16384 + (kb & 1) * 16384);
        const uint32_t sVb = sKb + 8192;

        // ---- S = Q K^T, m32 per warp (each K frag feeds 2 m16 tiles) ----
        float s[2][8][4];
#pragma unroll
        for (int mt = 0; mt < 2; ++mt)
#pragma unroll
            for (int nt = 0; nt < 8; ++nt)
#pragma unroll
                for (int j = 0; j < 4; ++j) s[mt][nt][j] = 0.f;

#pragma unroll
        for (int ks = 0; ks < 4; ++ks) {
            uint32_t qf[2][4];
            const int achk = ks * 2 + a_chk_l;
#pragma unroll
            for (int mt = 0; mt < 2; ++mt) {
                int row = wid * 32 + mt * 16 + a_row_l;
                ldsm4(qf[mt], sQb + row * 128 + ((achk ^ (row & 7)) << 4));
            }
            const int bchk = ks * 2 + b_chk_l;
#pragma unroll
            for (int np = 0; np < 4; ++np) {
                uint32_t kf[4];
                int row = np * 16 + b_row_l;
                ldsm4(kf, sKb + row * 128 + ((bchk ^ (row & 7)) << 4));
#pragma unroll
                for (int mt = 0; mt < 2; ++mt) {
                    mma_f16(s[mt][np * 2],     qf[mt], &kf[0]);
                    mma_f16(s[mt][np * 2 + 1], qf[mt], &kf[2]);
                }
            }
        }

        if (kb == 16) {
#pragma unroll
            for (int nt = 0; nt < 8; ++nt)
#pragma unroll
                for (int j = 0; j < 4; ++j) {
                    int tok = kb * 64 + nt * 8 + (lane & 3) * 2 + (j & 1);
                    if (tok > 1024) { s[0][nt][j] = -1e30f; s[1][nt][j] = -1e30f; }
                }
        }

        // ---- online softmax per m16 tile (exp2 domain, MUFU ex2) ----
#pragma unroll
        for (int mt = 0; mt < 2; ++mt) {
            float tm0 = -1e30f, tm1 = -1e30f;
#pragma unroll
            for (int nt = 0; nt < 8; ++nt) {
                tm0 = fmaxf(tm0, fmaxf(s[mt][nt][0], s[mt][nt][1]));
                tm1 = fmaxf(tm1, fmaxf(s[mt][nt][2], s[mt][nt][3]));
            }
            tm0 = fmaxf(tm0, __shfl_xor_sync(0xffffffffu, tm0, 1));
            tm0 = fmaxf(tm0, __shfl_xor_sync(0xffffffffu, tm0, 2));
            tm1 = fmaxf(tm1, __shfl_xor_sync(0xffffffffu, tm1, 1));
            tm1 = fmaxf(tm1, __shfl_xor_sync(0xffffffffu, tm1, 2));
            float mn0 = fmaxf(mr[mt][0], tm0), mn1 = fmaxf(mr[mt][1], tm1);
            float cr0 = ex2f(mr[mt][0] - mn0), cr1 = ex2f(mr[mt][1] - mn1);
            float rs0 = 0.f, rs1 = 0.f;
#pragma unroll
            for (int nt = 0; nt < 8; ++nt) {
                s[mt][nt][0] = ex2f(s[mt][nt][0] - mn0);
                s[mt][nt][1] = ex2f(s[mt][nt][1] - mn0);
                s[mt][nt][2] = ex2f(s[mt][nt][2] - mn1);
                s[mt][nt][3] = ex2f(s[mt][nt][3] - mn1);
                rs0 += s[mt][nt][0] + s[mt][nt][1];
                rs1 += s[mt][nt][2] + s[mt][nt][3];
            }
            rs0 += __shfl_xor_sync(0xffffffffu, rs0, 1);
            rs0 += __shfl_xor_sync(0xffffffffu, rs0, 2);
            rs1 += __shfl_xor_sync(0xffffffffu, rs1, 1);
            rs1 += __shfl_xor_sync(0xffffffffu, rs1, 2);
            lr[mt][0] = lr[mt][0] * cr0 + rs0;
            lr[mt][1] = lr[mt][1] * cr1 + rs1;
            mr[mt][0] = mn0; mr[mt][1] = mn1;
#pragma unroll
            for (int nt = 0; nt < 8; ++nt) {
                o[mt][nt][0] *= cr0; o[mt][nt][1] *= cr0;
                o[mt][nt][2] *= cr1; o[mt][nt][3] *= cr1;
            }
        }

        // ---- O += P V (each V frag feeds 2 m16 tiles) ----
#pragma unroll
        for (int k2 = 0; k2 < 4; ++k2) {
            uint32_t ph[2][4];
#pragma unroll
            for (int mt = 0; mt < 2; ++mt) {
                int t0 = 2 * k2, t1 = t0 + 1;
                ph[mt][0] = pack2h(s[mt][t0][0], s[mt][t0][1]);
                ph[mt][1] = pack2h(s[mt][t0][2], s[mt][t0][3]);
                ph[mt][2] = pack2h(s[mt][t1][0], s[mt][t1][1]);
                ph[mt][3] = pack2h(s[mt][t1][2], s[mt][t1][3]);
            }
#pragma unroll
            for (int ntp = 0; ntp < 4; ++ntp) {
                uint32_t vf[4];
                int row = k2 * 16 + (lane & 15);
                int chk = ntp * 2 + (lane >> 4);
                ldsm4_t(vf, sVb + row * 128 + ((chk ^ (row & 7)) << 4));
#pragma unroll
                for (int mt = 0; mt < 2; ++mt) {
                    mma_f16(o[mt][ntp * 2],     ph[mt], &vf[0]);
                    mma_f16(o[mt][ntp * 2 + 1], ph[mt], &vf[2]);
                }
            }
        }
        __syncthreads();
    }

    // ---- epilogue: normalize, single fp16 ctx ----
#pragma unroll
    for (int mt = 0; mt < 2; ++mt) {
        float inv0 = 1.f / lr[mt][0], inv1 = 1.f / lr[mt][1];
        int tok0 = qt * 128 + wid * 32 + mt * 16 + (lane >> 2);
        int tok1 = tok0 + 8;
        int dbase = (lane & 3) * 2;
#pragma unroll
        for (int nt = 0; nt < 8; ++nt) {
            int d = nt * 8 + dbase;
            if (tok0 <= 1024) {
                size_t idx = (size_t)(tok0 * 8 + b) * 1024 + colb + d;
                *(uint32_t*)(Ctx + idx) = pack2h(o[mt][nt][0] * inv0, o[mt][nt][1] * inv0);
            }
            if (tok1 <= 1024) {
                size_t idx = (size_t)(tok1 * 8 + b) * 1024 + colb + d;
                *(uint32_t*)(Ctx + idx) = pack2h(o[mt][nt][2] * inv1, o[mt][nt][3] * inv1);
            }
        }
    }
}

// ---------------------------------------------------------------------------
// Launch
// ---------------------------------------------------------------------------
extern "C" void kernel_launch(void* const* d_in, const int* in_sizes, int n_in,
                              void* d_out, int out_size)
{
    const float* query = (const float*)d_in[0];
    const float* key   = (const float*)d_in[1];
    const float* value = (const float*)d_in[2];
    const float* W_in  = (const float*)d_in[3];
    const float* b_in  = (const float*)d_in[4];
    const float* W_out = (const float*)d_in[5];
    const float* b_out = (const float*)d_in[6];
    float* out = (float*)d_out;

    __half *qraw, *kraw, *vraw, *wi, *wo, *aq, *ak, *av, *ctx;
    cudaGetSymbolAddress((void**)&qraw, g_qraw);
    cudaGetSymbolAddress((void**)&kraw, g_kraw);
    cudaGetSymbolAddress((void**)&vraw, g_vraw);
    cudaGetSymbolAddress((void**)&wi, g_wi);
    cudaGetSymbolAddress((void**)&wo, g_wo);
    cudaGetSymbolAddress((void**)&aq, g_aq);
    cudaGetSymbolAddress((void**)&ak, g_ak);
    cudaGetSymbolAddress((void**)&av, g_av);
    cudaGetSymbolAddress((void**)&ctx, g_c);

    cudaFuncSetAttribute(tc_gemm_qkv, cudaFuncAttributeMaxDynamicSharedMemorySize, GK_SMEM);
    cudaFuncSetAttribute(tc_gemm_out, cudaFuncAttributeMaxDynamicSharedMemorySize, GK_SMEM);
    cudaFuncSetAttribute(attn_f16,    cudaFuncAttributeMaxDynamicSharedMemorySize, ATTN_SMEM);

    // fused input conversion + dummy-row fill (4 elems/thread)
    split_all<<<(SPLIT_EXT + 1023) / 1024, 256>>>(
        (const float4*)query, (const float4*)key, (const float4*)value,
        (const float4*)W_in, (const float4*)W_out,
        (uint2*)qraw, (uint2*)kraw, (uint2*)vraw, (uint2*)wi, (uint2*)wo,
        (uint2*)aq, (uint2*)ak, (uint2*)av);

    // QKV projections (1-term fp16)
    tc_gemm_qkv<<<dim3(8, 64, 3), 256, GK_SMEM>>>(qraw, kraw, vraw, wi, b_in, aq, ak, av);

    // attention (fp16 mma.sync, 4 warps x m32)
    attn_f16<<<dim3(9, B_SZ * H_CNT), 128, ATTN_SMEM>>>(aq, ak, av, ctx);

    // out projection (1-term fp16)
    tc_gemm_out<<<dim3(8, 65), 256, GK_SMEM>>>(ctx, wo, b_out, out, NTOK);
}